// round 10
// baseline (speedup 1.0000x reference)
#include <cuda_runtime.h>
#include <cuda_bf16.h>
#include <math.h>
#include <stdint.h>

// Problem constants
#define Nb   4          // batch
#define Tt   4096       // sequence length
#define Dd   512        // model dim
#define Hh   8          // heads
#define NHh  4          // hash rounds
#define BSs  64         // bucket chunk size
#define DHh  64         // head dim
#define NBb  64         // n_buckets
#define CSs  256        // chunks = NH * NB
#define Ll   16384      // NH * T

typedef unsigned long long u64;

// ---------------- scratch (device globals; no allocation allowed) ----------
__device__ float g_Q[(size_t)Nb * Tt * Dd];                 // 33.5 MB
__device__ float g_V[(size_t)Nb * Tt * Dd];                 // 33.5 MB
__device__ int   g_buckets[(size_t)Nb * Hh * NHh * Tt];     // 2 MB
__device__ int   g_perm[(size_t)Nb * Hh * Ll];              // 2 MB
__device__ float g_O[(size_t)Nb * Hh * NHh * Tt * DHh];     // 134 MB
__device__ float g_logits[(size_t)Nb * Hh * NHh * Tt];      // 2 MB
__device__ __nv_bfloat16 g_wthi[2][Dd * Dd];                // 1 MB (W^T hi: 0=Q,1=V)
__device__ __nv_bfloat16 g_wtlo[2][Dd * Dd];                // 1 MB
#define MAXF 131072
__device__ int g_nflags;
__device__ int g_flags[MAXF];                               // packed (n<<17)|(h<<14)|(r<<12)|t

// ================= helpers ==================================================
__device__ __forceinline__ uint32_t smem_u32(const void* p) {
    uint32_t a;
    asm("{ .reg .u64 t; cvta.to.shared.u64 t, %1; cvt.u32.u64 %0, t; }" : "=r"(a) : "l"(p));
    return a;
}
#define MMA_BF16(d, a, b)                                                     \
    asm volatile("mma.sync.aligned.m16n8k16.row.col.f32.bf16.bf16.f32 "       \
        "{%0,%1,%2,%3}, {%4,%5,%6,%7}, {%8,%9}, {%0,%1,%2,%3};"               \
        : "+f"((d)[0]), "+f"((d)[1]), "+f"((d)[2]), "+f"((d)[3])              \
        : "r"((a)[0]), "r"((a)[1]), "r"((a)[2]), "r"((a)[3]),                 \
          "r"((b)[0]), "r"((b)[1]))
#define LDSM4(r0, r1, r2, r3, addr)                                           \
    asm volatile("ldmatrix.sync.aligned.m8n8.x4.shared.b16 {%0,%1,%2,%3}, [%4];" \
        : "=r"(r0), "=r"(r1), "=r"(r2), "=r"(r3) : "r"(addr))
#define LDSM4T(r0, r1, r2, r3, addr)                                          \
    asm volatile("ldmatrix.sync.aligned.m8n8.x4.trans.shared.b16 {%0,%1,%2,%3}, [%4];" \
        : "=r"(r0), "=r"(r1), "=r"(r2), "=r"(r3) : "r"(addr))
#define FFMA2(d, a, b) \
    asm("fma.rn.f32x2 %0, %1, %2, %0;" : "+l"(d) : "l"(a), "l"(b))
#define PACK2(d, x, y) \
    asm("mov.b64 %0, {%1, %2};" : "=l"(d) : "f"(x), "f"(y))
#define UNPACK2(x, y, d) \
    asm("mov.b64 {%0, %1}, %2;" : "=f"(x), "=f"(y) : "l"(d))

// ================= reset ====================================================
__global__ void reset_kernel() { g_nflags = 0; }

// ================= split + transpose W_Q / W_V ==============================
__global__ void split_w_kernel(const float* __restrict__ WQ, const float* __restrict__ WV)
{
    __shared__ float tile[32][33];
    const float* W = blockIdx.z ? WV : WQ;
    const int bx = blockIdx.x * 32;   // n block
    const int by = blockIdx.y * 32;   // k block
    const int tx = threadIdx.x, ty = threadIdx.y;   // 32 x 8
#pragma unroll
    for (int r = 0; r < 32; r += 8)
        tile[ty + r][tx] = W[(size_t)(by + ty + r) * Dd + bx + tx];
    __syncthreads();
#pragma unroll
    for (int r = 0; r < 32; r += 8) {
        float val = tile[tx][ty + r];
        __nv_bfloat16 hi = __float2bfloat16(val);
        __nv_bfloat16 lo = __float2bfloat16(val - __bfloat162float(hi));
        size_t o = (size_t)(bx + ty + r) * Dd + by + tx;
        g_wthi[blockIdx.z][o] = hi;
        g_wtlo[blockIdx.z][o] = lo;
    }
}

// ================= Q/V GEMM: mma.sync bf16 3-term (proven) ==================
#define PITCH 40
#define A_HI  0
#define A_LO  (128 * PITCH)
#define B_HI  (2 * 128 * PITCH)
#define B_LO  (2 * 128 * PITCH + 256 * PITCH)
#define SMEM_MMA ((2 * 128 * PITCH + 2 * 256 * PITCH) * 2)

__global__ __launch_bounds__(512, 1)
void gemm_qv_kernel(const float* __restrict__ x,
                    const float* __restrict__ bQ, const float* __restrict__ bV)
{
    extern __shared__ uint16_t sm16[];
    const int tid = threadIdx.x;
    const int wid = tid >> 5, lane = tid & 31;
    const int g = lane >> 2, tg = lane & 3;
    const int wm = wid & 3, wn = wid >> 2;
    const int mbase = blockIdx.y * 128;
    const int ncol0 = blockIdx.x * 256;
    const int which = blockIdx.z;                 // 0 = Q, 1 = V
    const __nv_bfloat16* Whi = g_wthi[which];
    const __nv_bfloat16* Wlo = g_wtlo[which];
    const float* bias = which ? bV : bQ;
    float* C = which ? g_V : g_Q;

    float acc[2][8][4];
#pragma unroll
    for (int i = 0; i < 2; i++)
#pragma unroll
        for (int j = 0; j < 8; j++)
#pragma unroll
            for (int k = 0; k < 4; k++) acc[i][j][k] = 0.f;

    for (int slab = 0; slab < 16; slab++) {
        const int kt = slab * 32;
#pragma unroll
        for (int i = 0; i < 2; i++) {
            const int e = tid + i * 512;
            const int m = e >> 3, k4 = e & 7;
            float4 v = *(const float4*)&x[(size_t)(mbase + m) * Dd + kt + k4 * 4];
            __nv_bfloat162 h01 = __floats2bfloat162_rn(v.x, v.y);
            __nv_bfloat162 h23 = __floats2bfloat162_rn(v.z, v.w);
            __nv_bfloat162 l01 = __floats2bfloat162_rn(v.x - __low2float(h01),
                                                       v.y - __high2float(h01));
            __nv_bfloat162 l23 = __floats2bfloat162_rn(v.z - __low2float(h23),
                                                       v.w - __high2float(h23));
            const int off = m * PITCH + k4 * 4;
            *(__nv_bfloat162*)(sm16 + A_HI + off)     = h01;
            *(__nv_bfloat162*)(sm16 + A_HI + off + 2) = h23;
            *(__nv_bfloat162*)(sm16 + A_LO + off)     = l01;
            *(__nv_bfloat162*)(sm16 + A_LO + off + 2) = l23;
        }
#pragma unroll
        for (int i = 0; i < 4; i++) {
            const int e = tid + i * 512;
            const int split = e >> 10;
            const int r = (e >> 2) & 255;
            const int k8 = e & 3;
            const __nv_bfloat16* src = (split ? Wlo : Whi)
                + (size_t)(ncol0 + r) * Dd + kt + k8 * 8;
            *(uint4*)(sm16 + (split ? B_LO : B_HI) + r * PITCH + k8 * 8)
                = *(const uint4*)src;
        }
        __syncthreads();

#pragma unroll
        for (int kk = 0; kk < 32; kk += 16) {
            uint32_t ah[2][4], al[2][4];
#pragma unroll
            for (int mt = 0; mt < 2; mt++) {
                const int ro = (wm * 32 + mt * 16 + g) * PITCH + kk + 2 * tg;
                ah[mt][0] = *(const uint32_t*)(sm16 + A_HI + ro);
                ah[mt][1] = *(const uint32_t*)(sm16 + A_HI + ro + 8 * PITCH);
                ah[mt][2] = *(const uint32_t*)(sm16 + A_HI + ro + 8);
                ah[mt][3] = *(const uint32_t*)(sm16 + A_HI + ro + 8 * PITCH + 8);
                al[mt][0] = *(const uint32_t*)(sm16 + A_LO + ro);
                al[mt][1] = *(const uint32_t*)(sm16 + A_LO + ro + 8 * PITCH);
                al[mt][2] = *(const uint32_t*)(sm16 + A_LO + ro + 8);
                al[mt][3] = *(const uint32_t*)(sm16 + A_LO + ro + 8 * PITCH + 8);
            }
#pragma unroll
            for (int ng = 0; ng < 2; ng++) {
                uint32_t bh[4][2], bl[4][2];
#pragma unroll
                for (int q = 0; q < 4; q++) {
                    const int ro = (wn * 64 + (ng * 4 + q) * 8 + g) * PITCH + kk + 2 * tg;
                    bh[q][0] = *(const uint32_t*)(sm16 + B_HI + ro);
                    bh[q][1] = *(const uint32_t*)(sm16 + B_HI + ro + 8);
                    bl[q][0] = *(const uint32_t*)(sm16 + B_LO + ro);
                    bl[q][1] = *(const uint32_t*)(sm16 + B_LO + ro + 8);
                }
#pragma unroll
                for (int mt = 0; mt < 2; mt++)
#pragma unroll
                    for (int q = 0; q < 4; q++) {
                        float* d = acc[mt][ng * 4 + q];
                        MMA_BF16(d, ah[mt], bh[q]);
                        MMA_BF16(d, ah[mt], bl[q]);
                        MMA_BF16(d, al[mt], bh[q]);
                    }
            }
        }
        __syncthreads();
    }

#pragma unroll
    for (int mt = 0; mt < 2; mt++) {
        const int r0 = mbase + wm * 32 + mt * 16 + g;
#pragma unroll
        for (int nt = 0; nt < 8; nt++) {
            const int col = ncol0 + wn * 64 + nt * 8 + 2 * tg;
            float2 b2 = *(const float2*)&bias[col];
            float2 o0, o1;
            o0.x = acc[mt][nt][0] + b2.x;
            o0.y = acc[mt][nt][1] + b2.y;
            o1.x = acc[mt][nt][2] + b2.x;
            o1.y = acc[mt][nt][3] + b2.y;
            *(float2*)&C[(size_t)r0 * Dd + col] = o0;
            *(float2*)&C[(size_t)(r0 + 8) * Dd + col] = o1;
        }
    }
}

// ================= bucket kernel: GEMM (FFMA2) + argmax + margin flag =======
#define AsP 68
#define BsP 132
#define SMEM_BKT ((128 * AsP + 64 * BsP) * 4)

__global__ __launch_bounds__(256, 2)
void bucket_kernel(const float* __restrict__ rot)
{
    extern __shared__ float smf[];
    float* As = smf;                  // [128 m][68 k]
    float* Bs = smf + 128 * AsP;      // [64 k][132 c]

    const int h = blockIdx.y, n = blockIdx.z;
    const int tid = threadIdx.x;      // 256
    const int tx = tid & 15, ty = tid >> 4;
    const int t0 = blockIdx.x * 128;

    const float* Qb = g_Q + ((size_t)n * Tt + t0) * Dd + h * DHh;
#pragma unroll
    for (int l = 0; l < 8; l++) {
        const int e = tid + l * 256;
        const int r = e >> 4, c4 = e & 15;
        *(float4*)&As[r * AsP + c4 * 4] = *(const float4*)&Qb[(size_t)r * Dd + c4 * 4];
    }
    const float* Rb = rot + (size_t)h * 8192;
#pragma unroll
    for (int l = 0; l < 8; l++) {
        const int e = tid + l * 256;
        const int kr = e >> 5, c4 = e & 31;
        *(float4*)&Bs[kr * BsP + c4 * 4] = *(const float4*)&Rb[kr * 128 + c4 * 4];
    }
    __syncthreads();

    u64 acc2[8][4];
#pragma unroll
    for (int i = 0; i < 8; i++)
#pragma unroll
        for (int j = 0; j < 4; j++) acc2[i][j] = 0ull;

#pragma unroll 4
    for (int k = 0; k < 64; k++) {
        float a[8];
#pragma unroll
        for (int i = 0; i < 8; i++) a[i] = As[(ty * 8 + i) * AsP + k];
        u64 a2[8];
#pragma unroll
        for (int i = 0; i < 8; i++) PACK2(a2[i], a[i], a[i]);
        ulonglong2 bp0 = *(const ulonglong2*)&Bs[k * BsP + tx * 8];
        ulonglong2 bp1 = *(const ulonglong2*)&Bs[k * BsP + tx * 8 + 4];
        u64 b2[4] = {bp0.x, bp0.y, bp1.x, bp1.y};
#pragma unroll
        for (int i = 0; i < 8; i++)
#pragma unroll
            for (int j = 0; j < 4; j++) FFMA2(acc2[i][j], a2[i], b2[j]);
    }

    const int ig = (tx & 3) * 8;
    const int r = tx >> 2;
#pragma unroll
    for (int i = 0; i < 8; i++) {
        float acc[8];
#pragma unroll
        for (int jp = 0; jp < 4; jp++)
            UNPACK2(acc[2 * jp], acc[2 * jp + 1], acc2[i][jp]);

        // local top1 (val,idx first-occurrence) + top2 value
        float t1 = acc[0]; int i1 = ig; float t2 = -3.4e38f;
#pragma unroll
        for (int j = 1; j < 8; j++) {
            float v = acc[j];
            if (v > t1) { t2 = t1; t1 = v; i1 = ig + j; }
            else t2 = fmaxf(t2, v);
        }
#pragma unroll
        for (int j = 0; j < 8; j++) {
            float v = -acc[j];
            if (v > t1) { t2 = t1; t1 = v; i1 = 32 + ig + j; }
            else t2 = fmaxf(t2, v);
        }
        // merge across the 4 threads of this round
#pragma unroll
        for (int o = 1; o <= 2; o <<= 1) {
            float o1 = __shfl_xor_sync(0xffffffffu, t1, o);
            int   oi = __shfl_xor_sync(0xffffffffu, i1, o);
            float o2 = __shfl_xor_sync(0xffffffffu, t2, o);
            if (o1 > t1 || (o1 == t1 && oi < i1)) {
                t2 = fmaxf(t1, o2); t1 = o1; i1 = oi;
            } else {
                t2 = fmaxf(t2, o1);
            }
        }

        if ((tx & 3) == 0) {
            const int t = t0 + ty * 8 + i;
            g_buckets[(((size_t)n * Hh + h) * NHh + r) * Tt + t] = i1 + r * NBb;
            if (t1 - t2 < 0.005f * t1 + 1e-3f) {
                int p = atomicAdd(&g_nflags, 1);
                if (p < MAXF)
                    g_flags[p] = (n << 17) | (h << 14) | (r << 12) | t;
            }
        }
    }
}

// ================= fix-up: exact recompute of flagged decisions =============
// grid (32 bins, 8 slices) x 256 threads. Warp batches 4 flags per W pass.
#define FCAP 6144
#define OF_LST 0
#define OF_XB  (FCAP * 4)
#define OF_QB  (FCAP * 4 + 8 * 4 * 512 * 4)
#define SMEM_FIX (FCAP * 4 + 8 * 4 * 512 * 4 + 8 * 4 * 64 * 4)

__global__ __launch_bounds__(256)
void fixup_kernel(const float* __restrict__ x, const float* __restrict__ WQ,
                  const float* __restrict__ bQ, const float* __restrict__ rot)
{
    extern __shared__ char fsm[];
    int*   lst = (int*)(fsm + OF_LST);
    float* xb  = (float*)(fsm + OF_XB);    // [8 warps][4 flags][512]
    float* qb  = (float*)(fsm + OF_QB);    // [8 warps][4 flags][64]
    __shared__ int lcnt;

    const int bin = blockIdx.x;            // n*8 + h
    const int slice = blockIdx.y;          // 0..7
    const int n = bin >> 3, h = bin & 7;
    const int tid = threadIdx.x;
    const int w = tid >> 5, lane = tid & 31;

    if (tid == 0) lcnt = 0;
    __syncthreads();

    int count = g_nflags;
    if (count > MAXF) count = MAXF;
    for (int e = tid; e < count; e += 256) {
        const int pk = g_flags[e];
        if (((pk >> 14) & 31) == bin && (e & 7) == slice) {
            int p = atomicAdd(&lcnt, 1);
            if (p < FCAP) lst[p] = pk;
        }
    }
    __syncthreads();
    int nf = lcnt;
    if (nf > FCAP) nf = FCAP;

    float* xw = xb + w * 4 * 512;
    float* qw = qb + w * 4 * 64;

    for (int s = w * 4; s < nf; s += 32) {
        const int nn = min(4, nf - s);
        for (int ff = 0; ff < nn; ff++) {
            const int t = lst[s + ff] & 4095;
            const float* xr = x + ((size_t)n * Tt + t) * Dd;
            for (int e4 = lane; e4 < 128; e4 += 32)
                *(float4*)&xw[ff * 512 + e4 * 4] = *(const float4*)&xr[e4 * 4];
        }
        __syncwarp();

        float acc[4][2];
#pragma unroll
        for (int ff = 0; ff < 4; ff++) { acc[ff][0] = 0.f; acc[ff][1] = 0.f; }
        const float* Wc = WQ + h * 64;
        for (int k = 0; k < Dd; k++) {
            const float w0 = Wc[(size_t)k * Dd + lane];
            const float w1 = Wc[(size_t)k * Dd + lane + 32];
#pragma unroll
            for (int ff = 0; ff < 4; ff++) {
                acc[ff][0] += xw[ff * 512 + k] * w0;
                acc[ff][1] += xw[ff * 512 + k] * w1;
            }
        }
        const float b0 = bQ[h * 64 + lane], b1 = bQ[h * 64 + lane + 32];
        for (int ff = 0; ff < nn; ff++) {
            qw[ff * 64 + lane]      = acc[ff][0] + b0;
            qw[ff * 64 + lane + 32] = acc[ff][1] + b1;
        }
        __syncwarp();

        for (int ff = 0; ff < nn; ff++) {
            const int pk = lst[s + ff];
            const int t = pk & 4095, r = (pk >> 12) & 3;
            const float* rp = rot + (size_t)h * 8192 + r * 32 + lane;
            float v = 0.f;
#pragma unroll 8
            for (int f = 0; f < 64; f++)
                v += qw[ff * 64 + f] * rp[f * 128];
            float bv; int bi;
            if (-v > v) { bv = -v; bi = 32 + lane; }
            else        { bv = v;  bi = lane; }
#pragma unroll
            for (int o = 16; o; o >>= 1) {
                float ov = __shfl_xor_sync(0xffffffffu, bv, o);
                int   oi = __shfl_xor_sync(0xffffffffu, bi, o);
                if (ov > bv || (ov == bv && oi < bi)) { bv = ov; bi = oi; }
            }
            if (lane == 0)
                g_buckets[(((size_t)n * Hh + h) * NHh + r) * Tt + t] = bi + r * NBb;
        }
        __syncwarp();
    }
}

// ================= segmented stable counting sort per (n,h) =================
#define HROW 258
#define SMEM_SORT (Ll + 256 * HROW * 2 + 256 * 4)
__global__ void sort_kernel()
{
    extern __shared__ char smraw[];
    unsigned char*  sb   = (unsigned char*)smraw;
    unsigned short* hist = (unsigned short*)(smraw + Ll);
    int*            base = (int*)(smraw + Ll + 256 * HROW * 2);
    __shared__ int tot[256];

    const int nh = blockIdx.x;
    const int tid = threadIdx.x;

    for (int e = tid; e < 256 * HROW / 2; e += 256)
        ((unsigned int*)hist)[e] = 0;
    __syncthreads();

    const int* bptr = g_buckets + (size_t)nh * Ll;
    for (int e = tid; e < Ll; e += 256)
        sb[e] = (unsigned char)bptr[e];
    __syncthreads();

    {
        const int s = tid;
#pragma unroll 4
        for (int j = 0; j < 64; j++) {
            int b = sb[s * 64 + j];
            hist[b * HROW + s]++;
        }
    }
    __syncthreads();

    {
        const unsigned short* row = &hist[tid * HROW];
        int sum = 0;
#pragma unroll 8
        for (int s2 = 0; s2 < 256; s2++) sum += row[s2];
        tot[tid] = sum;
    }
    __syncthreads();
    if (tid == 0) {
        int run = 0;
        for (int b = 0; b < 256; b++) { base[b] = run; run += tot[b]; }
    }
    __syncthreads();

    {
        unsigned short* row = &hist[tid * HROW];
        unsigned short run = 0;
        for (int s2 = 0; s2 < 256; s2++) {
            unsigned short v = row[s2];
            row[s2] = run;
            run = (unsigned short)(run + v);
        }
    }
    __syncthreads();

    {
        const int s = tid;
        int* pout = g_perm + (size_t)nh * Ll;
        for (int j = 0; j < 64; j++) {
            int i = s * 64 + j;
            int b = sb[i];
            unsigned short off = hist[b * HROW + s];
            hist[b * HROW + s] = (unsigned short)(off + 1);
            pout[base[b] + off] = (b << 16) | i;
        }
    }
}

// ================= chunked attention (R7/R9 proven version) =================
#define KHP 72
#define VP  72
#define OKH_HI 0
#define OKH_LO 18432
#define OV_HI  36864
#define OV_LO  55296
#define OMETA  73728
#define ORSC   74240
#define OINVS  74496
#define SMEM_ATT3 74752

__global__ __launch_bounds__(128, 3)
void attention_kernel()
{
    extern __shared__ char smb[];
    __nv_bfloat16* kh_hi = (__nv_bfloat16*)(smb + OKH_HI);   // [128][72]
    __nv_bfloat16* kh_lo = (__nv_bfloat16*)(smb + OKH_LO);
    __nv_bfloat16* v_hi  = (__nv_bfloat16*)(smb + OV_HI);    // [128][72]
    __nv_bfloat16* v_lo  = (__nv_bfloat16*)(smb + OV_LO);
    int*   pmeta = (int*)(smb + OMETA);                      // 128
    float* rsc   = (float*)(smb + ORSC);                     // 64
    float* invs  = (float*)(smb + OINVS);                    // 64

    const int c = blockIdx.x, h = blockIdx.y, n = blockIdx.z;
    const int tid = threadIdx.x;
    const int pc = (c + CSs - 1) % CSs;

    {
        const int p = (tid < 64) ? (c * BSs + tid) : (pc * BSs + (tid - 64));
        pmeta[tid] = g_perm[((size_t)n * Hh + h) * Ll + p];
    }
    __syncthreads();

    const float* Qb = g_Q + (size_t)n * Tt * Dd + h * DHh;
    const float* Vb = g_V + (size_t)n * Tt * Dd + h * DHh;
    const int sub = tid >> 4, c4 = tid & 15;
#pragma unroll
    for (int i = 0; i < 16; i++) {
        const int row = i * 8 + sub;
        const int t = pmeta[row] & 4095;
        float4 qv = *(const float4*)&Qb[(size_t)t * Dd + c4 * 4];
        float ss = qv.x * qv.x + qv.y * qv.y + qv.z * qv.z + qv.w * qv.w;
        ss += __shfl_xor_sync(0xffffffffu, ss, 1);
        ss += __shfl_xor_sync(0xffffffffu, ss, 2);
        ss += __shfl_xor_sync(0xffffffffu, ss, 4);
        ss += __shfl_xor_sync(0xffffffffu, ss, 8);
        const float nn = sqrtf(ss) + 1e-6f;
        const float rn = 1.f / nn;
        if (c4 == 0 && row < 64) rsc[row] = nn;

        const float a0 = qv.x * rn, a1 = qv.y * rn, a2 = qv.z * rn, a3 = qv.w * rn;
        __nv_bfloat162 kh01 = __floats2bfloat162_rn(a0, a1);
        __nv_bfloat162 kl01 = __floats2bfloat162_rn(a0 - __low2float(kh01), a1 - __high2float(kh01));
        __nv_bfloat162 kh23 = __floats2bfloat162_rn(a2, a3);
        __nv_bfloat162 kl23 = __floats2bfloat162_rn(a2 - __low2float(kh23), a3 - __high2float(kh23));
        *(__nv_bfloat162*)&kh_hi[row * KHP + c4 * 4]     = kh01;
        *(__nv_bfloat162*)&kh_hi[row * KHP + c4 * 4 + 2] = kh23;
        *(__nv_bfloat162*)&kh_lo[row * KHP + c4 * 4]     = kl01;
        *(__nv_bfloat162*)&kh_lo[row * KHP + c4 * 4 + 2] = kl23;

        float4 vv = *(const float4*)&Vb[(size_t)t * Dd + c4 * 4];
        __nv_bfloat162 vh01 = __floats2bfloat162_rn(vv.x, vv.y);
        __nv_bfloat162 vl01 = __floats2bfloat162_rn(vv.x - __low2float(vh01), vv.y - __high2float(vh01));
        __nv_bfloat162 vh23 = __floats2bfloat162_rn(vv.z, vv.w);
        __nv_bfloat162 vl23 = __floats2bfloat162_rn(vv.z - __low2float(vh23), vv.w - __high2float(vh23));
        *(__nv_bfloat162*)&v_hi[row * VP + c4 * 4]     = vh01;
        *(__nv_bfloat162*)&v_hi[row * VP + c4 * 4 + 2] = vh23;
        *(__nv_bfloat162*)&v_lo[row * VP + c4 * 4]     = vl01;
        *(__nv_bfloat162*)&v_lo[row * VP + c4 * 4 + 2] = vl23;
    }
    __syncthreads();

    const int w = tid >> 5, lane = tid & 31;
    const int g = lane >> 2, tg = lane & 3;
    const int i0 = w * 16;

    const uint32_t khb_hi = smem_u32(kh_hi), khb_lo = smem_u32(kh_lo);
    const uint32_t vb_hi  = smem_u32(v_hi),  vb_lo  = smem_u32(v_lo);
    const uint32_t aoff = ((i0 + (lane & 15)) * KHP + 8 * (lane >> 4)) * 2;
    const uint32_t boff = (((lane & 7) + ((lane >= 16) ? 8 : 0)) * KHP + ((lane >> 3) & 1) * 8) * 2;
    const uint32_t voff = (((lane & 7) + 8 * ((lane >> 3) & 1)) * VP + 8 * (lane >> 4)) * 2;

    float dc[16][4];
#pragma unroll
    for (int nt = 0; nt < 16; nt++)
#pragma unroll
        for (int k = 0; k < 4; k++) dc[nt][k] = 0.f;

#pragma unroll
    for (int k0 = 0; k0 < 64; k0 += 16) {
        uint32_t ah[4], al[4];
        LDSM4(ah[0], ah[1], ah[2], ah[3], khb_hi + aoff + k0 * 2);
        LDSM4(al[0], al[1], al[2], al[3], khb_lo + aoff + k0 * 2);
#pragma unroll
        for (int jt = 0; jt < 8; jt++) {
            uint32_t bh[4], bl[4];
            const uint32_t jb = (uint32_t)(jt * 16 * KHP + k0) * 2;
            LDSM4(bh[0], bh[1], bh[2], bh[3], khb_hi + boff + jb);
            LDSM4(bl[0], bl[1], bl[2], bl[3], khb_lo + boff + jb);
            MMA_BF16(dc[2 * jt], ah, bh);
            MMA_BF16(dc[2 * jt], ah, bl);
            MMA_BF16(dc[2 * jt], al, bh);
            MMA_BF16(dc[2 * jt + 1], ah, bh + 2);
            MMA_BF16(dc[2 * jt + 1], ah, bl + 2);
            MMA_BF16(dc[2 * jt + 1], al, bh + 2);
        }
    }

    const int ra = i0 + g, rb = i0 + g + 8;
    {
        const int pka = pmeta[ra], pkb = pmeta[rb];
        const float sca = 0.125f * rsc[ra];
        const float scb = 0.125f * rsc[rb];

#pragma unroll
        for (int nt = 0; nt < 16; nt++) {
            const int j0 = nt * 8 + 2 * tg;
            const int pj0 = pmeta[j0], pj1 = pmeta[j0 + 1];
            float x;
            x = dc[nt][0] * sca;
            if ((pka >> 16) != (pj0 >> 16)) x = -1e9f;
            if (((pka ^ pj0) & 4095) == 0)  x = -1e-5f;
            dc[nt][0] = x;
            x = dc[nt][1] * sca;
            if ((pka >> 16) != (pj1 >> 16)) x = -1e9f;
            if (((pka ^ pj1) & 4095) == 0)  x = -1e-5f;
            dc[nt][1] = x;
            x = dc[nt][2] * scb;
            if ((pkb >> 16) != (pj0 >> 16)) x = -1e9f;
            if (((pkb ^ pj0) & 4095) == 0)  x = -1e-5f;
            dc[nt][2] = x;
            x = dc[nt][3] * scb;
            if ((pkb >> 16) != (pj1 >> 16)) x = -1e9f;
            if (((pkb ^ pj1) & 4095) == 0)  x = -1e-5f;
            dc[nt][3] = x;
        }

        float ma = -1e30f, mb = -1e30f;
#pragma unroll
        for (int nt = 0; nt < 16; nt++) {
            ma = fmaxf(ma, fmaxf(dc[nt][0], dc[nt][1]));
            mb = fmaxf(mb, fmaxf(dc[nt][2], dc[nt][3]));
        }
        ma = fmaxf(ma, __shfl_xor_sync(0xffffffffu, ma, 1));
        ma = fmaxf(ma, __shfl_xor_sync(0xffffffffu, ma, 2));
        mb = fmaxf(mb, __shfl_xor_sync(0xffffffffu, mb, 1));
        mb = fmaxf(mb, __shfl_xor_sync(0xffffffffu, mb, 2));

        float sa = 0.f, sb2 = 0.f;
#pragma unroll
        for (int nt = 0; nt < 16; nt++) {
            dc[nt][0] = __expf(dc[nt][0] - ma); sa  += dc[nt][0];
            dc[nt][1] = __expf(dc[nt][1] - ma); sa  += dc[nt][1];
            dc[nt][2] = __expf(dc[nt][2] - mb); sb2 += dc[nt][2];
            dc[nt][3] = __expf(dc[nt][3] - mb); sb2 += dc[nt][3];
        }
        sa  += __shfl_xor_sync(0xffffffffu, sa, 1);
        sa  += __shfl_xor_sync(0xffffffffu, sa, 2);
        sb2 += __shfl_xor_sync(0xffffffffu, sb2, 1);
        sb2 += __shfl_xor_sync(0xffffffffu, sb2, 2);

        if (tg == 0) {
            const int nhbase = ((int)n * Hh + h) * NHh;
            const int ta = pka & 4095, rra = (pka >> 12) & 3;
            const int tb = pkb & 4095, rrb = (pkb >> 12) & 3;
            g_logits[((size_t)nhbase + rra) * Tt + ta] = ma + __logf(sa);
            g_logits[((size_t)nhbase + rrb) * Tt + tb] = mb + __logf(sb2);
            invs[ra] = 1.f / sa;
            invs[rb] = 1.f / sb2;
        }
        __syncwarp();
    }

    float oc[8][4];
#pragma unroll
    for (int nt = 0; nt < 8; nt++)
#pragma unroll
        for (int k = 0; k < 4; k++) oc[nt][k] = 0.f;

#pragma unroll
    for (int kc = 0; kc < 8; kc++) {
        uint32_t phi[4], plo[4];
        {
            __nv_bfloat162 hp, lp;
            hp = __floats2bfloat162_rn(dc[2 * kc][0], dc[2 * kc][1]);
            lp = __floats2bfloat162_rn(dc[2 * kc][0] - __low2float(hp),
                                       dc[2 * kc][1] - __high2float(hp));
            phi[0] = *(uint32_t*)&hp; plo[0] = *(uint32_t*)&lp;
            hp = __floats2bfloat162_rn(dc[2 * kc][2], dc[2 * kc][3]);
            lp = __floats2bfloat162_rn(dc[2 * kc][2] - __low2float(hp),
                                       dc[2 * kc][3] - __high2float(hp));
            phi[1] = *(uint32_t*)&hp; plo[1] = *(uint32_t*)&lp;
            hp = __floats2bfloat162_rn(dc[2 * kc + 1][0], dc[2 * kc + 1][1]);
            lp = __floats2bfloat162_rn(dc[2 * kc + 1][0] - __low2float(hp),
                                       dc[2 * kc + 1][1] - __high2float(hp));
            phi[2] = *(uint32_t*)&hp; plo[2] = *(uint32_t*)&lp;
            hp = __floats2bfloat162_rn(dc[2 * kc + 1][2], dc[2 * kc + 1][3]);
            lp = __floats2bfloat162_rn(dc[2 * kc + 1][2] - __low2float(hp),
                                       dc[2 * kc + 1][3] - __high2float(hp));
            phi[3] = *(uint32_t*)&hp; plo[3] = *(uint32_t*)&lp;
        }
#pragma unroll
        for (int ft = 0; ft < 4; ft++) {
            uint32_t vh[4], vl[4];
            const uint32_t vbo = (uint32_t)(kc * 16 * VP + ft * 16) * 2;
            LDSM4T(vh[0], vh[1], vh[2], vh[3], vb_hi + voff + vbo);
            LDSM4T(vl[0], vl[1], vl[2], vl[3], vb_lo + voff + vbo);
            MMA_BF16(oc[2 * ft], phi, vh);
            MMA_BF16(oc[2 * ft], phi, vl);
            MMA_BF16(oc[2 * ft], plo, vh);
            MMA_BF16(oc[2 * ft + 1], phi, vh + 2);
            MMA_BF16(oc[2 * ft + 1], phi, vl + 2);
            MMA_BF16(oc[2 * ft + 1], plo, vh + 2);
        }
    }

    {
        const int pka = pmeta[ra], pkb = pmeta[rb];
        const float iva = invs[ra], ivb = invs[rb];
        const size_t obase = ((size_t)n * Hh + h) * NHh;
        const size_t oa = ((obase + ((pka >> 12) & 3)) * Tt + (pka & 4095)) * DHh;
        const size_t ob = ((obase + ((pkb >> 12) & 3)) * Tt + (pkb & 4095)) * DHh;
#pragma unroll
        for (int ft = 0; ft < 4; ft++) {
            const int f0 = ft * 16 + 2 * tg;
            *(float2*)&g_O[oa + f0]     = make_float2(oc[2 * ft][0] * iva, oc[2 * ft][1] * iva);
            *(float2*)&g_O[ob + f0]     = make_float2(oc[2 * ft][2] * ivb, oc[2 * ft][3] * ivb);
            *(float2*)&g_O[oa + f0 + 8] = make_float2(oc[2 * ft + 1][0] * iva, oc[2 * ft + 1][1] * iva);
            *(float2*)&g_O[ob + f0 + 8] = make_float2(oc[2 * ft + 1][2] * ivb, oc[2 * ft + 1][3] * ivb);
        }
    }
}

// ================= round-combine softmax + LayerNorm ========================
__global__ void combine_ln_kernel(const float* __restrict__ gamma,
                                  const float* __restrict__ beta,
                                  float* __restrict__ out)
{
    const int bid = blockIdx.x;            // n*T + t
    const int n = bid >> 12, t = bid & 4095;
    const int tid = threadIdx.x;           // 128
    __shared__ float wsh[Hh][NHh];
    __shared__ float red[128];

    if (tid < Hh) {
        const int h = tid;
        float l[NHh];
        float m = -1e30f;
#pragma unroll
        for (int r = 0; r < NHh; r++) {
            l[r] = g_logits[(((size_t)n * Hh + h) * NHh + r) * Tt + t];
            m = fmaxf(m, l[r]);
        }
        float s = 0.f;
#pragma unroll
        for (int r = 0; r < NHh; r++) s += __expf(l[r] - m);
        const float lse = m + __logf(s);
#pragma unroll
        for (int r = 0; r < NHh; r++) wsh[h][r] = __expf(l[r] - lse);
    }
    __syncthreads();

    float vals[4];
    float lsum = 0.f, lsq = 0.f;
#pragma unroll
    for (int k2 = 0; k2 < 4; k2++) {
        const int d = tid + k2 * 128;
        const int h = d >> 6, f = d & 63;
        float a = 0.f;
#pragma unroll
        for (int r = 0; r < NHh; r++)
            a += wsh[h][r] * g_O[((((size_t)n * Hh + h) * NHh + r) * Tt + t) * DHh + f];
        vals[k2] = a;
        lsum += a;
        lsq  += a * a;
    }

    red[tid] = lsum;
    __syncthreads();
#pragma unroll
    for (int s = 64; s > 0; s >>= 1) {
        if (tid < s) red[tid] += red[tid + s];
        __syncthreads();
    }
    const float mu = red[0] * (1.f / Dd);
    __syncthreads();
    red[tid] = lsq;
    __syncthreads();
#pragma unroll
    for (int s = 64; s > 0; s >>= 1) {
        if (tid < s) red[tid] += red[tid + s];
        __syncthreads();
    }
    const float var = red[0] * (1.f / Dd) - mu * mu;
    const float rstd = rsqrtf(var + 1e-3f);

#pragma unroll
    for (int k2 = 0; k2 < 4; k2++) {
        const int d = tid + k2 * 128;
        out[(size_t)bid * Dd + d] = gamma[d] * (vals[k2] - mu) * rstd + beta[d];
    }
}

// ================= launch ===================================================
extern "C" void kernel_launch(void* const* d_in, const int* in_sizes, int n_in,
                              void* d_out, int out_size)
{
    const float* x     = (const float*)d_in[0];
    const float* W_Q   = (const float*)d_in[1];
    const float* b_Q   = (const float*)d_in[2];
    const float* W_V   = (const float*)d_in[3];
    const float* b_V   = (const float*)d_in[4];
    const float* gamma = (const float*)d_in[5];
    const float* beta  = (const float*)d_in[6];
    const float* rot   = (const float*)d_in[7];
    float* out = (float*)d_out;

    cudaFuncSetAttribute(attention_kernel,
                         cudaFuncAttributeMaxDynamicSharedMemorySize, SMEM_ATT3);
    cudaFuncSetAttribute(sort_kernel,
                         cudaFuncAttributeMaxDynamicSharedMemorySize, SMEM_SORT);
    cudaFuncSetAttribute(gemm_qv_kernel,
                         cudaFuncAttributeMaxDynamicSharedMemorySize, SMEM_MMA);
    cudaFuncSetAttribute(bucket_kernel,
                         cudaFuncAttributeMaxDynamicSharedMemorySize, SMEM_BKT);
    cudaFuncSetAttribute(fixup_kernel,
                         cudaFuncAttributeMaxDynamicSharedMemorySize, SMEM_FIX);

    reset_kernel<<<1, 1>>>();

    split_w_kernel<<<dim3(16, 16, 2), dim3(32, 8)>>>(W_Q, W_V);

    dim3 gGrid(2, (Nb * Tt) / 128, 2);          // (2, 128, 2) -> Q and V
    gemm_qv_kernel<<<gGrid, 512, SMEM_MMA>>>(x, b_Q, b_V);

    dim3 bGrid(Tt / 128, Hh, Nb);               // (32, 8, 4)
    bucket_kernel<<<bGrid, 256, SMEM_BKT>>>(rot);

    fixup_kernel<<<dim3(32, 8), 256, SMEM_FIX>>>(x, W_Q, b_Q, rot);

    sort_kernel<<<Nb * Hh, 256, SMEM_SORT>>>(); // 32 blocks

    dim3 aGrid(CSs, Hh, Nb);                    // (256, 8, 4)
    attention_kernel<<<aGrid, 128, SMEM_ATT3>>>();

    combine_ln_kernel<<<Nb * Tt, 128>>>(gamma, beta, out);
}

// round 11
// speedup vs baseline: 1.1086x; 1.1086x over previous
#include <cuda_runtime.h>
#include <cuda_bf16.h>
#include <math.h>
#include <stdint.h>

// Problem constants
#define Nb   4          // batch
#define Tt   4096       // sequence length
#define Dd   512        // model dim
#define Hh   8          // heads
#define NHh  4          // hash rounds
#define BSs  64         // bucket chunk size
#define DHh  64         // head dim
#define NBb  64         // n_buckets
#define CSs  256        // chunks = NH * NB
#define Ll   16384      // NH * T

typedef unsigned long long u64;

// ---------------- scratch (device globals; no allocation allowed) ----------
__device__ float g_Q[(size_t)Nb * Tt * Dd];                 // 33.5 MB
__device__ float g_V[(size_t)Nb * Tt * Dd];                 // 33.5 MB
__device__ int   g_buckets[(size_t)Nb * Hh * NHh * Tt];     // 2 MB
__device__ int   g_perm[(size_t)Nb * Hh * Ll];              // 2 MB
__device__ float g_O[(size_t)Nb * Hh * NHh * Tt * DHh];     // 134 MB
__device__ float g_logits[(size_t)Nb * Hh * NHh * Tt];      // 2 MB
__device__ __nv_bfloat16 g_wthi[2][Dd * Dd];                // 1 MB (W^T hi: 0=Q,1=V)
__device__ __nv_bfloat16 g_wtlo[2][Dd * Dd];                // 1 MB
#define MAXF 131072
__device__ int g_nflags;
__device__ int g_flags[MAXF];                               // packed (n<<17)|(h<<14)|(r<<12)|t

// ================= helpers ==================================================
__device__ __forceinline__ uint32_t smem_u32(const void* p) {
    uint32_t a;
    asm("{ .reg .u64 t; cvta.to.shared.u64 t, %1; cvt.u32.u64 %0, t; }" : "=r"(a) : "l"(p));
    return a;
}
#define MMA_BF16(d, a, b)                                                     \
    asm volatile("mma.sync.aligned.m16n8k16.row.col.f32.bf16.bf16.f32 "       \
        "{%0,%1,%2,%3}, {%4,%5,%6,%7}, {%8,%9}, {%0,%1,%2,%3};"               \
        : "+f"((d)[0]), "+f"((d)[1]), "+f"((d)[2]), "+f"((d)[3])              \
        : "r"((a)[0]), "r"((a)[1]), "r"((a)[2]), "r"((a)[3]),                 \
          "r"((b)[0]), "r"((b)[1]))
#define LDSM4(r0, r1, r2, r3, addr)                                           \
    asm volatile("ldmatrix.sync.aligned.m8n8.x4.shared.b16 {%0,%1,%2,%3}, [%4];" \
        : "=r"(r0), "=r"(r1), "=r"(r2), "=r"(r3) : "r"(addr))
#define LDSM4T(r0, r1, r2, r3, addr)                                          \
    asm volatile("ldmatrix.sync.aligned.m8n8.x4.trans.shared.b16 {%0,%1,%2,%3}, [%4];" \
        : "=r"(r0), "=r"(r1), "=r"(r2), "=r"(r3) : "r"(addr))
#define FFMA2(d, a, b) \
    asm("fma.rn.f32x2 %0, %1, %2, %0;" : "+l"(d) : "l"(a), "l"(b))
#define PACK2(d, x, y) \
    asm("mov.b64 %0, {%1, %2};" : "=l"(d) : "f"(x), "f"(y))
#define UNPACK2(x, y, d) \
    asm("mov.b64 {%0, %1}, %2;" : "=f"(x), "=f"(y) : "l"(d))

// ================= reset ====================================================
__global__ void reset_kernel() { g_nflags = 0; }

// ================= split + transpose W_Q / W_V ==============================
__global__ void split_w_kernel(const float* __restrict__ WQ, const float* __restrict__ WV)
{
    __shared__ float tile[32][33];
    const float* W = blockIdx.z ? WV : WQ;
    const int bx = blockIdx.x * 32;   // n block
    const int by = blockIdx.y * 32;   // k block
    const int tx = threadIdx.x, ty = threadIdx.y;   // 32 x 8
#pragma unroll
    for (int r = 0; r < 32; r += 8)
        tile[ty + r][tx] = W[(size_t)(by + ty + r) * Dd + bx + tx];
    __syncthreads();
#pragma unroll
    for (int r = 0; r < 32; r += 8) {
        float val = tile[tx][ty + r];
        __nv_bfloat16 hi = __float2bfloat16(val);
        __nv_bfloat16 lo = __float2bfloat16(val - __bfloat162float(hi));
        size_t o = (size_t)(bx + ty + r) * Dd + by + tx;
        g_wthi[blockIdx.z][o] = hi;
        g_wtlo[blockIdx.z][o] = lo;
    }
}

// ================= Q/V GEMM: mma.sync bf16 3-term (proven) ==================
#define PITCH 40
#define A_HI  0
#define A_LO  (128 * PITCH)
#define B_HI  (2 * 128 * PITCH)
#define B_LO  (2 * 128 * PITCH + 256 * PITCH)
#define SMEM_MMA ((2 * 128 * PITCH + 2 * 256 * PITCH) * 2)

__global__ __launch_bounds__(512, 1)
void gemm_qv_kernel(const float* __restrict__ x,
                    const float* __restrict__ bQ, const float* __restrict__ bV)
{
    extern __shared__ uint16_t sm16[];
    const int tid = threadIdx.x;
    const int wid = tid >> 5, lane = tid & 31;
    const int g = lane >> 2, tg = lane & 3;
    const int wm = wid & 3, wn = wid >> 2;
    const int mbase = blockIdx.y * 128;
    const int ncol0 = blockIdx.x * 256;
    const int which = blockIdx.z;                 // 0 = Q, 1 = V
    const __nv_bfloat16* Whi = g_wthi[which];
    const __nv_bfloat16* Wlo = g_wtlo[which];
    const float* bias = which ? bV : bQ;
    float* C = which ? g_V : g_Q;

    float acc[2][8][4];
#pragma unroll
    for (int i = 0; i < 2; i++)
#pragma unroll
        for (int j = 0; j < 8; j++)
#pragma unroll
            for (int k = 0; k < 4; k++) acc[i][j][k] = 0.f;

    for (int slab = 0; slab < 16; slab++) {
        const int kt = slab * 32;
#pragma unroll
        for (int i = 0; i < 2; i++) {
            const int e = tid + i * 512;
            const int m = e >> 3, k4 = e & 7;
            float4 v = *(const float4*)&x[(size_t)(mbase + m) * Dd + kt + k4 * 4];
            __nv_bfloat162 h01 = __floats2bfloat162_rn(v.x, v.y);
            __nv_bfloat162 h23 = __floats2bfloat162_rn(v.z, v.w);
            __nv_bfloat162 l01 = __floats2bfloat162_rn(v.x - __low2float(h01),
                                                       v.y - __high2float(h01));
            __nv_bfloat162 l23 = __floats2bfloat162_rn(v.z - __low2float(h23),
                                                       v.w - __high2float(h23));
            const int off = m * PITCH + k4 * 4;
            *(__nv_bfloat162*)(sm16 + A_HI + off)     = h01;
            *(__nv_bfloat162*)(sm16 + A_HI + off + 2) = h23;
            *(__nv_bfloat162*)(sm16 + A_LO + off)     = l01;
            *(__nv_bfloat162*)(sm16 + A_LO + off + 2) = l23;
        }
#pragma unroll
        for (int i = 0; i < 4; i++) {
            const int e = tid + i * 512;
            const int split = e >> 10;
            const int r = (e >> 2) & 255;
            const int k8 = e & 3;
            const __nv_bfloat16* src = (split ? Wlo : Whi)
                + (size_t)(ncol0 + r) * Dd + kt + k8 * 8;
            *(uint4*)(sm16 + (split ? B_LO : B_HI) + r * PITCH + k8 * 8)
                = *(const uint4*)src;
        }
        __syncthreads();

#pragma unroll
        for (int kk = 0; kk < 32; kk += 16) {
            uint32_t ah[2][4], al[2][4];
#pragma unroll
            for (int mt = 0; mt < 2; mt++) {
                const int ro = (wm * 32 + mt * 16 + g) * PITCH + kk + 2 * tg;
                ah[mt][0] = *(const uint32_t*)(sm16 + A_HI + ro);
                ah[mt][1] = *(const uint32_t*)(sm16 + A_HI + ro + 8 * PITCH);
                ah[mt][2] = *(const uint32_t*)(sm16 + A_HI + ro + 8);
                ah[mt][3] = *(const uint32_t*)(sm16 + A_HI + ro + 8 * PITCH + 8);
                al[mt][0] = *(const uint32_t*)(sm16 + A_LO + ro);
                al[mt][1] = *(const uint32_t*)(sm16 + A_LO + ro + 8 * PITCH);
                al[mt][2] = *(const uint32_t*)(sm16 + A_LO + ro + 8);
                al[mt][3] = *(const uint32_t*)(sm16 + A_LO + ro + 8 * PITCH + 8);
            }
#pragma unroll
            for (int ng = 0; ng < 2; ng++) {
                uint32_t bh[4][2], bl[4][2];
#pragma unroll
                for (int q = 0; q < 4; q++) {
                    const int ro = (wn * 64 + (ng * 4 + q) * 8 + g) * PITCH + kk + 2 * tg;
                    bh[q][0] = *(const uint32_t*)(sm16 + B_HI + ro);
                    bh[q][1] = *(const uint32_t*)(sm16 + B_HI + ro + 8);
                    bl[q][0] = *(const uint32_t*)(sm16 + B_LO + ro);
                    bl[q][1] = *(const uint32_t*)(sm16 + B_LO + ro + 8);
                }
#pragma unroll
                for (int mt = 0; mt < 2; mt++)
#pragma unroll
                    for (int q = 0; q < 4; q++) {
                        float* d = acc[mt][ng * 4 + q];
                        MMA_BF16(d, ah[mt], bh[q]);
                        MMA_BF16(d, ah[mt], bl[q]);
                        MMA_BF16(d, al[mt], bh[q]);
                    }
            }
        }
        __syncthreads();
    }

#pragma unroll
    for (int mt = 0; mt < 2; mt++) {
        const int r0 = mbase + wm * 32 + mt * 16 + g;
#pragma unroll
        for (int nt = 0; nt < 8; nt++) {
            const int col = ncol0 + wn * 64 + nt * 8 + 2 * tg;
            float2 b2 = *(const float2*)&bias[col];
            float2 o0, o1;
            o0.x = acc[mt][nt][0] + b2.x;
            o0.y = acc[mt][nt][1] + b2.y;
            o1.x = acc[mt][nt][2] + b2.x;
            o1.y = acc[mt][nt][3] + b2.y;
            *(float2*)&C[(size_t)r0 * Dd + col] = o0;
            *(float2*)&C[(size_t)(r0 + 8) * Dd + col] = o1;
        }
    }
}

// ================= bucket kernel: GEMM (FFMA2) + argmax + margin flag =======
#define AsP 68
#define BsP 132
#define SMEM_BKT ((128 * AsP + 64 * BsP) * 4)

__global__ __launch_bounds__(256, 2)
void bucket_kernel(const float* __restrict__ rot)
{
    extern __shared__ float smf[];
    float* As = smf;                  // [128 m][68 k]
    float* Bs = smf + 128 * AsP;      // [64 k][132 c]

    const int h = blockIdx.y, n = blockIdx.z;
    const int tid = threadIdx.x;      // 256
    const int tx = tid & 15, ty = tid >> 4;
    const int t0 = blockIdx.x * 128;

    const float* Qb = g_Q + ((size_t)n * Tt + t0) * Dd + h * DHh;
#pragma unroll
    for (int l = 0; l < 8; l++) {
        const int e = tid + l * 256;
        const int r = e >> 4, c4 = e & 15;
        *(float4*)&As[r * AsP + c4 * 4] = *(const float4*)&Qb[(size_t)r * Dd + c4 * 4];
    }
    const float* Rb = rot + (size_t)h * 8192;
#pragma unroll
    for (int l = 0; l < 8; l++) {
        const int e = tid + l * 256;
        const int kr = e >> 5, c4 = e & 31;
        *(float4*)&Bs[kr * BsP + c4 * 4] = *(const float4*)&Rb[kr * 128 + c4 * 4];
    }
    __syncthreads();

    u64 acc2[8][4];
#pragma unroll
    for (int i = 0; i < 8; i++)
#pragma unroll
        for (int j = 0; j < 4; j++) acc2[i][j] = 0ull;

#pragma unroll 4
    for (int k = 0; k < 64; k++) {
        float a[8];
#pragma unroll
        for (int i = 0; i < 8; i++) a[i] = As[(ty * 8 + i) * AsP + k];
        u64 a2[8];
#pragma unroll
        for (int i = 0; i < 8; i++) PACK2(a2[i], a[i], a[i]);
        ulonglong2 bp0 = *(const ulonglong2*)&Bs[k * BsP + tx * 8];
        ulonglong2 bp1 = *(const ulonglong2*)&Bs[k * BsP + tx * 8 + 4];
        u64 b2[4] = {bp0.x, bp0.y, bp1.x, bp1.y};
#pragma unroll
        for (int i = 0; i < 8; i++)
#pragma unroll
            for (int j = 0; j < 4; j++) FFMA2(acc2[i][j], a2[i], b2[j]);
    }

    const int ig = (tx & 3) * 8;
    const int r = tx >> 2;
#pragma unroll
    for (int i = 0; i < 8; i++) {
        float acc[8];
#pragma unroll
        for (int jp = 0; jp < 4; jp++)
            UNPACK2(acc[2 * jp], acc[2 * jp + 1], acc2[i][jp]);

        // local top1 (val,idx first-occurrence) + top2 value
        float t1 = acc[0]; int i1 = ig; float t2 = -3.4e38f;
#pragma unroll
        for (int j = 1; j < 8; j++) {
            float v = acc[j];
            if (v > t1) { t2 = t1; t1 = v; i1 = ig + j; }
            else t2 = fmaxf(t2, v);
        }
#pragma unroll
        for (int j = 0; j < 8; j++) {
            float v = -acc[j];
            if (v > t1) { t2 = t1; t1 = v; i1 = 32 + ig + j; }
            else t2 = fmaxf(t2, v);
        }
        // merge across the 4 threads of this round
#pragma unroll
        for (int o = 1; o <= 2; o <<= 1) {
            float o1 = __shfl_xor_sync(0xffffffffu, t1, o);
            int   oi = __shfl_xor_sync(0xffffffffu, i1, o);
            float o2 = __shfl_xor_sync(0xffffffffu, t2, o);
            if (o1 > t1 || (o1 == t1 && oi < i1)) {
                t2 = fmaxf(t1, o2); t1 = o1; i1 = oi;
            } else {
                t2 = fmaxf(t2, o1);
            }
        }

        if ((tx & 3) == 0) {
            const int t = t0 + ty * 8 + i;
            g_buckets[(((size_t)n * Hh + h) * NHh + r) * Tt + t] = i1 + r * NBb;
            // error sigma ~4e-5 abs; threshold ~2.1e-3 abs = ~52 sigma
            if (t1 - t2 < 1e-4f * t1 + 1e-4f) {
                int p = atomicAdd(&g_nflags, 1);
                if (p < MAXF)
                    g_flags[p] = (n << 17) | (h << 14) | (r << 12) | t;
            }
        }
    }
}

// ================= fix-up: exact recompute of flagged decisions =============
// grid (32 bins, 8 slices) x 256 threads. Warp batches 4 flags per W pass.
#define FCAP 6144
#define OF_LST 0
#define OF_XB  (FCAP * 4)
#define OF_QB  (FCAP * 4 + 8 * 4 * 512 * 4)
#define SMEM_FIX (FCAP * 4 + 8 * 4 * 512 * 4 + 8 * 4 * 64 * 4)

__global__ __launch_bounds__(256)
void fixup_kernel(const float* __restrict__ x, const float* __restrict__ WQ,
                  const float* __restrict__ bQ, const float* __restrict__ rot)
{
    extern __shared__ char fsm[];
    int*   lst = (int*)(fsm + OF_LST);
    float* xb  = (float*)(fsm + OF_XB);    // [8 warps][4 flags][512]
    float* qb  = (float*)(fsm + OF_QB);    // [8 warps][4 flags][64]
    __shared__ int lcnt;

    const int bin = blockIdx.x;            // n*8 + h
    const int slice = blockIdx.y;          // 0..7
    const int n = bin >> 3, h = bin & 7;
    const int tid = threadIdx.x;
    const int w = tid >> 5, lane = tid & 31;

    if (tid == 0) lcnt = 0;
    __syncthreads();

    int count = g_nflags;
    if (count > MAXF) count = MAXF;
    for (int e = tid; e < count; e += 256) {
        const int pk = g_flags[e];
        if (((pk >> 14) & 31) == bin && (e & 7) == slice) {
            int p = atomicAdd(&lcnt, 1);
            if (p < FCAP) lst[p] = pk;
        }
    }
    __syncthreads();
    int nf = lcnt;
    if (nf > FCAP) nf = FCAP;

    float* xw = xb + w * 4 * 512;
    float* qw = qb + w * 4 * 64;

    for (int s = w * 4; s < nf; s += 32) {
        const int nn = min(4, nf - s);
        for (int ff = 0; ff < nn; ff++) {
            const int t = lst[s + ff] & 4095;
            const float* xr = x + ((size_t)n * Tt + t) * Dd;
            for (int e4 = lane; e4 < 128; e4 += 32)
                *(float4*)&xw[ff * 512 + e4 * 4] = *(const float4*)&xr[e4 * 4];
        }
        __syncwarp();

        float acc[4][2];
#pragma unroll
        for (int ff = 0; ff < 4; ff++) { acc[ff][0] = 0.f; acc[ff][1] = 0.f; }
        const float* Wc = WQ + h * 64;
        for (int k = 0; k < Dd; k++) {
            const float w0 = Wc[(size_t)k * Dd + lane];
            const float w1 = Wc[(size_t)k * Dd + lane + 32];
#pragma unroll
            for (int ff = 0; ff < 4; ff++) {
                acc[ff][0] += xw[ff * 512 + k] * w0;
                acc[ff][1] += xw[ff * 512 + k] * w1;
            }
        }
        const float b0 = bQ[h * 64 + lane], b1 = bQ[h * 64 + lane + 32];
        for (int ff = 0; ff < nn; ff++) {
            qw[ff * 64 + lane]      = acc[ff][0] + b0;
            qw[ff * 64 + lane + 32] = acc[ff][1] + b1;
        }
        __syncwarp();

        for (int ff = 0; ff < nn; ff++) {
            const int pk = lst[s + ff];
            const int t = pk & 4095, r = (pk >> 12) & 3;
            const float* rp = rot + (size_t)h * 8192 + r * 32 + lane;
            float v = 0.f;
#pragma unroll 8
            for (int f = 0; f < 64; f++)
                v += qw[ff * 64 + f] * rp[f * 128];
            float bv; int bi;
            if (-v > v) { bv = -v; bi = 32 + lane; }
            else        { bv = v;  bi = lane; }
#pragma unroll
            for (int o = 16; o; o >>= 1) {
                float ov = __shfl_xor_sync(0xffffffffu, bv, o);
                int   oi = __shfl_xor_sync(0xffffffffu, bi, o);
                if (ov > bv || (ov == bv && oi < bi)) { bv = ov; bi = oi; }
            }
            if (lane == 0)
                g_buckets[(((size_t)n * Hh + h) * NHh + r) * Tt + t] = bi + r * NBb;
        }
        __syncwarp();
    }
}

// ================= segmented stable counting sort per (n,h) =================
#define HROW 258
#define SMEM_SORT (Ll + 256 * HROW * 2 + 256 * 4)
__global__ void sort_kernel()
{
    extern __shared__ char smraw[];
    unsigned char*  sb   = (unsigned char*)smraw;
    unsigned short* hist = (unsigned short*)(smraw + Ll);
    int*            base = (int*)(smraw + Ll + 256 * HROW * 2);
    __shared__ int tot[256];

    const int nh = blockIdx.x;
    const int tid = threadIdx.x;

    for (int e = tid; e < 256 * HROW / 2; e += 256)
        ((unsigned int*)hist)[e] = 0;
    __syncthreads();

    const int* bptr = g_buckets + (size_t)nh * Ll;
    for (int e = tid; e < Ll; e += 256)
        sb[e] = (unsigned char)bptr[e];
    __syncthreads();

    {
        const int s = tid;
#pragma unroll 4
        for (int j = 0; j < 64; j++) {
            int b = sb[s * 64 + j];
            hist[b * HROW + s]++;
        }
    }
    __syncthreads();

    {
        const unsigned short* row = &hist[tid * HROW];
        int sum = 0;
#pragma unroll 8
        for (int s2 = 0; s2 < 256; s2++) sum += row[s2];
        tot[tid] = sum;
    }
    __syncthreads();
    if (tid == 0) {
        int run = 0;
        for (int b = 0; b < 256; b++) { base[b] = run; run += tot[b]; }
    }
    __syncthreads();

    {
        unsigned short* row = &hist[tid * HROW];
        unsigned short run = 0;
        for (int s2 = 0; s2 < 256; s2++) {
            unsigned short v = row[s2];
            row[s2] = run;
            run = (unsigned short)(run + v);
        }
    }
    __syncthreads();

    {
        const int s = tid;
        int* pout = g_perm + (size_t)nh * Ll;
        for (int j = 0; j < 64; j++) {
            int i = s * 64 + j;
            int b = sb[i];
            unsigned short off = hist[b * HROW + s];
            hist[b * HROW + s] = (unsigned short)(off + 1);
            pout[base[b] + off] = (b << 16) | i;
        }
    }
}

// ================= chunked attention (R7/R9 proven version) =================
#define KHP 72
#define VP  72
#define OKH_HI 0
#define OKH_LO 18432
#define OV_HI  36864
#define OV_LO  55296
#define OMETA  73728
#define ORSC   74240
#define OINVS  74496
#define SMEM_ATT3 74752

__global__ __launch_bounds__(128, 3)
void attention_kernel()
{
    extern __shared__ char smb[];
    __nv_bfloat16* kh_hi = (__nv_bfloat16*)(smb + OKH_HI);   // [128][72]
    __nv_bfloat16* kh_lo = (__nv_bfloat16*)(smb + OKH_LO);
    __nv_bfloat16* v_hi  = (__nv_bfloat16*)(smb + OV_HI);    // [128][72]
    __nv_bfloat16* v_lo  = (__nv_bfloat16*)(smb + OV_LO);
    int*   pmeta = (int*)(smb + OMETA);                      // 128
    float* rsc   = (float*)(smb + ORSC);                     // 64
    float* invs  = (float*)(smb + OINVS);                    // 64

    const int c = blockIdx.x, h = blockIdx.y, n = blockIdx.z;
    const int tid = threadIdx.x;
    const int pc = (c + CSs - 1) % CSs;

    {
        const int p = (tid < 64) ? (c * BSs + tid) : (pc * BSs + (tid - 64));
        pmeta[tid] = g_perm[((size_t)n * Hh + h) * Ll + p];
    }
    __syncthreads();

    const float* Qb = g_Q + (size_t)n * Tt * Dd + h * DHh;
    const float* Vb = g_V + (size_t)n * Tt * Dd + h * DHh;
    const int sub = tid >> 4, c4 = tid & 15;
#pragma unroll
    for (int i = 0; i < 16; i++) {
        const int row = i * 8 + sub;
        const int t = pmeta[row] & 4095;
        float4 qv = *(const float4*)&Qb[(size_t)t * Dd + c4 * 4];
        float ss = qv.x * qv.x + qv.y * qv.y + qv.z * qv.z + qv.w * qv.w;
        ss += __shfl_xor_sync(0xffffffffu, ss, 1);
        ss += __shfl_xor_sync(0xffffffffu, ss, 2);
        ss += __shfl_xor_sync(0xffffffffu, ss, 4);
        ss += __shfl_xor_sync(0xffffffffu, ss, 8);
        const float nn = sqrtf(ss) + 1e-6f;
        const float rn = 1.f / nn;
        if (c4 == 0 && row < 64) rsc[row] = nn;

        const float a0 = qv.x * rn, a1 = qv.y * rn, a2 = qv.z * rn, a3 = qv.w * rn;
        __nv_bfloat162 kh01 = __floats2bfloat162_rn(a0, a1);
        __nv_bfloat162 kl01 = __floats2bfloat162_rn(a0 - __low2float(kh01), a1 - __high2float(kh01));
        __nv_bfloat162 kh23 = __floats2bfloat162_rn(a2, a3);
        __nv_bfloat162 kl23 = __floats2bfloat162_rn(a2 - __low2float(kh23), a3 - __high2float(kh23));
        *(__nv_bfloat162*)&kh_hi[row * KHP + c4 * 4]     = kh01;
        *(__nv_bfloat162*)&kh_hi[row * KHP + c4 * 4 + 2] = kh23;
        *(__nv_bfloat162*)&kh_lo[row * KHP + c4 * 4]     = kl01;
        *(__nv_bfloat162*)&kh_lo[row * KHP + c4 * 4 + 2] = kl23;

        float4 vv = *(const float4*)&Vb[(size_t)t * Dd + c4 * 4];
        __nv_bfloat162 vh01 = __floats2bfloat162_rn(vv.x, vv.y);
        __nv_bfloat162 vl01 = __floats2bfloat162_rn(vv.x - __low2float(vh01), vv.y - __high2float(vh01));
        __nv_bfloat162 vh23 = __floats2bfloat162_rn(vv.z, vv.w);
        __nv_bfloat162 vl23 = __floats2bfloat162_rn(vv.z - __low2float(vh23), vv.w - __high2float(vh23));
        *(__nv_bfloat162*)&v_hi[row * VP + c4 * 4]     = vh01;
        *(__nv_bfloat162*)&v_hi[row * VP + c4 * 4 + 2] = vh23;
        *(__nv_bfloat162*)&v_lo[row * VP + c4 * 4]     = vl01;
        *(__nv_bfloat162*)&v_lo[row * VP + c4 * 4 + 2] = vl23;
    }
    __syncthreads();

    const int w = tid >> 5, lane = tid & 31;
    const int g = lane >> 2, tg = lane & 3;
    const int i0 = w * 16;

    const uint32_t khb_hi = smem_u32(kh_hi), khb_lo = smem_u32(kh_lo);
    const uint32_t vb_hi  = smem_u32(v_hi),  vb_lo  = smem_u32(v_lo);
    const uint32_t aoff = ((i0 + (lane & 15)) * KHP + 8 * (lane >> 4)) * 2;
    const uint32_t boff = (((lane & 7) + ((lane >= 16) ? 8 : 0)) * KHP + ((lane >> 3) & 1) * 8) * 2;
    const uint32_t voff = (((lane & 7) + 8 * ((lane >> 3) & 1)) * VP + 8 * (lane >> 4)) * 2;

    float dc[16][4];
#pragma unroll
    for (int nt = 0; nt < 16; nt++)
#pragma unroll
        for (int k = 0; k < 4; k++) dc[nt][k] = 0.f;

#pragma unroll
    for (int k0 = 0; k0 < 64; k0 += 16) {
        uint32_t ah[4], al[4];
        LDSM4(ah[0], ah[1], ah[2], ah[3], khb_hi + aoff + k0 * 2);
        LDSM4(al[0], al[1], al[2], al[3], khb_lo + aoff + k0 * 2);
#pragma unroll
        for (int jt = 0; jt < 8; jt++) {
            uint32_t bh[4], bl[4];
            const uint32_t jb = (uint32_t)(jt * 16 * KHP + k0) * 2;
            LDSM4(bh[0], bh[1], bh[2], bh[3], khb_hi + boff + jb);
            LDSM4(bl[0], bl[1], bl[2], bl[3], khb_lo + boff + jb);
            MMA_BF16(dc[2 * jt], ah, bh);
            MMA_BF16(dc[2 * jt], ah, bl);
            MMA_BF16(dc[2 * jt], al, bh);
            MMA_BF16(dc[2 * jt + 1], ah, bh + 2);
            MMA_BF16(dc[2 * jt + 1], ah, bl + 2);
            MMA_BF16(dc[2 * jt + 1], al, bh + 2);
        }
    }

    const int ra = i0 + g, rb = i0 + g + 8;
    {
        const int pka = pmeta[ra], pkb = pmeta[rb];
        const float sca = 0.125f * rsc[ra];
        const float scb = 0.125f * rsc[rb];

#pragma unroll
        for (int nt = 0; nt < 16; nt++) {
            const int j0 = nt * 8 + 2 * tg;
            const int pj0 = pmeta[j0], pj1 = pmeta[j0 + 1];
            float x;
            x = dc[nt][0] * sca;
            if ((pka >> 16) != (pj0 >> 16)) x = -1e9f;
            if (((pka ^ pj0) & 4095) == 0)  x = -1e-5f;
            dc[nt][0] = x;
            x = dc[nt][1] * sca;
            if ((pka >> 16) != (pj1 >> 16)) x = -1e9f;
            if (((pka ^ pj1) & 4095) == 0)  x = -1e-5f;
            dc[nt][1] = x;
            x = dc[nt][2] * scb;
            if ((pkb >> 16) != (pj0 >> 16)) x = -1e9f;
            if (((pkb ^ pj0) & 4095) == 0)  x = -1e-5f;
            dc[nt][2] = x;
            x = dc[nt][3] * scb;
            if ((pkb >> 16) != (pj1 >> 16)) x = -1e9f;
            if (((pkb ^ pj1) & 4095) == 0)  x = -1e-5f;
            dc[nt][3] = x;
        }

        float ma = -1e30f, mb = -1e30f;
#pragma unroll
        for (int nt = 0; nt < 16; nt++) {
            ma = fmaxf(ma, fmaxf(dc[nt][0], dc[nt][1]));
            mb = fmaxf(mb, fmaxf(dc[nt][2], dc[nt][3]));
        }
        ma = fmaxf(ma, __shfl_xor_sync(0xffffffffu, ma, 1));
        ma = fmaxf(ma, __shfl_xor_sync(0xffffffffu, ma, 2));
        mb = fmaxf(mb, __shfl_xor_sync(0xffffffffu, mb, 1));
        mb = fmaxf(mb, __shfl_xor_sync(0xffffffffu, mb, 2));

        float sa = 0.f, sb2 = 0.f;
#pragma unroll
        for (int nt = 0; nt < 16; nt++) {
            dc[nt][0] = __expf(dc[nt][0] - ma); sa  += dc[nt][0];
            dc[nt][1] = __expf(dc[nt][1] - ma); sa  += dc[nt][1];
            dc[nt][2] = __expf(dc[nt][2] - mb); sb2 += dc[nt][2];
            dc[nt][3] = __expf(dc[nt][3] - mb); sb2 += dc[nt][3];
        }
        sa  += __shfl_xor_sync(0xffffffffu, sa, 1);
        sa  += __shfl_xor_sync(0xffffffffu, sa, 2);
        sb2 += __shfl_xor_sync(0xffffffffu, sb2, 1);
        sb2 += __shfl_xor_sync(0xffffffffu, sb2, 2);

        if (tg == 0) {
            const int nhbase = ((int)n * Hh + h) * NHh;
            const int ta = pka & 4095, rra = (pka >> 12) & 3;
            const int tb = pkb & 4095, rrb = (pkb >> 12) & 3;
            g_logits[((size_t)nhbase + rra) * Tt + ta] = ma + __logf(sa);
            g_logits[((size_t)nhbase + rrb) * Tt + tb] = mb + __logf(sb2);
            invs[ra] = 1.f / sa;
            invs[rb] = 1.f / sb2;
        }
        __syncwarp();
    }

    float oc[8][4];
#pragma unroll
    for (int nt = 0; nt < 8; nt++)
#pragma unroll
        for (int k = 0; k < 4; k++) oc[nt][k] = 0.f;

#pragma unroll
    for (int kc = 0; kc < 8; kc++) {
        uint32_t phi[4], plo[4];
        {
            __nv_bfloat162 hp, lp;
            hp = __floats2bfloat162_rn(dc[2 * kc][0], dc[2 * kc][1]);
            lp = __floats2bfloat162_rn(dc[2 * kc][0] - __low2float(hp),
                                       dc[2 * kc][1] - __high2float(hp));
            phi[0] = *(uint32_t*)&hp; plo[0] = *(uint32_t*)&lp;
            hp = __floats2bfloat162_rn(dc[2 * kc][2], dc[2 * kc][3]);
            lp = __floats2bfloat162_rn(dc[2 * kc][2] - __low2float(hp),
                                       dc[2 * kc][3] - __high2float(hp));
            phi[1] = *(uint32_t*)&hp; plo[1] = *(uint32_t*)&lp;
            hp = __floats2bfloat162_rn(dc[2 * kc + 1][0], dc[2 * kc + 1][1]);
            lp = __floats2bfloat162_rn(dc[2 * kc + 1][0] - __low2float(hp),
                                       dc[2 * kc + 1][1] - __high2float(hp));
            phi[2] = *(uint32_t*)&hp; plo[2] = *(uint32_t*)&lp;
            hp = __floats2bfloat162_rn(dc[2 * kc + 1][2], dc[2 * kc + 1][3]);
            lp = __floats2bfloat162_rn(dc[2 * kc + 1][2] - __low2float(hp),
                                       dc[2 * kc + 1][3] - __high2float(hp));
            phi[3] = *(uint32_t*)&hp; plo[3] = *(uint32_t*)&lp;
        }
#pragma unroll
        for (int ft = 0; ft < 4; ft++) {
            uint32_t vh[4], vl[4];
            const uint32_t vbo = (uint32_t)(kc * 16 * VP + ft * 16) * 2;
            LDSM4T(vh[0], vh[1], vh[2], vh[3], vb_hi + voff + vbo);
            LDSM4T(vl[0], vl[1], vl[2], vl[3], vb_lo + voff + vbo);
            MMA_BF16(oc[2 * ft], phi, vh);
            MMA_BF16(oc[2 * ft], phi, vl);
            MMA_BF16(oc[2 * ft], plo, vh);
            MMA_BF16(oc[2 * ft + 1], phi, vh + 2);
            MMA_BF16(oc[2 * ft + 1], phi, vl + 2);
            MMA_BF16(oc[2 * ft + 1], plo, vh + 2);
        }
    }

    {
        const int pka = pmeta[ra], pkb = pmeta[rb];
        const float iva = invs[ra], ivb = invs[rb];
        const size_t obase = ((size_t)n * Hh + h) * NHh;
        const size_t oa = ((obase + ((pka >> 12) & 3)) * Tt + (pka & 4095)) * DHh;
        const size_t ob = ((obase + ((pkb >> 12) & 3)) * Tt + (pkb & 4095)) * DHh;
#pragma unroll
        for (int ft = 0; ft < 4; ft++) {
            const int f0 = ft * 16 + 2 * tg;
            *(float2*)&g_O[oa + f0]     = make_float2(oc[2 * ft][0] * iva, oc[2 * ft][1] * iva);
            *(float2*)&g_O[ob + f0]     = make_float2(oc[2 * ft][2] * ivb, oc[2 * ft][3] * ivb);
            *(float2*)&g_O[oa + f0 + 8] = make_float2(oc[2 * ft + 1][0] * iva, oc[2 * ft + 1][1] * iva);
            *(float2*)&g_O[ob + f0 + 8] = make_float2(oc[2 * ft + 1][2] * ivb, oc[2 * ft + 1][3] * ivb);
        }
    }
}

// ================= round-combine softmax + LayerNorm ========================
__global__ void combine_ln_kernel(const float* __restrict__ gamma,
                                  const float* __restrict__ beta,
                                  float* __restrict__ out)
{
    const int bid = blockIdx.x;            // n*T + t
    const int n = bid >> 12, t = bid & 4095;
    const int tid = threadIdx.x;           // 128
    __shared__ float wsh[Hh][NHh];
    __shared__ float red[128];

    if (tid < Hh) {
        const int h = tid;
        float l[NHh];
        float m = -1e30f;
#pragma unroll
        for (int r = 0; r < NHh; r++) {
            l[r] = g_logits[(((size_t)n * Hh + h) * NHh + r) * Tt + t];
            m = fmaxf(m, l[r]);
        }
        float s = 0.f;
#pragma unroll
        for (int r = 0; r < NHh; r++) s += __expf(l[r] - m);
        const float lse = m + __logf(s);
#pragma unroll
        for (int r = 0; r < NHh; r++) wsh[h][r] = __expf(l[r] - lse);
    }
    __syncthreads();

    float vals[4];
    float lsum = 0.f, lsq = 0.f;
#pragma unroll
    for (int k2 = 0; k2 < 4; k2++) {
        const int d = tid + k2 * 128;
        const int h = d >> 6, f = d & 63;
        float a = 0.f;
#pragma unroll
        for (int r = 0; r < NHh; r++)
            a += wsh[h][r] * g_O[((((size_t)n * Hh + h) * NHh + r) * Tt + t) * DHh + f];
        vals[k2] = a;
        lsum += a;
        lsq  += a * a;
    }

    red[tid] = lsum;
    __syncthreads();
#pragma unroll
    for (int s = 64; s > 0; s >>= 1) {
        if (tid < s) red[tid] += red[tid + s];
        __syncthreads();
    }
    const float mu = red[0] * (1.f / Dd);
    __syncthreads();
    red[tid] = lsq;
    __syncthreads();
#pragma unroll
    for (int s = 64; s > 0; s >>= 1) {
        if (tid < s) red[tid] += red[tid + s];
        __syncthreads();
    }
    const float var = red[0] * (1.f / Dd) - mu * mu;
    const float rstd = rsqrtf(var + 1e-3f);

#pragma unroll
    for (int k2 = 0; k2 < 4; k2++) {
        const int d = tid + k2 * 128;
        out[(size_t)bid * Dd + d] = gamma[d] * (vals[k2] - mu) * rstd + beta[d];
    }
}

// ================= launch ===================================================
extern "C" void kernel_launch(void* const* d_in, const int* in_sizes, int n_in,
                              void* d_out, int out_size)
{
    const float* x     = (const float*)d_in[0];
    const float* W_Q   = (const float*)d_in[1];
    const float* b_Q   = (const float*)d_in[2];
    const float* W_V   = (const float*)d_in[3];
    const float* b_V   = (const float*)d_in[4];
    const float* gamma = (const float*)d_in[5];
    const float* beta  = (const float*)d_in[6];
    const float* rot   = (const float*)d_in[7];
    float* out = (float*)d_out;

    cudaFuncSetAttribute(attention_kernel,
                         cudaFuncAttributeMaxDynamicSharedMemorySize, SMEM_ATT3);
    cudaFuncSetAttribute(sort_kernel,
                         cudaFuncAttributeMaxDynamicSharedMemorySize, SMEM_SORT);
    cudaFuncSetAttribute(gemm_qv_kernel,
                         cudaFuncAttributeMaxDynamicSharedMemorySize, SMEM_MMA);
    cudaFuncSetAttribute(bucket_kernel,
                         cudaFuncAttributeMaxDynamicSharedMemorySize, SMEM_BKT);
    cudaFuncSetAttribute(fixup_kernel,
                         cudaFuncAttributeMaxDynamicSharedMemorySize, SMEM_FIX);

    reset_kernel<<<1, 1>>>();

    split_w_kernel<<<dim3(16, 16, 2), dim3(32, 8)>>>(W_Q, W_V);

    dim3 gGrid(2, (Nb * Tt) / 128, 2);          // (2, 128, 2) -> Q and V
    gemm_qv_kernel<<<gGrid, 512, SMEM_MMA>>>(x, b_Q, b_V);

    dim3 bGrid(Tt / 128, Hh, Nb);               // (32, 8, 4)
    bucket_kernel<<<bGrid, 256, SMEM_BKT>>>(rot);

    fixup_kernel<<<dim3(32, 8), 256, SMEM_FIX>>>(x, W_Q, b_Q, rot);

    sort_kernel<<<Nb * Hh, 256, SMEM_SORT>>>(); // 32 blocks

    dim3 aGrid(CSs, Hh, Nb);                    // (256, 8, 4)
    attention_kernel<<<aGrid, 128, SMEM_ATT3>>>();

    combine_ln_kernel<<<Nb * Tt, 128>>>(gamma, beta, out);
}

// round 12
// speedup vs baseline: 1.2017x; 1.0839x over previous
#include <cuda_runtime.h>
#include <cuda_bf16.h>
#include <math.h>
#include <stdint.h>

// Problem constants
#define Nb   4          // batch
#define Tt   4096       // sequence length
#define Dd   512        // model dim
#define Hh   8          // heads
#define NHh  4          // hash rounds
#define BSs  64         // bucket chunk size
#define DHh  64         // head dim
#define NBb  64         // n_buckets
#define CSs  256        // chunks = NH * NB
#define Ll   16384      // NH * T

typedef unsigned long long u64;

// ---------------- scratch (device globals; no allocation allowed) ----------
__device__ float g_Q[(size_t)Nb * Tt * Dd];                 // 33.5 MB
__device__ float g_V[(size_t)Nb * Tt * Dd];                 // 33.5 MB
__device__ int   g_buckets[(size_t)Nb * Hh * NHh * Tt];     // 2 MB
__device__ int   g_perm[(size_t)Nb * Hh * Ll];              // 2 MB
__device__ float g_O[(size_t)Nb * Hh * NHh * Tt * DHh];     // 134 MB
__device__ float g_logits[(size_t)Nb * Hh * NHh * Tt];      // 2 MB
__device__ __nv_bfloat16 g_wthi[2][Dd * Dd];                // 1 MB (W^T hi: 0=Q,1=V)
__device__ __nv_bfloat16 g_wtlo[2][Dd * Dd];                // 1 MB
#define MAXF 131072
__device__ int g_nflags;
__device__ int g_flags[MAXF];                               // packed (n<<17)|(h<<14)|(r<<12)|t

// ================= helpers ==================================================
__device__ __forceinline__ uint32_t smem_u32(const void* p) {
    uint32_t a;
    asm("{ .reg .u64 t; cvta.to.shared.u64 t, %1; cvt.u32.u64 %0, t; }" : "=r"(a) : "l"(p));
    return a;
}
#define MMA_BF16(d, a, b)                                                     \
    asm volatile("mma.sync.aligned.m16n8k16.row.col.f32.bf16.bf16.f32 "       \
        "{%0,%1,%2,%3}, {%4,%5,%6,%7}, {%8,%9}, {%0,%1,%2,%3};"               \
        : "+f"((d)[0]), "+f"((d)[1]), "+f"((d)[2]), "+f"((d)[3])              \
        : "r"((a)[0]), "r"((a)[1]), "r"((a)[2]), "r"((a)[3]),                 \
          "r"((b)[0]), "r"((b)[1]))
#define LDSM4(r0, r1, r2, r3, addr)                                           \
    asm volatile("ldmatrix.sync.aligned.m8n8.x4.shared.b16 {%0,%1,%2,%3}, [%4];" \
        : "=r"(r0), "=r"(r1), "=r"(r2), "=r"(r3) : "r"(addr))
#define LDSM4T(r0, r1, r2, r3, addr)                                          \
    asm volatile("ldmatrix.sync.aligned.m8n8.x4.trans.shared.b16 {%0,%1,%2,%3}, [%4];" \
        : "=r"(r0), "=r"(r1), "=r"(r2), "=r"(r3) : "r"(addr))
#define FFMA2(d, a, b) \
    asm("fma.rn.f32x2 %0, %1, %2, %0;" : "+l"(d) : "l"(a), "l"(b))
#define PACK2(d, x, y) \
    asm("mov.b64 %0, {%1, %2};" : "=l"(d) : "f"(x), "f"(y))
#define UNPACK2(x, y, d) \
    asm("mov.b64 {%0, %1}, %2;" : "=f"(x), "=f"(y) : "l"(d))

// ================= reset ====================================================
__global__ void reset_kernel() { g_nflags = 0; }

// ================= split + transpose W_Q / W_V ==============================
__global__ void split_w_kernel(const float* __restrict__ WQ, const float* __restrict__ WV)
{
    __shared__ float tile[32][33];
    const float* W = blockIdx.z ? WV : WQ;
    const int bx = blockIdx.x * 32;   // n block
    const int by = blockIdx.y * 32;   // k block
    const int tx = threadIdx.x, ty = threadIdx.y;   // 32 x 8
#pragma unroll
    for (int r = 0; r < 32; r += 8)
        tile[ty + r][tx] = W[(size_t)(by + ty + r) * Dd + bx + tx];
    __syncthreads();
#pragma unroll
    for (int r = 0; r < 32; r += 8) {
        float val = tile[tx][ty + r];
        __nv_bfloat16 hi = __float2bfloat16(val);
        __nv_bfloat16 lo = __float2bfloat16(val - __bfloat162float(hi));
        size_t o = (size_t)(bx + ty + r) * Dd + by + tx;
        g_wthi[blockIdx.z][o] = hi;
        g_wtlo[blockIdx.z][o] = lo;
    }
}

// ================= Q/V GEMM: mma.sync bf16 3-term (proven) ==================
#define PITCH 40
#define A_HI  0
#define A_LO  (128 * PITCH)
#define B_HI  (2 * 128 * PITCH)
#define B_LO  (2 * 128 * PITCH + 256 * PITCH)
#define SMEM_MMA ((2 * 128 * PITCH + 2 * 256 * PITCH) * 2)

__global__ __launch_bounds__(512, 1)
void gemm_qv_kernel(const float* __restrict__ x,
                    const float* __restrict__ bQ, const float* __restrict__ bV)
{
    extern __shared__ uint16_t sm16[];
    const int tid = threadIdx.x;
    const int wid = tid >> 5, lane = tid & 31;
    const int g = lane >> 2, tg = lane & 3;
    const int wm = wid & 3, wn = wid >> 2;
    const int mbase = blockIdx.y * 128;
    const int ncol0 = blockIdx.x * 256;
    const int which = blockIdx.z;                 // 0 = Q, 1 = V
    const __nv_bfloat16* Whi = g_wthi[which];
    const __nv_bfloat16* Wlo = g_wtlo[which];
    const float* bias = which ? bV : bQ;
    float* C = which ? g_V : g_Q;

    float acc[2][8][4];
#pragma unroll
    for (int i = 0; i < 2; i++)
#pragma unroll
        for (int j = 0; j < 8; j++)
#pragma unroll
            for (int k = 0; k < 4; k++) acc[i][j][k] = 0.f;

    for (int slab = 0; slab < 16; slab++) {
        const int kt = slab * 32;
#pragma unroll
        for (int i = 0; i < 2; i++) {
            const int e = tid + i * 512;
            const int m = e >> 3, k4 = e & 7;
            float4 v = *(const float4*)&x[(size_t)(mbase + m) * Dd + kt + k4 * 4];
            __nv_bfloat162 h01 = __floats2bfloat162_rn(v.x, v.y);
            __nv_bfloat162 h23 = __floats2bfloat162_rn(v.z, v.w);
            __nv_bfloat162 l01 = __floats2bfloat162_rn(v.x - __low2float(h01),
                                                       v.y - __high2float(h01));
            __nv_bfloat162 l23 = __floats2bfloat162_rn(v.z - __low2float(h23),
                                                       v.w - __high2float(h23));
            const int off = m * PITCH + k4 * 4;
            *(__nv_bfloat162*)(sm16 + A_HI + off)     = h01;
            *(__nv_bfloat162*)(sm16 + A_HI + off + 2) = h23;
            *(__nv_bfloat162*)(sm16 + A_LO + off)     = l01;
            *(__nv_bfloat162*)(sm16 + A_LO + off + 2) = l23;
        }
#pragma unroll
        for (int i = 0; i < 4; i++) {
            const int e = tid + i * 512;
            const int split = e >> 10;
            const int r = (e >> 2) & 255;
            const int k8 = e & 3;
            const __nv_bfloat16* src = (split ? Wlo : Whi)
                + (size_t)(ncol0 + r) * Dd + kt + k8 * 8;
            *(uint4*)(sm16 + (split ? B_LO : B_HI) + r * PITCH + k8 * 8)
                = *(const uint4*)src;
        }
        __syncthreads();

#pragma unroll
        for (int kk = 0; kk < 32; kk += 16) {
            uint32_t ah[2][4], al[2][4];
#pragma unroll
            for (int mt = 0; mt < 2; mt++) {
                const int ro = (wm * 32 + mt * 16 + g) * PITCH + kk + 2 * tg;
                ah[mt][0] = *(const uint32_t*)(sm16 + A_HI + ro);
                ah[mt][1] = *(const uint32_t*)(sm16 + A_HI + ro + 8 * PITCH);
                ah[mt][2] = *(const uint32_t*)(sm16 + A_HI + ro + 8);
                ah[mt][3] = *(const uint32_t*)(sm16 + A_HI + ro + 8 * PITCH + 8);
                al[mt][0] = *(const uint32_t*)(sm16 + A_LO + ro);
                al[mt][1] = *(const uint32_t*)(sm16 + A_LO + ro + 8 * PITCH);
                al[mt][2] = *(const uint32_t*)(sm16 + A_LO + ro + 8);
                al[mt][3] = *(const uint32_t*)(sm16 + A_LO + ro + 8 * PITCH + 8);
            }
#pragma unroll
            for (int ng = 0; ng < 2; ng++) {
                uint32_t bh[4][2], bl[4][2];
#pragma unroll
                for (int q = 0; q < 4; q++) {
                    const int ro = (wn * 64 + (ng * 4 + q) * 8 + g) * PITCH + kk + 2 * tg;
                    bh[q][0] = *(const uint32_t*)(sm16 + B_HI + ro);
                    bh[q][1] = *(const uint32_t*)(sm16 + B_HI + ro + 8);
                    bl[q][0] = *(const uint32_t*)(sm16 + B_LO + ro);
                    bl[q][1] = *(const uint32_t*)(sm16 + B_LO + ro + 8);
                }
#pragma unroll
                for (int mt = 0; mt < 2; mt++)
#pragma unroll
                    for (int q = 0; q < 4; q++) {
                        float* d = acc[mt][ng * 4 + q];
                        MMA_BF16(d, ah[mt], bh[q]);
                        MMA_BF16(d, ah[mt], bl[q]);
                        MMA_BF16(d, al[mt], bh[q]);
                    }
            }
        }
        __syncthreads();
    }

#pragma unroll
    for (int mt = 0; mt < 2; mt++) {
        const int r0 = mbase + wm * 32 + mt * 16 + g;
#pragma unroll
        for (int nt = 0; nt < 8; nt++) {
            const int col = ncol0 + wn * 64 + nt * 8 + 2 * tg;
            float2 b2 = *(const float2*)&bias[col];
            float2 o0, o1;
            o0.x = acc[mt][nt][0] + b2.x;
            o0.y = acc[mt][nt][1] + b2.y;
            o1.x = acc[mt][nt][2] + b2.x;
            o1.y = acc[mt][nt][3] + b2.y;
            *(float2*)&C[(size_t)r0 * Dd + col] = o0;
            *(float2*)&C[(size_t)(r0 + 8) * Dd + col] = o1;
        }
    }
}

// ================= bucket kernel: GEMM (FFMA2) + argmax + margin flag =======
#define AsP 68
#define BsP 132
#define SMEM_BKT ((128 * AsP + 64 * BsP) * 4)

__global__ __launch_bounds__(256, 2)
void bucket_kernel(const float* __restrict__ rot)
{
    extern __shared__ float smf[];
    float* As = smf;                  // [128 m][68 k]
    float* Bs = smf + 128 * AsP;      // [64 k][132 c]

    const int h = blockIdx.y, n = blockIdx.z;
    const int tid = threadIdx.x;      // 256
    const int tx = tid & 15, ty = tid >> 4;
    const int t0 = blockIdx.x * 128;

    const float* Qb = g_Q + ((size_t)n * Tt + t0) * Dd + h * DHh;
#pragma unroll
    for (int l = 0; l < 8; l++) {
        const int e = tid + l * 256;
        const int r = e >> 4, c4 = e & 15;
        *(float4*)&As[r * AsP + c4 * 4] = *(const float4*)&Qb[(size_t)r * Dd + c4 * 4];
    }
    const float* Rb = rot + (size_t)h * 8192;
#pragma unroll
    for (int l = 0; l < 8; l++) {
        const int e = tid + l * 256;
        const int kr = e >> 5, c4 = e & 31;
        *(float4*)&Bs[kr * BsP + c4 * 4] = *(const float4*)&Rb[kr * 128 + c4 * 4];
    }
    __syncthreads();

    u64 acc2[8][4];
#pragma unroll
    for (int i = 0; i < 8; i++)
#pragma unroll
        for (int j = 0; j < 4; j++) acc2[i][j] = 0ull;

#pragma unroll 4
    for (int k = 0; k < 64; k++) {
        float a[8];
#pragma unroll
        for (int i = 0; i < 8; i++) a[i] = As[(ty * 8 + i) * AsP + k];
        u64 a2[8];
#pragma unroll
        for (int i = 0; i < 8; i++) PACK2(a2[i], a[i], a[i]);
        ulonglong2 bp0 = *(const ulonglong2*)&Bs[k * BsP + tx * 8];
        ulonglong2 bp1 = *(const ulonglong2*)&Bs[k * BsP + tx * 8 + 4];
        u64 b2[4] = {bp0.x, bp0.y, bp1.x, bp1.y};
#pragma unroll
        for (int i = 0; i < 8; i++)
#pragma unroll
            for (int j = 0; j < 4; j++) FFMA2(acc2[i][j], a2[i], b2[j]);
    }

    const int ig = (tx & 3) * 8;
    const int r = tx >> 2;
#pragma unroll
    for (int i = 0; i < 8; i++) {
        float acc[8];
#pragma unroll
        for (int jp = 0; jp < 4; jp++)
            UNPACK2(acc[2 * jp], acc[2 * jp + 1], acc2[i][jp]);

        // local top1 (val,idx first-occurrence) + top2 value
        float t1 = acc[0]; int i1 = ig; float t2 = -3.4e38f;
#pragma unroll
        for (int j = 1; j < 8; j++) {
            float v = acc[j];
            if (v > t1) { t2 = t1; t1 = v; i1 = ig + j; }
            else t2 = fmaxf(t2, v);
        }
#pragma unroll
        for (int j = 0; j < 8; j++) {
            float v = -acc[j];
            if (v > t1) { t2 = t1; t1 = v; i1 = 32 + ig + j; }
            else t2 = fmaxf(t2, v);
        }
        // merge across the 4 threads of this round
#pragma unroll
        for (int o = 1; o <= 2; o <<= 1) {
            float o1 = __shfl_xor_sync(0xffffffffu, t1, o);
            int   oi = __shfl_xor_sync(0xffffffffu, i1, o);
            float o2 = __shfl_xor_sync(0xffffffffu, t2, o);
            if (o1 > t1 || (o1 == t1 && oi < i1)) {
                t2 = fmaxf(t1, o2); t1 = o1; i1 = oi;
            } else {
                t2 = fmaxf(t2, o1);
            }
        }

        if ((tx & 3) == 0) {
            const int t = t0 + ty * 8 + i;
            g_buckets[(((size_t)n * Hh + h) * NHh + r) * Tt + t] = i1 + r * NBb;
            // error sigma ~4e-5 abs; threshold ~2.1e-3 abs = ~52 sigma
            if (t1 - t2 < 1e-4f * t1 + 1e-4f) {
                int p = atomicAdd(&g_nflags, 1);
                if (p < MAXF)
                    g_flags[p] = (n << 17) | (h << 14) | (r << 12) | t;
            }
        }
    }
}

// ================= fix-up: exact recompute of flagged decisions =============
#define FCAP 6144
#define OF_LST 0
#define OF_XB  (FCAP * 4)
#define OF_QB  (FCAP * 4 + 8 * 4 * 512 * 4)
#define SMEM_FIX (FCAP * 4 + 8 * 4 * 512 * 4 + 8 * 4 * 64 * 4)

__global__ __launch_bounds__(256)
void fixup_kernel(const float* __restrict__ x, const float* __restrict__ WQ,
                  const float* __restrict__ bQ, const float* __restrict__ rot)
{
    extern __shared__ char fsm[];
    int*   lst = (int*)(fsm + OF_LST);
    float* xb  = (float*)(fsm + OF_XB);    // [8 warps][4 flags][512]
    float* qb  = (float*)(fsm + OF_QB);    // [8 warps][4 flags][64]
    __shared__ int lcnt;

    const int bin = blockIdx.x;            // n*8 + h
    const int slice = blockIdx.y;          // 0..7
    const int n = bin >> 3, h = bin & 7;
    const int tid = threadIdx.x;
    const int w = tid >> 5, lane = tid & 31;

    if (tid == 0) lcnt = 0;
    __syncthreads();

    int count = g_nflags;
    if (count > MAXF) count = MAXF;
    for (int e = tid; e < count; e += 256) {
        const int pk = g_flags[e];
        if (((pk >> 14) & 31) == bin && (e & 7) == slice) {
            int p = atomicAdd(&lcnt, 1);
            if (p < FCAP) lst[p] = pk;
        }
    }
    __syncthreads();
    int nf = lcnt;
    if (nf > FCAP) nf = FCAP;

    float* xw = xb + w * 4 * 512;
    float* qw = qb + w * 4 * 64;

    for (int s = w * 4; s < nf; s += 32) {
        const int nn = min(4, nf - s);
        for (int ff = 0; ff < nn; ff++) {
            const int t = lst[s + ff] & 4095;
            const float* xr = x + ((size_t)n * Tt + t) * Dd;
            for (int e4 = lane; e4 < 128; e4 += 32)
                *(float4*)&xw[ff * 512 + e4 * 4] = *(const float4*)&xr[e4 * 4];
        }
        __syncwarp();

        float acc[4][2];
#pragma unroll
        for (int ff = 0; ff < 4; ff++) { acc[ff][0] = 0.f; acc[ff][1] = 0.f; }
        const float* Wc = WQ + h * 64;
        for (int k = 0; k < Dd; k++) {
            const float w0 = Wc[(size_t)k * Dd + lane];
            const float w1 = Wc[(size_t)k * Dd + lane + 32];
#pragma unroll
            for (int ff = 0; ff < 4; ff++) {
                acc[ff][0] += xw[ff * 512 + k] * w0;
                acc[ff][1] += xw[ff * 512 + k] * w1;
            }
        }
        const float b0 = bQ[h * 64 + lane], b1 = bQ[h * 64 + lane + 32];
        for (int ff = 0; ff < nn; ff++) {
            qw[ff * 64 + lane]      = acc[ff][0] + b0;
            qw[ff * 64 + lane + 32] = acc[ff][1] + b1;
        }
        __syncwarp();

        for (int ff = 0; ff < nn; ff++) {
            const int pk = lst[s + ff];
            const int t = pk & 4095, r = (pk >> 12) & 3;
            const float* rp = rot + (size_t)h * 8192 + r * 32 + lane;
            float v = 0.f;
#pragma unroll 8
            for (int f = 0; f < 64; f++)
                v += qw[ff * 64 + f] * rp[f * 128];
            float bv; int bi;
            if (-v > v) { bv = -v; bi = 32 + lane; }
            else        { bv = v;  bi = lane; }
#pragma unroll
            for (int o = 16; o; o >>= 1) {
                float ov = __shfl_xor_sync(0xffffffffu, bv, o);
                int   oi = __shfl_xor_sync(0xffffffffu, bi, o);
                if (ov > bv || (ov == bv && oi < bi)) { bv = ov; bi = oi; }
            }
            if (lane == 0)
                g_buckets[(((size_t)n * Hh + h) * NHh + r) * Tt + t] = bi + r * NBb;
        }
        __syncwarp();
    }
}

// ================= segmented stable counting sort per (n,h) =================
#define HROW 258
#define SMEM_SORT (Ll + 256 * HROW * 2 + 256 * 4)
__global__ void sort_kernel()
{
    extern __shared__ char smraw[];
    unsigned char*  sb   = (unsigned char*)smraw;
    unsigned short* hist = (unsigned short*)(smraw + Ll);
    int*            base = (int*)(smraw + Ll + 256 * HROW * 2);
    __shared__ int tot[256];

    const int nh = blockIdx.x;
    const int tid = threadIdx.x;

    for (int e = tid; e < 256 * HROW / 2; e += 256)
        ((unsigned int*)hist)[e] = 0;
    __syncthreads();

    const int* bptr = g_buckets + (size_t)nh * Ll;
    for (int e = tid; e < Ll; e += 256)
        sb[e] = (unsigned char)bptr[e];
    __syncthreads();

    {
        const int s = tid;
#pragma unroll 4
        for (int j = 0; j < 64; j++) {
            int b = sb[s * 64 + j];
            hist[b * HROW + s]++;
        }
    }
    __syncthreads();

    {
        const unsigned short* row = &hist[tid * HROW];
        int sum = 0;
#pragma unroll 8
        for (int s2 = 0; s2 < 256; s2++) sum += row[s2];
        tot[tid] = sum;
    }
    __syncthreads();
    if (tid == 0) {
        int run = 0;
        for (int b = 0; b < 256; b++) { base[b] = run; run += tot[b]; }
    }
    __syncthreads();

    {
        unsigned short* row = &hist[tid * HROW];
        unsigned short run = 0;
        for (int s2 = 0; s2 < 256; s2++) {
            unsigned short v = row[s2];
            row[s2] = run;
            run = (unsigned short)(run + v);
        }
    }
    __syncthreads();

    {
        const int s = tid;
        int* pout = g_perm + (size_t)nh * Ll;
        for (int j = 0; j < 64; j++) {
            int i = s * 64 + j;
            int b = sb[i];
            unsigned short off = hist[b * HROW + s];
            hist[b * HROW + s] = (unsigned short)(off + 1);
            pout[base[b] + off] = (b << 16) | i;
        }
    }
}

// ================= chunked attention (raw-q dots, column norm scale) ========
#define KHP 72
#define VP  72
#define OKH_HI 0
#define OKH_LO 18432
#define OV_HI  36864
#define OV_LO  55296
#define OMETA  73728
#define ORNORM 74240
#define OINVS  74752
#define SMEM_ATT3 75008

__global__ __launch_bounds__(128, 3)
void attention_kernel()
{
    extern __shared__ char smb[];
    __nv_bfloat16* kh_hi = (__nv_bfloat16*)(smb + OKH_HI);   // [128][72] raw q
    __nv_bfloat16* kh_lo = (__nv_bfloat16*)(smb + OKH_LO);
    __nv_bfloat16* v_hi  = (__nv_bfloat16*)(smb + OV_HI);    // [128][72]
    __nv_bfloat16* v_lo  = (__nv_bfloat16*)(smb + OV_LO);
    int*   pmeta = (int*)(smb + OMETA);                      // 128
    float* rnorm = (float*)(smb + ORNORM);                   // 128 (1/(||q||+eps))
    float* invs  = (float*)(smb + OINVS);                    // 64

    const int c = blockIdx.x, h = blockIdx.y, n = blockIdx.z;
    const int tid = threadIdx.x;
    const int pc = (c + CSs - 1) % CSs;

    {
        const int p = (tid < 64) ? (c * BSs + tid) : (pc * BSs + (tid - 64));
        pmeta[tid] = g_perm[((size_t)n * Hh + h) * Ll + p];
    }
    __syncthreads();

    const float* Qb = g_Q + (size_t)n * Tt * Dd + h * DHh;
    const float* Vb = g_V + (size_t)n * Tt * Dd + h * DHh;
    const int sub = tid >> 4, c4 = tid & 15;
#pragma unroll
    for (int i = 0; i < 16; i++) {
        const int row = i * 8 + sub;
        const int t = pmeta[row] & 4095;
        float4 qv = *(const float4*)&Qb[(size_t)t * Dd + c4 * 4];
        // raw q -> smem hi/lo (stores independent of the norm reduction)
        __nv_bfloat162 kh01 = __floats2bfloat162_rn(qv.x, qv.y);
        __nv_bfloat162 kl01 = __floats2bfloat162_rn(qv.x - __low2float(kh01), qv.y - __high2float(kh01));
        __nv_bfloat162 kh23 = __floats2bfloat162_rn(qv.z, qv.w);
        __nv_bfloat162 kl23 = __floats2bfloat162_rn(qv.z - __low2float(kh23), qv.w - __high2float(kh23));
        *(__nv_bfloat162*)&kh_hi[row * KHP + c4 * 4]     = kh01;
        *(__nv_bfloat162*)&kh_hi[row * KHP + c4 * 4 + 2] = kh23;
        *(__nv_bfloat162*)&kh_lo[row * KHP + c4 * 4]     = kl01;
        *(__nv_bfloat162*)&kh_lo[row * KHP + c4 * 4 + 2] = kl23;

        float4 vv = *(const float4*)&Vb[(size_t)t * Dd + c4 * 4];
        __nv_bfloat162 vh01 = __floats2bfloat162_rn(vv.x, vv.y);
        __nv_bfloat162 vl01 = __floats2bfloat162_rn(vv.x - __low2float(vh01), vv.y - __high2float(vh01));
        __nv_bfloat162 vh23 = __floats2bfloat162_rn(vv.z, vv.w);
        __nv_bfloat162 vl23 = __floats2bfloat162_rn(vv.z - __low2float(vh23), vv.w - __high2float(vh23));
        *(__nv_bfloat162*)&v_hi[row * VP + c4 * 4]     = vh01;
        *(__nv_bfloat162*)&v_hi[row * VP + c4 * 4 + 2] = vh23;
        *(__nv_bfloat162*)&v_lo[row * VP + c4 * 4]     = vl01;
        *(__nv_bfloat162*)&v_lo[row * VP + c4 * 4 + 2] = vl23;

        // norm (only feeds rnorm[], not the stores above)
        float ss = qv.x * qv.x + qv.y * qv.y + qv.z * qv.z + qv.w * qv.w;
        ss += __shfl_xor_sync(0xffffffffu, ss, 1);
        ss += __shfl_xor_sync(0xffffffffu, ss, 2);
        ss += __shfl_xor_sync(0xffffffffu, ss, 4);
        ss += __shfl_xor_sync(0xffffffffu, ss, 8);
        if (c4 == 0) rnorm[row] = 1.f / (sqrtf(ss) + 1e-6f);
    }
    __syncthreads();

    const int w = tid >> 5, lane = tid & 31;
    const int g = lane >> 2, tg = lane & 3;
    const int i0 = w * 16;

    const uint32_t khb_hi = smem_u32(kh_hi), khb_lo = smem_u32(kh_lo);
    const uint32_t vb_hi  = smem_u32(v_hi),  vb_lo  = smem_u32(v_lo);
    const uint32_t aoff = ((i0 + (lane & 15)) * KHP + 8 * (lane >> 4)) * 2;
    const uint32_t boff = (((lane & 7) + ((lane >= 16) ? 8 : 0)) * KHP + ((lane >> 3) & 1) * 8) * 2;
    const uint32_t voff = (((lane & 7) + 8 * ((lane >> 3) & 1)) * VP + 8 * (lane >> 4)) * 2;

    // ---- dots: D_ij = q_i . q_j (raw) ----
    float dc[16][4];
#pragma unroll
    for (int nt = 0; nt < 16; nt++)
#pragma unroll
        for (int k = 0; k < 4; k++) dc[nt][k] = 0.f;

#pragma unroll
    for (int k0 = 0; k0 < 64; k0 += 16) {
        uint32_t ah[4], al[4];
        LDSM4(ah[0], ah[1], ah[2], ah[3], khb_hi + aoff + k0 * 2);
        LDSM4(al[0], al[1], al[2], al[3], khb_lo + aoff + k0 * 2);
#pragma unroll
        for (int jt = 0; jt < 8; jt++) {
            uint32_t bh[4], bl[4];
            const uint32_t jb = (uint32_t)(jt * 16 * KHP + k0) * 2;
            LDSM4(bh[0], bh[1], bh[2], bh[3], khb_hi + boff + jb);
            LDSM4(bl[0], bl[1], bl[2], bl[3], khb_lo + boff + jb);
            MMA_BF16(dc[2 * jt], ah, bh);
            MMA_BF16(dc[2 * jt], ah, bl);
            MMA_BF16(dc[2 * jt], al, bh);
            MMA_BF16(dc[2 * jt + 1], ah, bh + 2);
            MMA_BF16(dc[2 * jt + 1], ah, bl + 2);
            MMA_BF16(dc[2 * jt + 1], al, bh + 2);
        }
    }

    // ---- masks + softmax; S_ij = D_ij * 0.125 * rnorm_j (column scale) ----
    const int ra = i0 + g, rb = i0 + g + 8;
    {
        const int pka = pmeta[ra], pkb = pmeta[rb];

#pragma unroll
        for (int nt = 0; nt < 16; nt++) {
            const int j0 = nt * 8 + 2 * tg;
            const int pj0 = pmeta[j0], pj1 = pmeta[j0 + 1];
            const float s0 = 0.125f * rnorm[j0];
            const float s1 = 0.125f * rnorm[j0 + 1];
            float x;
            x = dc[nt][0] * s0;
            if ((pka >> 16) != (pj0 >> 16)) x = -1e9f;
            if (((pka ^ pj0) & 4095) == 0)  x = -1e-5f;
            dc[nt][0] = x;
            x = dc[nt][1] * s1;
            if ((pka >> 16) != (pj1 >> 16)) x = -1e9f;
            if (((pka ^ pj1) & 4095) == 0)  x = -1e-5f;
            dc[nt][1] = x;
            x = dc[nt][2] * s0;
            if ((pkb >> 16) != (pj0 >> 16)) x = -1e9f;
            if (((pkb ^ pj0) & 4095) == 0)  x = -1e-5f;
            dc[nt][2] = x;
            x = dc[nt][3] * s1;
            if ((pkb >> 16) != (pj1 >> 16)) x = -1e9f;
            if (((pkb ^ pj1) & 4095) == 0)  x = -1e-5f;
            dc[nt][3] = x;
        }

        float ma = -1e30f, mb = -1e30f;
#pragma unroll
        for (int nt = 0; nt < 16; nt++) {
            ma = fmaxf(ma, fmaxf(dc[nt][0], dc[nt][1]));
            mb = fmaxf(mb, fmaxf(dc[nt][2], dc[nt][3]));
        }
        ma = fmaxf(ma, __shfl_xor_sync(0xffffffffu, ma, 1));
        ma = fmaxf(ma, __shfl_xor_sync(0xffffffffu, ma, 2));
        mb = fmaxf(mb, __shfl_xor_sync(0xffffffffu, mb, 1));
        mb = fmaxf(mb, __shfl_xor_sync(0xffffffffu, mb, 2));

        float sa = 0.f, sb2 = 0.f;
#pragma unroll
        for (int nt = 0; nt < 16; nt++) {
            dc[nt][0] = __expf(dc[nt][0] - ma); sa  += dc[nt][0];
            dc[nt][1] = __expf(dc[nt][1] - ma); sa  += dc[nt][1];
            dc[nt][2] = __expf(dc[nt][2] - mb); sb2 += dc[nt][2];
            dc[nt][3] = __expf(dc[nt][3] - mb); sb2 += dc[nt][3];
        }
        sa  += __shfl_xor_sync(0xffffffffu, sa, 1);
        sa  += __shfl_xor_sync(0xffffffffu, sa, 2);
        sb2 += __shfl_xor_sync(0xffffffffu, sb2, 1);
        sb2 += __shfl_xor_sync(0xffffffffu, sb2, 2);

        if (tg == 0) {
            const int nhbase = ((int)n * Hh + h) * NHh;
            const int ta = pka & 4095, rra = (pka >> 12) & 3;
            const int tb = pkb & 4095, rrb = (pkb >> 12) & 3;
            g_logits[((size_t)nhbase + rra) * Tt + ta] = ma + __logf(sa);
            g_logits[((size_t)nhbase + rrb) * Tt + tb] = mb + __logf(sb2);
            invs[ra] = 1.f / sa;
            invs[rb] = 1.f / sb2;
        }
        __syncwarp();
    }

    // ---- PV: O = P @ V, P fed straight from registers ----
    float oc[8][4];
#pragma unroll
    for (int nt = 0; nt < 8; nt++)
#pragma unroll
        for (int k = 0; k < 4; k++) oc[nt][k] = 0.f;

#pragma unroll
    for (int kc = 0; kc < 8; kc++) {
        uint32_t phi[4], plo[4];
        {
            __nv_bfloat162 hp, lp;
            hp = __floats2bfloat162_rn(dc[2 * kc][0], dc[2 * kc][1]);
            lp = __floats2bfloat162_rn(dc[2 * kc][0] - __low2float(hp),
                                       dc[2 * kc][1] - __high2float(hp));
            phi[0] = *(uint32_t*)&hp; plo[0] = *(uint32_t*)&lp;
            hp = __floats2bfloat162_rn(dc[2 * kc][2], dc[2 * kc][3]);
            lp = __floats2bfloat162_rn(dc[2 * kc][2] - __low2float(hp),
                                       dc[2 * kc][3] - __high2float(hp));
            phi[1] = *(uint32_t*)&hp; plo[1] = *(uint32_t*)&lp;
            hp = __floats2bfloat162_rn(dc[2 * kc + 1][0], dc[2 * kc + 1][1]);
            lp = __floats2bfloat162_rn(dc[2 * kc + 1][0] - __low2float(hp),
                                       dc[2 * kc + 1][1] - __high2float(hp));
            phi[2] = *(uint32_t*)&hp; plo[2] = *(uint32_t*)&lp;
            hp = __floats2bfloat162_rn(dc[2 * kc + 1][2], dc[2 * kc + 1][3]);
            lp = __floats2bfloat162_rn(dc[2 * kc + 1][2] - __low2float(hp),
                                       dc[2 * kc + 1][3] - __high2float(hp));
            phi[3] = *(uint32_t*)&hp; plo[3] = *(uint32_t*)&lp;
        }
#pragma unroll
        for (int ft = 0; ft < 4; ft++) {
            uint32_t vh[4], vl[4];
            const uint32_t vbo = (uint32_t)(kc * 16 * VP + ft * 16) * 2;
            LDSM4T(vh[0], vh[1], vh[2], vh[3], vb_hi + voff + vbo);
            LDSM4T(vl[0], vl[1], vl[2], vl[3], vb_lo + voff + vbo);
            MMA_BF16(oc[2 * ft], phi, vh);
            MMA_BF16(oc[2 * ft], phi, vl);
            MMA_BF16(oc[2 * ft], plo, vh);
            MMA_BF16(oc[2 * ft + 1], phi, vh + 2);
            MMA_BF16(oc[2 * ft + 1], phi, vl + 2);
            MMA_BF16(oc[2 * ft + 1], plo, vh + 2);
        }
    }

    {
        const int pka = pmeta[ra], pkb = pmeta[rb];
        const float iva = invs[ra], ivb = invs[rb];
        const size_t obase = ((size_t)n * Hh + h) * NHh;
        const size_t oa = ((obase + ((pka >> 12) & 3)) * Tt + (pka & 4095)) * DHh;
        const size_t ob = ((obase + ((pkb >> 12) & 3)) * Tt + (pkb & 4095)) * DHh;
#pragma unroll
        for (int ft = 0; ft < 4; ft++) {
            const int f0 = ft * 16 + 2 * tg;
            *(float2*)&g_O[oa + f0]     = make_float2(oc[2 * ft][0] * iva, oc[2 * ft][1] * iva);
            *(float2*)&g_O[ob + f0]     = make_float2(oc[2 * ft][2] * ivb, oc[2 * ft][3] * ivb);
            *(float2*)&g_O[oa + f0 + 8] = make_float2(oc[2 * ft + 1][0] * iva, oc[2 * ft + 1][1] * iva);
            *(float2*)&g_O[ob + f0 + 8] = make_float2(oc[2 * ft + 1][2] * ivb, oc[2 * ft + 1][3] * ivb);
        }
    }
}

// ================= round-combine softmax + LayerNorm (shfl reduce) ==========
__global__ void combine_ln_kernel(const float* __restrict__ gamma,
                                  const float* __restrict__ beta,
                                  float* __restrict__ out)
{
    const int bid = blockIdx.x;            // n*T + t
    const int n = bid >> 12, t = bid & 4095;
    const int tid = threadIdx.x;           // 128
    const int w = tid >> 5, lane = tid & 31;
    __shared__ float wsh[Hh][NHh];
    __shared__ float rs[4], rq[4];

    if (tid < Hh) {
        const int h = tid;
        float l[NHh];
        float m = -1e30f;
#pragma unroll
        for (int r = 0; r < NHh; r++) {
            l[r] = g_logits[(((size_t)n * Hh + h) * NHh + r) * Tt + t];
            m = fmaxf(m, l[r]);
        }
        float s = 0.f;
#pragma unroll
        for (int r = 0; r < NHh; r++) s += __expf(l[r] - m);
        const float lse = m + __logf(s);
#pragma unroll
        for (int r = 0; r < NHh; r++) wsh[h][r] = __expf(l[r] - lse);
    }
    __syncthreads();

    float vals[4];
    float lsum = 0.f, lsq = 0.f;
#pragma unroll
    for (int k2 = 0; k2 < 4; k2++) {
        const int d = tid + k2 * 128;
        const int h = d >> 6, f = d & 63;
        float a = 0.f;
#pragma unroll
        for (int r = 0; r < NHh; r++)
            a += wsh[h][r] * g_O[((((size_t)n * Hh + h) * NHh + r) * Tt + t) * DHh + f];
        vals[k2] = a;
        lsum += a;
        lsq  += a * a;
    }

#pragma unroll
    for (int o = 16; o; o >>= 1) {
        lsum += __shfl_xor_sync(0xffffffffu, lsum, o);
        lsq  += __shfl_xor_sync(0xffffffffu, lsq, o);
    }
    if (lane == 0) { rs[w] = lsum; rq[w] = lsq; }
    __syncthreads();
    const float ts = rs[0] + rs[1] + rs[2] + rs[3];
    const float tq = rq[0] + rq[1] + rq[2] + rq[3];
    const float mu = ts * (1.f / Dd);
    const float var = tq * (1.f / Dd) - mu * mu;
    const float rstd = rsqrtf(var + 1e-3f);

#pragma unroll
    for (int k2 = 0; k2 < 4; k2++) {
        const int d = tid + k2 * 128;
        out[(size_t)bid * Dd + d] = gamma[d] * (vals[k2] - mu) * rstd + beta[d];
    }
}

// ================= launch ===================================================
extern "C" void kernel_launch(void* const* d_in, const int* in_sizes, int n_in,
                              void* d_out, int out_size)
{
    const float* x     = (const float*)d_in[0];
    const float* W_Q   = (const float*)d_in[1];
    const float* b_Q   = (const float*)d_in[2];
    const float* W_V   = (const float*)d_in[3];
    const float* b_V   = (const float*)d_in[4];
    const float* gamma = (const float*)d_in[5];
    const float* beta  = (const float*)d_in[6];
    const float* rot   = (const float*)d_in[7];
    float* out = (float*)d_out;

    cudaFuncSetAttribute(attention_kernel,
                         cudaFuncAttributeMaxDynamicSharedMemorySize, SMEM_ATT3);
    cudaFuncSetAttribute(sort_kernel,
                         cudaFuncAttributeMaxDynamicSharedMemorySize, SMEM_SORT);
    cudaFuncSetAttribute(gemm_qv_kernel,
                         cudaFuncAttributeMaxDynamicSharedMemorySize, SMEM_MMA);
    cudaFuncSetAttribute(bucket_kernel,
                         cudaFuncAttributeMaxDynamicSharedMemorySize, SMEM_BKT);
    cudaFuncSetAttribute(fixup_kernel,
                         cudaFuncAttributeMaxDynamicSharedMemorySize, SMEM_FIX);

    reset_kernel<<<1, 1>>>();

    split_w_kernel<<<dim3(16, 16, 2), dim3(32, 8)>>>(W_Q, W_V);

    dim3 gGrid(2, (Nb * Tt) / 128, 2);          // (2, 128, 2) -> Q and V
    gemm_qv_kernel<<<gGrid, 512, SMEM_MMA>>>(x, b_Q, b_V);

    dim3 bGrid(Tt / 128, Hh, Nb);               // (32, 8, 4)
    bucket_kernel<<<bGrid, 256, SMEM_BKT>>>(rot);

    fixup_kernel<<<dim3(32, 8), 256, SMEM_FIX>>>(x, W_Q, b_Q, rot);

    sort_kernel<<<Nb * Hh, 256, SMEM_SORT>>>(); // 32 blocks

    dim3 aGrid(CSs, Hh, Nb);                    // (256, 8, 4)
    attention_kernel<<<aGrid, 128, SMEM_ATT3>>>();

    combine_ln_kernel<<<Nb * Tt, 128>>>(gamma, beta, out);
}

// round 13
// speedup vs baseline: 1.2143x; 1.0105x over previous
#include <cuda_runtime.h>
#include <cuda_bf16.h>
#include <math.h>
#include <stdint.h>

// Problem constants
#define Nb   4          // batch
#define Tt   4096       // sequence length
#define Dd   512        // model dim
#define Hh   8          // heads
#define NHh  4          // hash rounds
#define BSs  64         // bucket chunk size
#define DHh  64         // head dim
#define NBb  64         // n_buckets
#define CSs  256        // chunks = NH * NB
#define Ll   16384      // NH * T

typedef unsigned long long u64;

// ---------------- scratch (device globals; no allocation allowed) ----------
__device__ float g_Q[(size_t)Nb * Tt * Dd];                 // 33.5 MB
__device__ float g_V[(size_t)Nb * Tt * Dd];                 // 33.5 MB
__device__ int   g_buckets[(size_t)Nb * Hh * NHh * Tt];     // 2 MB
__device__ int   g_perm[(size_t)Nb * Hh * Ll];              // 2 MB
__device__ float g_O[(size_t)Nb * Hh * NHh * Tt * DHh];     // 134 MB
__device__ float g_logits[(size_t)Nb * Hh * NHh * Tt];      // 2 MB
__device__ __nv_bfloat16 g_wthi[2][Dd * Dd];                // 1 MB (W^T hi: 0=Q,1=V)
__device__ __nv_bfloat16 g_wtlo[2][Dd * Dd];                // 1 MB
#define MAXF 131072
__device__ int g_nflags;
__device__ int g_flags[MAXF];                               // packed (n<<17)|(h<<14)|(r<<12)|t

// ================= helpers ==================================================
__device__ __forceinline__ uint32_t smem_u32(const void* p) {
    uint32_t a;
    asm("{ .reg .u64 t; cvta.to.shared.u64 t, %1; cvt.u32.u64 %0, t; }" : "=r"(a) : "l"(p));
    return a;
}
#define MMA_BF16(d, a, b)                                                     \
    asm volatile("mma.sync.aligned.m16n8k16.row.col.f32.bf16.bf16.f32 "       \
        "{%0,%1,%2,%3}, {%4,%5,%6,%7}, {%8,%9}, {%0,%1,%2,%3};"               \
        : "+f"((d)[0]), "+f"((d)[1]), "+f"((d)[2]), "+f"((d)[3])              \
        : "r"((a)[0]), "r"((a)[1]), "r"((a)[2]), "r"((a)[3]),                 \
          "r"((b)[0]), "r"((b)[1]))
#define LDSM4(r0, r1, r2, r3, addr)                                           \
    asm volatile("ldmatrix.sync.aligned.m8n8.x4.shared.b16 {%0,%1,%2,%3}, [%4];" \
        : "=r"(r0), "=r"(r1), "=r"(r2), "=r"(r3) : "r"(addr))
#define LDSM4T(r0, r1, r2, r3, addr)                                          \
    asm volatile("ldmatrix.sync.aligned.m8n8.x4.trans.shared.b16 {%0,%1,%2,%3}, [%4];" \
        : "=r"(r0), "=r"(r1), "=r"(r2), "=r"(r3) : "r"(addr))
#define FFMA2(d, a, b) \
    asm("fma.rn.f32x2 %0, %1, %2, %0;" : "+l"(d) : "l"(a), "l"(b))
#define PACK2(d, x, y) \
    asm("mov.b64 %0, {%1, %2};" : "=l"(d) : "f"(x), "f"(y))
#define UNPACK2(x, y, d) \
    asm("mov.b64 {%0, %1}, %2;" : "=f"(x), "=f"(y) : "l"(d))

// ================= reset ====================================================
__global__ void reset_kernel() { g_nflags = 0; }

// ================= split + transpose W_Q / W_V ==============================
__global__ void split_w_kernel(const float* __restrict__ WQ, const float* __restrict__ WV)
{
    __shared__ float tile[32][33];
    const float* W = blockIdx.z ? WV : WQ;
    const int bx = blockIdx.x * 32;   // n block
    const int by = blockIdx.y * 32;   // k block
    const int tx = threadIdx.x, ty = threadIdx.y;   // 32 x 8
#pragma unroll
    for (int r = 0; r < 32; r += 8)
        tile[ty + r][tx] = W[(size_t)(by + ty + r) * Dd + bx + tx];
    __syncthreads();
#pragma unroll
    for (int r = 0; r < 32; r += 8) {
        float val = tile[tx][ty + r];
        __nv_bfloat16 hi = __float2bfloat16(val);
        __nv_bfloat16 lo = __float2bfloat16(val - __bfloat162float(hi));
        size_t o = (size_t)(bx + ty + r) * Dd + by + tx;
        g_wthi[blockIdx.z][o] = hi;
        g_wtlo[blockIdx.z][o] = lo;
    }
}

// ================= Q/V GEMM: mma.sync bf16 3-term + ldmatrix ================
#define PITCH 40
#define A_HI  0
#define A_LO  (128 * PITCH)
#define B_HI  (2 * 128 * PITCH)
#define B_LO  (2 * 128 * PITCH + 256 * PITCH)
#define SMEM_MMA ((2 * 128 * PITCH + 2 * 256 * PITCH) * 2)
// byte offsets
#define ALO_B  (128 * PITCH * 2)
#define BHI_B  (2 * 128 * PITCH * 2)
#define BLO_D  (256 * PITCH * 2)    // B_LO - B_HI in bytes

__global__ __launch_bounds__(512, 1)
void gemm_qv_kernel(const float* __restrict__ x,
                    const float* __restrict__ bQ, const float* __restrict__ bV)
{
    extern __shared__ uint16_t sm16[];
    const int tid = threadIdx.x;
    const int wid = tid >> 5, lane = tid & 31;
    const int g = lane >> 2, tg = lane & 3;
    const int wm = wid & 3, wn = wid >> 2;
    const int mbase = blockIdx.y * 128;
    const int ncol0 = blockIdx.x * 256;
    const int which = blockIdx.z;                 // 0 = Q, 1 = V
    const __nv_bfloat16* Whi = g_wthi[which];
    const __nv_bfloat16* Wlo = g_wtlo[which];
    const float* bias = which ? bV : bQ;
    float* C = which ? g_V : g_Q;

    const uint32_t smbase = smem_u32(sm16);
    // ldmatrix per-lane offsets (verified patterns from attention kernel)
    const uint32_t aoff0 = ((wm * 32 + (lane & 15)) * PITCH + 8 * (lane >> 4)) * 2;
    const uint32_t boff0 = (((lane & 7) + ((lane >= 16) ? 8 : 0)) * PITCH
                            + ((lane >> 3) & 1) * 8) * 2;

    float acc[2][8][4];
#pragma unroll
    for (int i = 0; i < 2; i++)
#pragma unroll
        for (int j = 0; j < 8; j++)
#pragma unroll
            for (int k = 0; k < 4; k++) acc[i][j][k] = 0.f;

    for (int slab = 0; slab < 16; slab++) {
        const int kt = slab * 32;
#pragma unroll
        for (int i = 0; i < 2; i++) {
            const int e = tid + i * 512;
            const int m = e >> 3, k4 = e & 7;
            float4 v = *(const float4*)&x[(size_t)(mbase + m) * Dd + kt + k4 * 4];
            __nv_bfloat162 h01 = __floats2bfloat162_rn(v.x, v.y);
            __nv_bfloat162 h23 = __floats2bfloat162_rn(v.z, v.w);
            __nv_bfloat162 l01 = __floats2bfloat162_rn(v.x - __low2float(h01),
                                                       v.y - __high2float(h01));
            __nv_bfloat162 l23 = __floats2bfloat162_rn(v.z - __low2float(h23),
                                                       v.w - __high2float(h23));
            const int off = m * PITCH + k4 * 4;
            *(__nv_bfloat162*)(sm16 + A_HI + off)     = h01;
            *(__nv_bfloat162*)(sm16 + A_HI + off + 2) = h23;
            *(__nv_bfloat162*)(sm16 + A_LO + off)     = l01;
            *(__nv_bfloat162*)(sm16 + A_LO + off + 2) = l23;
        }
#pragma unroll
        for (int i = 0; i < 4; i++) {
            const int e = tid + i * 512;
            const int split = e >> 10;
            const int r = (e >> 2) & 255;
            const int k8 = e & 3;
            const __nv_bfloat16* src = (split ? Wlo : Whi)
                + (size_t)(ncol0 + r) * Dd + kt + k8 * 8;
            *(uint4*)(sm16 + (split ? B_LO : B_HI) + r * PITCH + k8 * 8)
                = *(const uint4*)src;
        }
        __syncthreads();

#pragma unroll
        for (int kk = 0; kk < 32; kk += 16) {
            uint32_t ah[2][4], al[2][4];
#pragma unroll
            for (int mt = 0; mt < 2; mt++) {
                const uint32_t aa = smbase + aoff0
                    + (uint32_t)(mt * 16 * PITCH + kk) * 2;
                LDSM4(ah[mt][0], ah[mt][1], ah[mt][2], ah[mt][3], aa);
                LDSM4(al[mt][0], al[mt][1], al[mt][2], al[mt][3], aa + ALO_B);
            }
#pragma unroll
            for (int ng = 0; ng < 2; ng++) {
                uint32_t bh[2][4], bl[2][4];
#pragma unroll
                for (int hh = 0; hh < 2; hh++) {
                    const uint32_t bb = smbase + BHI_B + boff0
                        + (uint32_t)((wn * 64 + ng * 32 + hh * 16) * PITCH + kk) * 2;
                    LDSM4(bh[hh][0], bh[hh][1], bh[hh][2], bh[hh][3], bb);
                    LDSM4(bl[hh][0], bl[hh][1], bl[hh][2], bl[hh][3], bb + BLO_D);
                }
                // per-acc order preserved: hh, hl, lh
#pragma unroll
                for (int mt = 0; mt < 2; mt++)
#pragma unroll
                    for (int q = 0; q < 4; q++) {
                        float* d = acc[mt][ng * 4 + q];
                        uint32_t* bhp = bh[q >> 1] + (q & 1) * 2;
                        uint32_t* blp = bl[q >> 1] + (q & 1) * 2;
                        MMA_BF16(d, ah[mt], bhp);
                        MMA_BF16(d, ah[mt], blp);
                        MMA_BF16(d, al[mt], bhp);
                    }
            }
        }
        __syncthreads();
    }

#pragma unroll
    for (int mt = 0; mt < 2; mt++) {
        const int r0 = mbase + wm * 32 + mt * 16 + g;
#pragma unroll
        for (int nt = 0; nt < 8; nt++) {
            const int col = ncol0 + wn * 64 + nt * 8 + 2 * tg;
            float2 b2 = *(const float2*)&bias[col];
            float2 o0, o1;
            o0.x = acc[mt][nt][0] + b2.x;
            o0.y = acc[mt][nt][1] + b2.y;
            o1.x = acc[mt][nt][2] + b2.x;
            o1.y = acc[mt][nt][3] + b2.y;
            *(float2*)&C[(size_t)r0 * Dd + col] = o0;
            *(float2*)&C[(size_t)(r0 + 8) * Dd + col] = o1;
        }
    }
}

// ================= bucket kernel: GEMM (FFMA2) + argmax + margin flag =======
#define AsP 68
#define BsP 132
#define SMEM_BKT ((128 * AsP + 64 * BsP) * 4)

__global__ __launch_bounds__(256, 2)
void bucket_kernel(const float* __restrict__ rot)
{
    extern __shared__ float smf[];
    float* As = smf;                  // [128 m][68 k]
    float* Bs = smf + 128 * AsP;      // [64 k][132 c]

    const int h = blockIdx.y, n = blockIdx.z;
    const int tid = threadIdx.x;      // 256
    const int tx = tid & 15, ty = tid >> 4;
    const int t0 = blockIdx.x * 128;

    const float* Qb = g_Q + ((size_t)n * Tt + t0) * Dd + h * DHh;
#pragma unroll
    for (int l = 0; l < 8; l++) {
        const int e = tid + l * 256;
        const int r = e >> 4, c4 = e & 15;
        *(float4*)&As[r * AsP + c4 * 4] = *(const float4*)&Qb[(size_t)r * Dd + c4 * 4];
    }
    const float* Rb = rot + (size_t)h * 8192;
#pragma unroll
    for (int l = 0; l < 8; l++) {
        const int e = tid + l * 256;
        const int kr = e >> 5, c4 = e & 31;
        *(float4*)&Bs[kr * BsP + c4 * 4] = *(const float4*)&Rb[kr * 128 + c4 * 4];
    }
    __syncthreads();

    u64 acc2[8][4];
#pragma unroll
    for (int i = 0; i < 8; i++)
#pragma unroll
        for (int j = 0; j < 4; j++) acc2[i][j] = 0ull;

#pragma unroll 4
    for (int k = 0; k < 64; k++) {
        float a[8];
#pragma unroll
        for (int i = 0; i < 8; i++) a[i] = As[(ty * 8 + i) * AsP + k];
        u64 a2[8];
#pragma unroll
        for (int i = 0; i < 8; i++) PACK2(a2[i], a[i], a[i]);
        ulonglong2 bp0 = *(const ulonglong2*)&Bs[k * BsP + tx * 8];
        ulonglong2 bp1 = *(const ulonglong2*)&Bs[k * BsP + tx * 8 + 4];
        u64 b2[4] = {bp0.x, bp0.y, bp1.x, bp1.y};
#pragma unroll
        for (int i = 0; i < 8; i++)
#pragma unroll
            for (int j = 0; j < 4; j++) FFMA2(acc2[i][j], a2[i], b2[j]);
    }

    const int ig = (tx & 3) * 8;
    const int r = tx >> 2;
#pragma unroll
    for (int i = 0; i < 8; i++) {
        float acc[8];
#pragma unroll
        for (int jp = 0; jp < 4; jp++)
            UNPACK2(acc[2 * jp], acc[2 * jp + 1], acc2[i][jp]);

        float t1 = acc[0]; int i1 = ig; float t2 = -3.4e38f;
#pragma unroll
        for (int j = 1; j < 8; j++) {
            float v = acc[j];
            if (v > t1) { t2 = t1; t1 = v; i1 = ig + j; }
            else t2 = fmaxf(t2, v);
        }
#pragma unroll
        for (int j = 0; j < 8; j++) {
            float v = -acc[j];
            if (v > t1) { t2 = t1; t1 = v; i1 = 32 + ig + j; }
            else t2 = fmaxf(t2, v);
        }
#pragma unroll
        for (int o = 1; o <= 2; o <<= 1) {
            float o1 = __shfl_xor_sync(0xffffffffu, t1, o);
            int   oi = __shfl_xor_sync(0xffffffffu, i1, o);
            float o2 = __shfl_xor_sync(0xffffffffu, t2, o);
            if (o1 > t1 || (o1 == t1 && oi < i1)) {
                t2 = fmaxf(t1, o2); t1 = o1; i1 = oi;
            } else {
                t2 = fmaxf(t2, o1);
            }
        }

        if ((tx & 3) == 0) {
            const int t = t0 + ty * 8 + i;
            g_buckets[(((size_t)n * Hh + h) * NHh + r) * Tt + t] = i1 + r * NBb;
            if (t1 - t2 < 1e-4f * t1 + 1e-4f) {
                int p = atomicAdd(&g_nflags, 1);
                if (p < MAXF)
                    g_flags[p] = (n << 17) | (h << 14) | (r << 12) | t;
            }
        }
    }
}

// ================= fix-up: exact recompute of flagged decisions =============
#define FCAP 6144
#define OF_LST 0
#define OF_XB  (FCAP * 4)
#define OF_QB  (FCAP * 4 + 8 * 4 * 512 * 4)
#define SMEM_FIX (FCAP * 4 + 8 * 4 * 512 * 4 + 8 * 4 * 64 * 4)

__global__ __launch_bounds__(256)
void fixup_kernel(const float* __restrict__ x, const float* __restrict__ WQ,
                  const float* __restrict__ bQ, const float* __restrict__ rot)
{
    extern __shared__ char fsm[];
    int*   lst = (int*)(fsm + OF_LST);
    float* xb  = (float*)(fsm + OF_XB);    // [8 warps][4 flags][512]
    float* qb  = (float*)(fsm + OF_QB);    // [8 warps][4 flags][64]
    __shared__ int lcnt;

    const int bin = blockIdx.x;            // n*8 + h
    const int slice = blockIdx.y;          // 0..7
    const int n = bin >> 3, h = bin & 7;
    const int tid = threadIdx.x;
    const int w = tid >> 5, lane = tid & 31;

    if (tid == 0) lcnt = 0;
    __syncthreads();

    int count = g_nflags;
    if (count > MAXF) count = MAXF;
    for (int e = tid; e < count; e += 256) {
        const int pk = g_flags[e];
        if (((pk >> 14) & 31) == bin && (e & 7) == slice) {
            int p = atomicAdd(&lcnt, 1);
            if (p < FCAP) lst[p] = pk;
        }
    }
    __syncthreads();
    int nf = lcnt;
    if (nf > FCAP) nf = FCAP;

    float* xw = xb + w * 4 * 512;
    float* qw = qb + w * 4 * 64;

    for (int s = w * 4; s < nf; s += 32) {
        const int nn = min(4, nf - s);
        for (int ff = 0; ff < nn; ff++) {
            const int t = lst[s + ff] & 4095;
            const float* xr = x + ((size_t)n * Tt + t) * Dd;
            for (int e4 = lane; e4 < 128; e4 += 32)
                *(float4*)&xw[ff * 512 + e4 * 4] = *(const float4*)&xr[e4 * 4];
        }
        __syncwarp();

        float acc[4][2];
#pragma unroll
        for (int ff = 0; ff < 4; ff++) { acc[ff][0] = 0.f; acc[ff][1] = 0.f; }
        const float* Wc = WQ + h * 64;
        for (int k = 0; k < Dd; k++) {
            const float w0 = Wc[(size_t)k * Dd + lane];
            const float w1 = Wc[(size_t)k * Dd + lane + 32];
#pragma unroll
            for (int ff = 0; ff < 4; ff++) {
                acc[ff][0] += xw[ff * 512 + k] * w0;
                acc[ff][1] += xw[ff * 512 + k] * w1;
            }
        }
        const float b0 = bQ[h * 64 + lane], b1 = bQ[h * 64 + lane + 32];
        for (int ff = 0; ff < nn; ff++) {
            qw[ff * 64 + lane]      = acc[ff][0] + b0;
            qw[ff * 64 + lane + 32] = acc[ff][1] + b1;
        }
        __syncwarp();

        for (int ff = 0; ff < nn; ff++) {
            const int pk = lst[s + ff];
            const int t = pk & 4095, r = (pk >> 12) & 3;
            const float* rp = rot + (size_t)h * 8192 + r * 32 + lane;
            float v = 0.f;
#pragma unroll 8
            for (int f = 0; f < 64; f++)
                v += qw[ff * 64 + f] * rp[f * 128];
            float bv; int bi;
            if (-v > v) { bv = -v; bi = 32 + lane; }
            else        { bv = v;  bi = lane; }
#pragma unroll
            for (int o = 16; o; o >>= 1) {
                float ov = __shfl_xor_sync(0xffffffffu, bv, o);
                int   oi = __shfl_xor_sync(0xffffffffu, bi, o);
                if (ov > bv || (ov == bv && oi < bi)) { bv = ov; bi = oi; }
            }
            if (lane == 0)
                g_buckets[(((size_t)n * Hh + h) * NHh + r) * Tt + t] = bi + r * NBb;
        }
        __syncwarp();
    }
}

// ================= segmented stable counting sort per (n,h) =================
#define HROW 258
#define SMEM_SORT (Ll + 256 * HROW * 2 + 256 * 4)
__global__ void sort_kernel()
{
    extern __shared__ char smraw[];
    unsigned char*  sb   = (unsigned char*)smraw;
    unsigned short* hist = (unsigned short*)(smraw + Ll);
    int*            base = (int*)(smraw + Ll + 256 * HROW * 2);
    __shared__ int tot[256];

    const int nh = blockIdx.x;
    const int tid = threadIdx.x;

    for (int e = tid; e < 256 * HROW / 2; e += 256)
        ((unsigned int*)hist)[e] = 0;
    __syncthreads();

    const int* bptr = g_buckets + (size_t)nh * Ll;
    for (int e = tid; e < Ll; e += 256)
        sb[e] = (unsigned char)bptr[e];
    __syncthreads();

    {
        const int s = tid;
#pragma unroll 4
        for (int j = 0; j < 64; j++) {
            int b = sb[s * 64 + j];
            hist[b * HROW + s]++;
        }
    }
    __syncthreads();

    {
        const unsigned short* row = &hist[tid * HROW];
        int sum = 0;
#pragma unroll 8
        for (int s2 = 0; s2 < 256; s2++) sum += row[s2];
        tot[tid] = sum;
    }
    __syncthreads();
    if (tid == 0) {
        int run = 0;
        for (int b = 0; b < 256; b++) { base[b] = run; run += tot[b]; }
    }
    __syncthreads();

    {
        unsigned short* row = &hist[tid * HROW];
        unsigned short run = 0;
        for (int s2 = 0; s2 < 256; s2++) {
            unsigned short v = row[s2];
            row[s2] = run;
            run = (unsigned short)(run + v);
        }
    }
    __syncthreads();

    {
        const int s = tid;
        int* pout = g_perm + (size_t)nh * Ll;
        for (int j = 0; j < 64; j++) {
            int i = s * 64 + j;
            int b = sb[i];
            unsigned short off = hist[b * HROW + s];
            hist[b * HROW + s] = (unsigned short)(off + 1);
            pout[base[b] + off] = (b << 16) | i;
        }
    }
}

// ================= chunked attention (raw-q dots, column norm scale) ========
#define KHP 72
#define VP  72
#define OKH_HI 0
#define OKH_LO 18432
#define OV_HI  36864
#define OV_LO  55296
#define OMETA  73728
#define ORNORM 74240
#define OINVS  74752
#define SMEM_ATT3 75008

__global__ __launch_bounds__(128, 3)
void attention_kernel()
{
    extern __shared__ char smb[];
    __nv_bfloat16* kh_hi = (__nv_bfloat16*)(smb + OKH_HI);   // [128][72] raw q
    __nv_bfloat16* kh_lo = (__nv_bfloat16*)(smb + OKH_LO);
    __nv_bfloat16* v_hi  = (__nv_bfloat16*)(smb + OV_HI);    // [128][72]
    __nv_bfloat16* v_lo  = (__nv_bfloat16*)(smb + OV_LO);
    int*   pmeta = (int*)(smb + OMETA);                      // 128
    float* rnorm = (float*)(smb + ORNORM);                   // 128 (1/(||q||+eps))
    float* invs  = (float*)(smb + OINVS);                    // 64

    const int c = blockIdx.x, h = blockIdx.y, n = blockIdx.z;
    const int tid = threadIdx.x;
    const int pc = (c + CSs - 1) % CSs;

    {
        const int p = (tid < 64) ? (c * BSs + tid) : (pc * BSs + (tid - 64));
        pmeta[tid] = g_perm[((size_t)n * Hh + h) * Ll + p];
    }
    __syncthreads();

    const float* Qb = g_Q + (size_t)n * Tt * Dd + h * DHh;
    const float* Vb = g_V + (size_t)n * Tt * Dd + h * DHh;
    const int sub = tid >> 4, c4 = tid & 15;
#pragma unroll
    for (int i = 0; i < 16; i++) {
        const int row = i * 8 + sub;
        const int t = pmeta[row] & 4095;
        float4 qv = *(const float4*)&Qb[(size_t)t * Dd + c4 * 4];
        __nv_bfloat162 kh01 = __floats2bfloat162_rn(qv.x, qv.y);
        __nv_bfloat162 kl01 = __floats2bfloat162_rn(qv.x - __low2float(kh01), qv.y - __high2float(kh01));
        __nv_bfloat162 kh23 = __floats2bfloat162_rn(qv.z, qv.w);
        __nv_bfloat162 kl23 = __floats2bfloat162_rn(qv.z - __low2float(kh23), qv.w - __high2float(kh23));
        *(__nv_bfloat162*)&kh_hi[row * KHP + c4 * 4]     = kh01;
        *(__nv_bfloat162*)&kh_hi[row * KHP + c4 * 4 + 2] = kh23;
        *(__nv_bfloat162*)&kh_lo[row * KHP + c4 * 4]     = kl01;
        *(__nv_bfloat162*)&kh_lo[row * KHP + c4 * 4 + 2] = kl23;

        float4 vv = *(const float4*)&Vb[(size_t)t * Dd + c4 * 4];
        __nv_bfloat162 vh01 = __floats2bfloat162_rn(vv.x, vv.y);
        __nv_bfloat162 vl01 = __floats2bfloat162_rn(vv.x - __low2float(vh01), vv.y - __high2float(vh01));
        __nv_bfloat162 vh23 = __floats2bfloat162_rn(vv.z, vv.w);
        __nv_bfloat162 vl23 = __floats2bfloat162_rn(vv.z - __low2float(vh23), vv.w - __high2float(vh23));
        *(__nv_bfloat162*)&v_hi[row * VP + c4 * 4]     = vh01;
        *(__nv_bfloat162*)&v_hi[row * VP + c4 * 4 + 2] = vh23;
        *(__nv_bfloat162*)&v_lo[row * VP + c4 * 4]     = vl01;
        *(__nv_bfloat162*)&v_lo[row * VP + c4 * 4 + 2] = vl23;

        float ss = qv.x * qv.x + qv.y * qv.y + qv.z * qv.z + qv.w * qv.w;
        ss += __shfl_xor_sync(0xffffffffu, ss, 1);
        ss += __shfl_xor_sync(0xffffffffu, ss, 2);
        ss += __shfl_xor_sync(0xffffffffu, ss, 4);
        ss += __shfl_xor_sync(0xffffffffu, ss, 8);
        if (c4 == 0) rnorm[row] = 1.f / (sqrtf(ss) + 1e-6f);
    }
    __syncthreads();

    const int w = tid >> 5, lane = tid & 31;
    const int g = lane >> 2, tg = lane & 3;
    const int i0 = w * 16;

    const uint32_t khb_hi = smem_u32(kh_hi), khb_lo = smem_u32(kh_lo);
    const uint32_t vb_hi  = smem_u32(v_hi),  vb_lo  = smem_u32(v_lo);
    const uint32_t aoff = ((i0 + (lane & 15)) * KHP + 8 * (lane >> 4)) * 2;
    const uint32_t boff = (((lane & 7) + ((lane >= 16) ? 8 : 0)) * KHP + ((lane >> 3) & 1) * 8) * 2;
    const uint32_t voff = (((lane & 7) + 8 * ((lane >> 3) & 1)) * VP + 8 * (lane >> 4)) * 2;

    // ---- dots: D_ij = q_i . q_j (raw) ----
    float dc[16][4];
#pragma unroll
    for (int nt = 0; nt < 16; nt++)
#pragma unroll
        for (int k = 0; k < 4; k++) dc[nt][k] = 0.f;

#pragma unroll
    for (int k0 = 0; k0 < 64; k0 += 16) {
        uint32_t ah[4], al[4];
        LDSM4(ah[0], ah[1], ah[2], ah[3], khb_hi + aoff + k0 * 2);
        LDSM4(al[0], al[1], al[2], al[3], khb_lo + aoff + k0 * 2);
#pragma unroll
        for (int jt = 0; jt < 8; jt++) {
            uint32_t bh[4], bl[4];
            const uint32_t jb = (uint32_t)(jt * 16 * KHP + k0) * 2;
            LDSM4(bh[0], bh[1], bh[2], bh[3], khb_hi + boff + jb);
            LDSM4(bl[0], bl[1], bl[2], bl[3], khb_lo + boff + jb);
            MMA_BF16(dc[2 * jt], ah, bh);
            MMA_BF16(dc[2 * jt], ah, bl);
            MMA_BF16(dc[2 * jt], al, bh);
            MMA_BF16(dc[2 * jt + 1], ah, bh + 2);
            MMA_BF16(dc[2 * jt + 1], ah, bl + 2);
            MMA_BF16(dc[2 * jt + 1], al, bh + 2);
        }
    }

    // ---- masks + softmax; S_ij = D_ij * 0.125 * rnorm_j (column scale) ----
    const int ra = i0 + g, rb = i0 + g + 8;
    {
        const int pka = pmeta[ra], pkb = pmeta[rb];

#pragma unroll
        for (int nt = 0; nt < 16; nt++) {
            const int j0 = nt * 8 + 2 * tg;
            const int pj0 = pmeta[j0], pj1 = pmeta[j0 + 1];
            const float s0 = 0.125f * rnorm[j0];
            const float s1 = 0.125f * rnorm[j0 + 1];
            float x;
            x = dc[nt][0] * s0;
            if ((pka >> 16) != (pj0 >> 16)) x = -1e9f;
            if (((pka ^ pj0) & 4095) == 0)  x = -1e-5f;
            dc[nt][0] = x;
            x = dc[nt][1] * s1;
            if ((pka >> 16) != (pj1 >> 16)) x = -1e9f;
            if (((pka ^ pj1) & 4095) == 0)  x = -1e-5f;
            dc[nt][1] = x;
            x = dc[nt][2] * s0;
            if ((pkb >> 16) != (pj0 >> 16)) x = -1e9f;
            if (((pkb ^ pj0) & 4095) == 0)  x = -1e-5f;
            dc[nt][2] = x;
            x = dc[nt][3] * s1;
            if ((pkb >> 16) != (pj1 >> 16)) x = -1e9f;
            if (((pkb ^ pj1) & 4095) == 0)  x = -1e-5f;
            dc[nt][3] = x;
        }

        float ma = -1e30f, mb = -1e30f;
#pragma unroll
        for (int nt = 0; nt < 16; nt++) {
            ma = fmaxf(ma, fmaxf(dc[nt][0], dc[nt][1]));
            mb = fmaxf(mb, fmaxf(dc[nt][2], dc[nt][3]));
        }
        ma = fmaxf(ma, __shfl_xor_sync(0xffffffffu, ma, 1));
        ma = fmaxf(ma, __shfl_xor_sync(0xffffffffu, ma, 2));
        mb = fmaxf(mb, __shfl_xor_sync(0xffffffffu, mb, 1));
        mb = fmaxf(mb, __shfl_xor_sync(0xffffffffu, mb, 2));

        float sa = 0.f, sb2 = 0.f;
#pragma unroll
        for (int nt = 0; nt < 16; nt++) {
            dc[nt][0] = __expf(dc[nt][0] - ma); sa  += dc[nt][0];
            dc[nt][1] = __expf(dc[nt][1] - ma); sa  += dc[nt][1];
            dc[nt][2] = __expf(dc[nt][2] - mb); sb2 += dc[nt][2];
            dc[nt][3] = __expf(dc[nt][3] - mb); sb2 += dc[nt][3];
        }
        sa  += __shfl_xor_sync(0xffffffffu, sa, 1);
        sa  += __shfl_xor_sync(0xffffffffu, sa, 2);
        sb2 += __shfl_xor_sync(0xffffffffu, sb2, 1);
        sb2 += __shfl_xor_sync(0xffffffffu, sb2, 2);

        if (tg == 0) {
            const int nhbase = ((int)n * Hh + h) * NHh;
            const int ta = pka & 4095, rra = (pka >> 12) & 3;
            const int tb = pkb & 4095, rrb = (pkb >> 12) & 3;
            g_logits[((size_t)nhbase + rra) * Tt + ta] = ma + __logf(sa);
            g_logits[((size_t)nhbase + rrb) * Tt + tb] = mb + __logf(sb2);
            invs[ra] = 1.f / sa;
            invs[rb] = 1.f / sb2;
        }
        __syncwarp();
    }

    // ---- PV: O = P @ V, P fed straight from registers ----
    float oc[8][4];
#pragma unroll
    for (int nt = 0; nt < 8; nt++)
#pragma unroll
        for (int k = 0; k < 4; k++) oc[nt][k] = 0.f;

#pragma unroll
    for (int kc = 0; kc < 8; kc++) {
        uint32_t phi[4], plo[4];
        {
            __nv_bfloat162 hp, lp;
            hp = __floats2bfloat162_rn(dc[2 * kc][0], dc[2 * kc][1]);
            lp = __floats2bfloat162_rn(dc[2 * kc][0] - __low2float(hp),
                                       dc[2 * kc][1] - __high2float(hp));
            phi[0] = *(uint32_t*)&hp; plo[0] = *(uint32_t*)&lp;
            hp = __floats2bfloat162_rn(dc[2 * kc][2], dc[2 * kc][3]);
            lp = __floats2bfloat162_rn(dc[2 * kc][2] - __low2float(hp),
                                       dc[2 * kc][3] - __high2float(hp));
            phi[1] = *(uint32_t*)&hp; plo[1] = *(uint32_t*)&lp;
            hp = __floats2bfloat162_rn(dc[2 * kc + 1][0], dc[2 * kc + 1][1]);
            lp = __floats2bfloat162_rn(dc[2 * kc + 1][0] - __low2float(hp),
                                       dc[2 * kc + 1][1] - __high2float(hp));
            phi[2] = *(uint32_t*)&hp; plo[2] = *(uint32_t*)&lp;
            hp = __floats2bfloat162_rn(dc[2 * kc + 1][2], dc[2 * kc + 1][3]);
            lp = __floats2bfloat162_rn(dc[2 * kc + 1][2] - __low2float(hp),
                                       dc[2 * kc + 1][3] - __high2float(hp));
            phi[3] = *(uint32_t*)&hp; plo[3] = *(uint32_t*)&lp;
        }
#pragma unroll
        for (int ft = 0; ft < 4; ft++) {
            uint32_t vh[4], vl[4];
            const uint32_t vbo = (uint32_t)(kc * 16 * VP + ft * 16) * 2;
            LDSM4T(vh[0], vh[1], vh[2], vh[3], vb_hi + voff + vbo);
            LDSM4T(vl[0], vl[1], vl[2], vl[3], vb_lo + voff + vbo);
            MMA_BF16(oc[2 * ft], phi, vh);
            MMA_BF16(oc[2 * ft], phi, vl);
            MMA_BF16(oc[2 * ft], plo, vh);
            MMA_BF16(oc[2 * ft + 1], phi, vh + 2);
            MMA_BF16(oc[2 * ft + 1], phi, vl + 2);
            MMA_BF16(oc[2 * ft + 1], plo, vh + 2);
        }
    }

    {
        const int pka = pmeta[ra], pkb = pmeta[rb];
        const float iva = invs[ra], ivb = invs[rb];
        const size_t obase = ((size_t)n * Hh + h) * NHh;
        const size_t oa = ((obase + ((pka >> 12) & 3)) * Tt + (pka & 4095)) * DHh;
        const size_t ob = ((obase + ((pkb >> 12) & 3)) * Tt + (pkb & 4095)) * DHh;
#pragma unroll
        for (int ft = 0; ft < 4; ft++) {
            const int f0 = ft * 16 + 2 * tg;
            *(float2*)&g_O[oa + f0]     = make_float2(oc[2 * ft][0] * iva, oc[2 * ft][1] * iva);
            *(float2*)&g_O[ob + f0]     = make_float2(oc[2 * ft][2] * ivb, oc[2 * ft][3] * ivb);
            *(float2*)&g_O[oa + f0 + 8] = make_float2(oc[2 * ft + 1][0] * iva, oc[2 * ft + 1][1] * iva);
            *(float2*)&g_O[ob + f0 + 8] = make_float2(oc[2 * ft + 1][2] * ivb, oc[2 * ft + 1][3] * ivb);
        }
    }
}

// ================= round-combine softmax + LayerNorm (shfl reduce) ==========
__global__ void combine_ln_kernel(const float* __restrict__ gamma,
                                  const float* __restrict__ beta,
                                  float* __restrict__ out)
{
    const int bid = blockIdx.x;            // n*T + t
    const int n = bid >> 12, t = bid & 4095;
    const int tid = threadIdx.x;           // 128
    const int w = tid >> 5, lane = tid & 31;
    __shared__ float wsh[Hh][NHh];
    __shared__ float rs[4], rq[4];

    if (tid < Hh) {
        const int h = tid;
        float l[NHh];
        float m = -1e30f;
#pragma unroll
        for (int r = 0; r < NHh; r++) {
            l[r] = g_logits[(((size_t)n * Hh + h) * NHh + r) * Tt + t];
            m = fmaxf(m, l[r]);
        }
        float s = 0.f;
#pragma unroll
        for (int r = 0; r < NHh; r++) s += __expf(l[r] - m);
        const float lse = m + __logf(s);
#pragma unroll
        for (int r = 0; r < NHh; r++) wsh[h][r] = __expf(l[r] - lse);
    }
    __syncthreads();

    float vals[4];
    float lsum = 0.f, lsq = 0.f;
#pragma unroll
    for (int k2 = 0; k2 < 4; k2++) {
        const int d = tid + k2 * 128;
        const int h = d >> 6, f = d & 63;
        float a = 0.f;
#pragma unroll
        for (int r = 0; r < NHh; r++)
            a += wsh[h][r] * g_O[((((size_t)n * Hh + h) * NHh + r) * Tt + t) * DHh + f];
        vals[k2] = a;
        lsum += a;
        lsq  += a * a;
    }

#pragma unroll
    for (int o = 16; o; o >>= 1) {
        lsum += __shfl_xor_sync(0xffffffffu, lsum, o);
        lsq  += __shfl_xor_sync(0xffffffffu, lsq, o);
    }
    if (lane == 0) { rs[w] = lsum; rq[w] = lsq; }
    __syncthreads();
    const float ts = rs[0] + rs[1] + rs[2] + rs[3];
    const float tq = rq[0] + rq[1] + rq[2] + rq[3];
    const float mu = ts * (1.f / Dd);
    const float var = tq * (1.f / Dd) - mu * mu;
    const float rstd = rsqrtf(var + 1e-3f);

#pragma unroll
    for (int k2 = 0; k2 < 4; k2++) {
        const int d = tid + k2 * 128;
        out[(size_t)bid * Dd + d] = gamma[d] * (vals[k2] - mu) * rstd + beta[d];
    }
}

// ================= launch ===================================================
extern "C" void kernel_launch(void* const* d_in, const int* in_sizes, int n_in,
                              void* d_out, int out_size)
{
    const float* x     = (const float*)d_in[0];
    const float* W_Q   = (const float*)d_in[1];
    const float* b_Q   = (const float*)d_in[2];
    const float* W_V   = (const float*)d_in[3];
    const float* b_V   = (const float*)d_in[4];
    const float* gamma = (const float*)d_in[5];
    const float* beta  = (const float*)d_in[6];
    const float* rot   = (const float*)d_in[7];
    float* out = (float*)d_out;

    cudaFuncSetAttribute(attention_kernel,
                         cudaFuncAttributeMaxDynamicSharedMemorySize, SMEM_ATT3);
    cudaFuncSetAttribute(sort_kernel,
                         cudaFuncAttributeMaxDynamicSharedMemorySize, SMEM_SORT);
    cudaFuncSetAttribute(gemm_qv_kernel,
                         cudaFuncAttributeMaxDynamicSharedMemorySize, SMEM_MMA);
    cudaFuncSetAttribute(bucket_kernel,
                         cudaFuncAttributeMaxDynamicSharedMemorySize, SMEM_BKT);
    cudaFuncSetAttribute(fixup_kernel,
                         cudaFuncAttributeMaxDynamicSharedMemorySize, SMEM_FIX);

    reset_kernel<<<1, 1>>>();

    split_w_kernel<<<dim3(16, 16, 2), dim3(32, 8)>>>(W_Q, W_V);

    dim3 gGrid(2, (Nb * Tt) / 128, 2);          // (2, 128, 2) -> Q and V
    gemm_qv_kernel<<<gGrid, 512, SMEM_MMA>>>(x, b_Q, b_V);

    dim3 bGrid(Tt / 128, Hh, Nb);               // (32, 8, 4)
    bucket_kernel<<<bGrid, 256, SMEM_BKT>>>(rot);

    fixup_kernel<<<dim3(32, 8), 256, SMEM_FIX>>>(x, W_Q, b_Q, rot);

    sort_kernel<<<Nb * Hh, 256, SMEM_SORT>>>(); // 32 blocks

    dim3 aGrid(CSs, Hh, Nb);                    // (256, 8, 4)
    attention_kernel<<<aGrid, 128, SMEM_ATT3>>>();

    combine_ln_kernel<<<Nb * Tt, 128>>>(gamma, beta, out);
}

// round 14
// speedup vs baseline: 1.2191x; 1.0039x over previous
#include <cuda_runtime.h>
#include <cuda_bf16.h>
#include <math.h>
#include <stdint.h>

// Problem constants
#define Nb   4          // batch
#define Tt   4096       // sequence length
#define Dd   512        // model dim
#define Hh   8          // heads
#define NHh  4          // hash rounds
#define BSs  64         // bucket chunk size
#define DHh  64         // head dim
#define NBb  64         // n_buckets
#define CSs  256        // chunks = NH * NB
#define Ll   16384      // NH * T

typedef unsigned long long u64;

// ---------------- scratch (device globals; no allocation allowed) ----------
__device__ float g_Q[(size_t)Nb * Tt * Dd];                 // 33.5 MB
__device__ float g_V[(size_t)Nb * Tt * Dd];                 // 33.5 MB
__device__ int   g_buckets[(size_t)Nb * Hh * NHh * Tt];     // 2 MB
__device__ int   g_perm[(size_t)Nb * Hh * Ll];              // 2 MB
__device__ float g_O[(size_t)Nb * Hh * NHh * Tt * DHh];     // 134 MB
__device__ float g_logits[(size_t)Nb * Hh * NHh * Tt];      // 2 MB
__device__ __nv_bfloat16 g_wthi[2][Dd * Dd];                // 1 MB (W^T hi: 0=Q,1=V)
__device__ __nv_bfloat16 g_wtlo[2][Dd * Dd];                // 1 MB
__device__ __nv_bfloat16 g_xhi[(size_t)Nb * Tt * Dd];       // 16 MB
__device__ __nv_bfloat16 g_xlo[(size_t)Nb * Tt * Dd];       // 16 MB
#define MAXF 131072
__device__ int g_nflags;
__device__ int g_flags[MAXF];                               // packed (n<<17)|(h<<14)|(r<<12)|t

// ================= helpers ==================================================
__device__ __forceinline__ uint32_t smem_u32(const void* p) {
    uint32_t a;
    asm("{ .reg .u64 t; cvta.to.shared.u64 t, %1; cvt.u32.u64 %0, t; }" : "=r"(a) : "l"(p));
    return a;
}
#define MMA_BF16(d, a, b)                                                     \
    asm volatile("mma.sync.aligned.m16n8k16.row.col.f32.bf16.bf16.f32 "       \
        "{%0,%1,%2,%3}, {%4,%5,%6,%7}, {%8,%9}, {%0,%1,%2,%3};"               \
        : "+f"((d)[0]), "+f"((d)[1]), "+f"((d)[2]), "+f"((d)[3])              \
        : "r"((a)[0]), "r"((a)[1]), "r"((a)[2]), "r"((a)[3]),                 \
          "r"((b)[0]), "r"((b)[1]))
#define LDSM4(r0, r1, r2, r3, addr)                                           \
    asm volatile("ldmatrix.sync.aligned.m8n8.x4.shared.b16 {%0,%1,%2,%3}, [%4];" \
        : "=r"(r0), "=r"(r1), "=r"(r2), "=r"(r3) : "r"(addr))
#define LDSM4T(r0, r1, r2, r3, addr)                                          \
    asm volatile("ldmatrix.sync.aligned.m8n8.x4.trans.shared.b16 {%0,%1,%2,%3}, [%4];" \
        : "=r"(r0), "=r"(r1), "=r"(r2), "=r"(r3) : "r"(addr))
#define FFMA2(d, a, b) \
    asm("fma.rn.f32x2 %0, %1, %2, %0;" : "+l"(d) : "l"(a), "l"(b))
#define PACK2(d, x, y) \
    asm("mov.b64 %0, {%1, %2};" : "=l"(d) : "f"(x), "f"(y))
#define UNPACK2(x, y, d) \
    asm("mov.b64 {%0, %1}, %2;" : "=f"(x), "=f"(y) : "l"(d))

// ================= reset ====================================================
__global__ void reset_kernel() { g_nflags = 0; }

// ================= split x -> bf16 hi/lo ====================================
__global__ void split_x_kernel(const float* __restrict__ x)
{
    const size_t i = (size_t)blockIdx.x * 256 + threadIdx.x;   // per float4
    float4 v = ((const float4*)x)[i];
    __nv_bfloat162 h01 = __floats2bfloat162_rn(v.x, v.y);
    __nv_bfloat162 h23 = __floats2bfloat162_rn(v.z, v.w);
    __nv_bfloat162 l01 = __floats2bfloat162_rn(v.x - __low2float(h01), v.y - __high2float(h01));
    __nv_bfloat162 l23 = __floats2bfloat162_rn(v.z - __low2float(h23), v.w - __high2float(h23));
    ((__nv_bfloat162*)g_xhi)[i * 2]     = h01;
    ((__nv_bfloat162*)g_xhi)[i * 2 + 1] = h23;
    ((__nv_bfloat162*)g_xlo)[i * 2]     = l01;
    ((__nv_bfloat162*)g_xlo)[i * 2 + 1] = l23;
}

// ================= split + transpose W_Q / W_V ==============================
__global__ void split_w_kernel(const float* __restrict__ WQ, const float* __restrict__ WV)
{
    __shared__ float tile[32][33];
    const float* W = blockIdx.z ? WV : WQ;
    const int bx = blockIdx.x * 32;   // n block
    const int by = blockIdx.y * 32;   // k block
    const int tx = threadIdx.x, ty = threadIdx.y;   // 32 x 8
#pragma unroll
    for (int r = 0; r < 32; r += 8)
        tile[ty + r][tx] = W[(size_t)(by + ty + r) * Dd + bx + tx];
    __syncthreads();
#pragma unroll
    for (int r = 0; r < 32; r += 8) {
        float val = tile[tx][ty + r];
        __nv_bfloat16 hi = __float2bfloat16(val);
        __nv_bfloat16 lo = __float2bfloat16(val - __bfloat162float(hi));
        size_t o = (size_t)(bx + ty + r) * Dd + by + tx;
        g_wthi[blockIdx.z][o] = hi;
        g_wtlo[blockIdx.z][o] = lo;
    }
}

// ================= Q/V GEMM: bf16 mma + ldmatrix + reg-prefetch pipeline ====
#define PITCH 40
#define A_HI  0
#define A_LO  (128 * PITCH)
#define B_HI  (2 * 128 * PITCH)
#define B_LO  (2 * 128 * PITCH + 256 * PITCH)
#define SMEM_MMA ((2 * 128 * PITCH + 2 * 256 * PITCH) * 2)
#define ALO_B  (128 * PITCH * 2)
#define BHI_B  (2 * 128 * PITCH * 2)
#define BLO_D  (256 * PITCH * 2)

__global__ __launch_bounds__(512, 1)
void gemm_qv_kernel(const float* __restrict__ bQ, const float* __restrict__ bV)
{
    extern __shared__ uint16_t sm16[];
    const int tid = threadIdx.x;
    const int wid = tid >> 5, lane = tid & 31;
    const int g = lane >> 2, tg = lane & 3;
    const int wm = wid & 3, wn = wid >> 2;
    const int mbase = blockIdx.y * 128;
    const int ncol0 = blockIdx.x * 256;
    const int which = blockIdx.z;                 // 0 = Q, 1 = V
    const __nv_bfloat16* Whi = g_wthi[which];
    const __nv_bfloat16* Wlo = g_wtlo[which];
    const float* bias = which ? bV : bQ;
    float* C = which ? g_V : g_Q;

    const uint32_t smbase = smem_u32(sm16);
    const uint32_t aoff0 = ((wm * 32 + (lane & 15)) * PITCH + 8 * (lane >> 4)) * 2;
    const uint32_t boff0 = (((lane & 7) + ((lane >= 16) ? 8 : 0)) * PITCH
                            + ((lane >> 3) & 1) * 8) * 2;

    // precomputed staging indices (per thread)
    int ar[2], ak8[2]; const __nv_bfloat16* asrc[2]; uint32_t adst[2];
#pragma unroll
    for (int i = 0; i < 2; i++) {
        const int e = tid + i * 512;              // [0,1024)
        const int split = e >> 9;
        ar[i] = (e >> 2) & 127;
        ak8[i] = e & 3;
        asrc[i] = (split ? g_xlo : g_xhi) + (size_t)(mbase + ar[i]) * Dd + ak8[i] * 8;
        adst[i] = (split ? A_LO : A_HI) + ar[i] * PITCH + ak8[i] * 8;
    }
    const __nv_bfloat16* bsrc[4]; uint32_t bdst[4];
#pragma unroll
    for (int i = 0; i < 4; i++) {
        const int e = tid + i * 512;              // [0,2048)
        const int split = e >> 10;
        const int r = (e >> 2) & 255;
        const int k8 = e & 3;
        bsrc[i] = (split ? Wlo : Whi) + (size_t)(ncol0 + r) * Dd + k8 * 8;
        bdst[i] = (split ? B_LO : B_HI) + r * PITCH + k8 * 8;
    }

    float acc[2][8][4];
#pragma unroll
    for (int i = 0; i < 2; i++)
#pragma unroll
        for (int j = 0; j < 8; j++)
#pragma unroll
            for (int k = 0; k < 4; k++) acc[i][j][k] = 0.f;

    uint4 pa[2], pb[4];
    // prologue: load + store slab 0
#pragma unroll
    for (int i = 0; i < 2; i++) pa[i] = *(const uint4*)(asrc[i]);
#pragma unroll
    for (int i = 0; i < 4; i++) pb[i] = *(const uint4*)(bsrc[i]);
#pragma unroll
    for (int i = 0; i < 2; i++) *(uint4*)(sm16 + adst[i]) = pa[i];
#pragma unroll
    for (int i = 0; i < 4; i++) *(uint4*)(sm16 + bdst[i]) = pb[i];
    __syncthreads();

    for (int slab = 0; slab < 16; slab++) {
        // prefetch next slab into registers (hidden behind MMA work)
        if (slab < 15) {
            const int kt = (slab + 1) * 32;
#pragma unroll
            for (int i = 0; i < 2; i++) pa[i] = *(const uint4*)(asrc[i] + kt);
#pragma unroll
            for (int i = 0; i < 4; i++) pb[i] = *(const uint4*)(bsrc[i] + kt);
        }

#pragma unroll
        for (int kk = 0; kk < 32; kk += 16) {
            uint32_t ah[2][4], al[2][4];
#pragma unroll
            for (int mt = 0; mt < 2; mt++) {
                const uint32_t aa = smbase + aoff0
                    + (uint32_t)(mt * 16 * PITCH + kk) * 2;
                LDSM4(ah[mt][0], ah[mt][1], ah[mt][2], ah[mt][3], aa);
                LDSM4(al[mt][0], al[mt][1], al[mt][2], al[mt][3], aa + ALO_B);
            }
#pragma unroll
            for (int ng = 0; ng < 2; ng++) {
                uint32_t bh[2][4], bl[2][4];
#pragma unroll
                for (int hh = 0; hh < 2; hh++) {
                    const uint32_t bb = smbase + BHI_B + boff0
                        + (uint32_t)((wn * 64 + ng * 32 + hh * 16) * PITCH + kk) * 2;
                    LDSM4(bh[hh][0], bh[hh][1], bh[hh][2], bh[hh][3], bb);
                    LDSM4(bl[hh][0], bl[hh][1], bl[hh][2], bl[hh][3], bb + BLO_D);
                }
#pragma unroll
                for (int mt = 0; mt < 2; mt++)
#pragma unroll
                    for (int q = 0; q < 4; q++) {
                        float* d = acc[mt][ng * 4 + q];
                        uint32_t* bhp = bh[q >> 1] + (q & 1) * 2;
                        uint32_t* blp = bl[q >> 1] + (q & 1) * 2;
                        MMA_BF16(d, ah[mt], bhp);
                        MMA_BF16(d, ah[mt], blp);
                        MMA_BF16(d, al[mt], bhp);
                    }
            }
        }
        __syncthreads();
        if (slab < 15) {
#pragma unroll
            for (int i = 0; i < 2; i++) *(uint4*)(sm16 + adst[i]) = pa[i];
#pragma unroll
            for (int i = 0; i < 4; i++) *(uint4*)(sm16 + bdst[i]) = pb[i];
            __syncthreads();
        }
    }

#pragma unroll
    for (int mt = 0; mt < 2; mt++) {
        const int r0 = mbase + wm * 32 + mt * 16 + g;
#pragma unroll
        for (int nt = 0; nt < 8; nt++) {
            const int col = ncol0 + wn * 64 + nt * 8 + 2 * tg;
            float2 b2 = *(const float2*)&bias[col];
            float2 o0, o1;
            o0.x = acc[mt][nt][0] + b2.x;
            o0.y = acc[mt][nt][1] + b2.y;
            o1.x = acc[mt][nt][2] + b2.x;
            o1.y = acc[mt][nt][3] + b2.y;
            *(float2*)&C[(size_t)r0 * Dd + col] = o0;
            *(float2*)&C[(size_t)(r0 + 8) * Dd + col] = o1;
        }
    }
}

// ================= bucket kernel: GEMM (FFMA2) + argmax + margin flag =======
#define AsP 68
#define BsP 132
#define SMEM_BKT ((128 * AsP + 64 * BsP) * 4)

__global__ __launch_bounds__(256, 2)
void bucket_kernel(const float* __restrict__ rot)
{
    extern __shared__ float smf[];
    float* As = smf;                  // [128 m][68 k]
    float* Bs = smf + 128 * AsP;      // [64 k][132 c]

    const int h = blockIdx.y, n = blockIdx.z;
    const int tid = threadIdx.x;      // 256
    const int tx = tid & 15, ty = tid >> 4;
    const int t0 = blockIdx.x * 128;

    const float* Qb = g_Q + ((size_t)n * Tt + t0) * Dd + h * DHh;
#pragma unroll
    for (int l = 0; l < 8; l++) {
        const int e = tid + l * 256;
        const int r = e >> 4, c4 = e & 15;
        *(float4*)&As[r * AsP + c4 * 4] = *(const float4*)&Qb[(size_t)r * Dd + c4 * 4];
    }
    const float* Rb = rot + (size_t)h * 8192;
#pragma unroll
    for (int l = 0; l < 8; l++) {
        const int e = tid + l * 256;
        const int kr = e >> 5, c4 = e & 31;
        *(float4*)&Bs[kr * BsP + c4 * 4] = *(const float4*)&Rb[kr * 128 + c4 * 4];
    }
    __syncthreads();

    u64 acc2[8][4];
#pragma unroll
    for (int i = 0; i < 8; i++)
#pragma unroll
        for (int j = 0; j < 4; j++) acc2[i][j] = 0ull;

#pragma unroll 4
    for (int k = 0; k < 64; k++) {
        float a[8];
#pragma unroll
        for (int i = 0; i < 8; i++) a[i] = As[(ty * 8 + i) * AsP + k];
        u64 a2[8];
#pragma unroll
        for (int i = 0; i < 8; i++) PACK2(a2[i], a[i], a[i]);
        ulonglong2 bp0 = *(const ulonglong2*)&Bs[k * BsP + tx * 8];
        ulonglong2 bp1 = *(const ulonglong2*)&Bs[k * BsP + tx * 8 + 4];
        u64 b2[4] = {bp0.x, bp0.y, bp1.x, bp1.y};
#pragma unroll
        for (int i = 0; i < 8; i++)
#pragma unroll
            for (int j = 0; j < 4; j++) FFMA2(acc2[i][j], a2[i], b2[j]);
    }

    const int ig = (tx & 3) * 8;
    const int r = tx >> 2;
#pragma unroll
    for (int i = 0; i < 8; i++) {
        float acc[8];
#pragma unroll
        for (int jp = 0; jp < 4; jp++)
            UNPACK2(acc[2 * jp], acc[2 * jp + 1], acc2[i][jp]);

        float t1 = acc[0]; int i1 = ig; float t2 = -3.4e38f;
#pragma unroll
        for (int j = 1; j < 8; j++) {
            float v = acc[j];
            if (v > t1) { t2 = t1; t1 = v; i1 = ig + j; }
            else t2 = fmaxf(t2, v);
        }
#pragma unroll
        for (int j = 0; j < 8; j++) {
            float v = -acc[j];
            if (v > t1) { t2 = t1; t1 = v; i1 = 32 + ig + j; }
            else t2 = fmaxf(t2, v);
        }
#pragma unroll
        for (int o = 1; o <= 2; o <<= 1) {
            float o1 = __shfl_xor_sync(0xffffffffu, t1, o);
            int   oi = __shfl_xor_sync(0xffffffffu, i1, o);
            float o2 = __shfl_xor_sync(0xffffffffu, t2, o);
            if (o1 > t1 || (o1 == t1 && oi < i1)) {
                t2 = fmaxf(t1, o2); t1 = o1; i1 = oi;
            } else {
                t2 = fmaxf(t2, o1);
            }
        }

        if ((tx & 3) == 0) {
            const int t = t0 + ty * 8 + i;
            g_buckets[(((size_t)n * Hh + h) * NHh + r) * Tt + t] = i1 + r * NBb;
            if (t1 - t2 < 1e-4f * t1 + 1e-4f) {
                int p = atomicAdd(&g_nflags, 1);
                if (p < MAXF)
                    g_flags[p] = (n << 17) | (h << 14) | (r << 12) | t;
            }
        }
    }
}

// ================= fix-up: exact recompute of flagged decisions =============
#define FCAP 6144
#define OF_LST 0
#define OF_XB  (FCAP * 4)
#define OF_QB  (FCAP * 4 + 8 * 4 * 512 * 4)
#define SMEM_FIX (FCAP * 4 + 8 * 4 * 512 * 4 + 8 * 4 * 64 * 4)

__global__ __launch_bounds__(256)
void fixup_kernel(const float* __restrict__ x, const float* __restrict__ WQ,
                  const float* __restrict__ bQ, const float* __restrict__ rot)
{
    extern __shared__ char fsm[];
    int*   lst = (int*)(fsm + OF_LST);
    float* xb  = (float*)(fsm + OF_XB);    // [8 warps][4 flags][512]
    float* qb  = (float*)(fsm + OF_QB);    // [8 warps][4 flags][64]
    __shared__ int lcnt;

    const int bin = blockIdx.x;            // n*8 + h
    const int slice = blockIdx.y;          // 0..7
    const int n = bin >> 3, h = bin & 7;
    const int tid = threadIdx.x;
    const int w = tid >> 5, lane = tid & 31;

    if (tid == 0) lcnt = 0;
    __syncthreads();

    int count = g_nflags;
    if (count > MAXF) count = MAXF;
    for (int e = tid; e < count; e += 256) {
        const int pk = g_flags[e];
        if (((pk >> 14) & 31) == bin && (e & 7) == slice) {
            int p = atomicAdd(&lcnt, 1);
            if (p < FCAP) lst[p] = pk;
        }
    }
    __syncthreads();
    int nf = lcnt;
    if (nf > FCAP) nf = FCAP;

    float* xw = xb + w * 4 * 512;
    float* qw = qb + w * 4 * 64;

    for (int s = w * 4; s < nf; s += 32) {
        const int nn = min(4, nf - s);
        for (int ff = 0; ff < nn; ff++) {
            const int t = lst[s + ff] & 4095;
            const float* xr = x + ((size_t)n * Tt + t) * Dd;
            for (int e4 = lane; e4 < 128; e4 += 32)
                *(float4*)&xw[ff * 512 + e4 * 4] = *(const float4*)&xr[e4 * 4];
        }
        __syncwarp();

        float acc[4][2];
#pragma unroll
        for (int ff = 0; ff < 4; ff++) { acc[ff][0] = 0.f; acc[ff][1] = 0.f; }
        const float* Wc = WQ + h * 64;
        for (int k = 0; k < Dd; k++) {
            const float w0 = Wc[(size_t)k * Dd + lane];
            const float w1 = Wc[(size_t)k * Dd + lane + 32];
#pragma unroll
            for (int ff = 0; ff < 4; ff++) {
                acc[ff][0] += xw[ff * 512 + k] * w0;
                acc[ff][1] += xw[ff * 512 + k] * w1;
            }
        }
        const float b0 = bQ[h * 64 + lane], b1 = bQ[h * 64 + lane + 32];
        for (int ff = 0; ff < nn; ff++) {
            qw[ff * 64 + lane]      = acc[ff][0] + b0;
            qw[ff * 64 + lane + 32] = acc[ff][1] + b1;
        }
        __syncwarp();

        for (int ff = 0; ff < nn; ff++) {
            const int pk = lst[s + ff];
            const int t = pk & 4095, r = (pk >> 12) & 3;
            const float* rp = rot + (size_t)h * 8192 + r * 32 + lane;
            float v = 0.f;
#pragma unroll 8
            for (int f = 0; f < 64; f++)
                v += qw[ff * 64 + f] * rp[f * 128];
            float bv; int bi;
            if (-v > v) { bv = -v; bi = 32 + lane; }
            else        { bv = v;  bi = lane; }
#pragma unroll
            for (int o = 16; o; o >>= 1) {
                float ov = __shfl_xor_sync(0xffffffffu, bv, o);
                int   oi = __shfl_xor_sync(0xffffffffu, bi, o);
                if (ov > bv || (ov == bv && oi < bi)) { bv = ov; bi = oi; }
            }
            if (lane == 0)
                g_buckets[(((size_t)n * Hh + h) * NHh + r) * Tt + t] = bi + r * NBb;
        }
        __syncwarp();
    }
}

// ================= segmented stable counting sort per (n,h) =================
#define HROW 258
#define SMEM_SORT (Ll + 256 * HROW * 2 + 256 * 4)
__global__ void sort_kernel()
{
    extern __shared__ char smraw[];
    unsigned char*  sb   = (unsigned char*)smraw;
    unsigned short* hist = (unsigned short*)(smraw + Ll);
    int*            base = (int*)(smraw + Ll + 256 * HROW * 2);
    __shared__ int tot[256];

    const int nh = blockIdx.x;
    const int tid = threadIdx.x;

    for (int e = tid; e < 256 * HROW / 2; e += 256)
        ((unsigned int*)hist)[e] = 0;
    __syncthreads();

    const int* bptr = g_buckets + (size_t)nh * Ll;
    for (int e = tid; e < Ll; e += 256)
        sb[e] = (unsigned char)bptr[e];
    __syncthreads();

    {
        const int s = tid;
#pragma unroll 4
        for (int j = 0; j < 64; j++) {
            int b = sb[s * 64 + j];
            hist[b * HROW + s]++;
        }
    }
    __syncthreads();

    {
        const unsigned short* row = &hist[tid * HROW];
        int sum = 0;
#pragma unroll 8
        for (int s2 = 0; s2 < 256; s2++) sum += row[s2];
        tot[tid] = sum;
    }
    __syncthreads();
    if (tid == 0) {
        int run = 0;
        for (int b = 0; b < 256; b++) { base[b] = run; run += tot[b]; }
    }
    __syncthreads();

    {
        unsigned short* row = &hist[tid * HROW];
        unsigned short run = 0;
        for (int s2 = 0; s2 < 256; s2++) {
            unsigned short v = row[s2];
            row[s2] = run;
            run = (unsigned short)(run + v);
        }
    }
    __syncthreads();

    {
        const int s = tid;
        int* pout = g_perm + (size_t)nh * Ll;
        for (int j = 0; j < 64; j++) {
            int i = s * 64 + j;
            int b = sb[i];
            unsigned short off = hist[b * HROW + s];
            hist[b * HROW + s] = (unsigned short)(off + 1);
            pout[base[b] + off] = (b << 16) | i;
        }
    }
}

// ================= chunked attention (raw-q dots, column norm scale) ========
#define KHP 72
#define VP  72
#define OKH_HI 0
#define OKH_LO 18432
#define OV_HI  36864
#define OV_LO  55296
#define OMETA  73728
#define ORNORM 74240
#define OINVS  74752
#define SMEM_ATT3 75008

__global__ __launch_bounds__(128, 3)
void attention_kernel()
{
    extern __shared__ char smb[];
    __nv_bfloat16* kh_hi = (__nv_bfloat16*)(smb + OKH_HI);   // [128][72] raw q
    __nv_bfloat16* kh_lo = (__nv_bfloat16*)(smb + OKH_LO);
    __nv_bfloat16* v_hi  = (__nv_bfloat16*)(smb + OV_HI);    // [128][72]
    __nv_bfloat16* v_lo  = (__nv_bfloat16*)(smb + OV_LO);
    int*   pmeta = (int*)(smb + OMETA);                      // 128
    float* rnorm = (float*)(smb + ORNORM);                   // 128 (1/(||q||+eps))
    float* invs  = (float*)(smb + OINVS);                    // 64

    const int c = blockIdx.x, h = blockIdx.y, n = blockIdx.z;
    const int tid = threadIdx.x;
    const int pc = (c + CSs - 1) % CSs;

    {
        const int p = (tid < 64) ? (c * BSs + tid) : (pc * BSs + (tid - 64));
        pmeta[tid] = g_perm[((size_t)n * Hh + h) * Ll + p];
    }
    __syncthreads();

    const float* Qb = g_Q + (size_t)n * Tt * Dd + h * DHh;
    const float* Vb = g_V + (size_t)n * Tt * Dd + h * DHh;
    const int sub = tid >> 4, c4 = tid & 15;
#pragma unroll
    for (int i = 0; i < 16; i++) {
        const int row = i * 8 + sub;
        const int t = pmeta[row] & 4095;
        float4 qv = *(const float4*)&Qb[(size_t)t * Dd + c4 * 4];
        __nv_bfloat162 kh01 = __floats2bfloat162_rn(qv.x, qv.y);
        __nv_bfloat162 kl01 = __floats2bfloat162_rn(qv.x - __low2float(kh01), qv.y - __high2float(kh01));
        __nv_bfloat162 kh23 = __floats2bfloat162_rn(qv.z, qv.w);
        __nv_bfloat162 kl23 = __floats2bfloat162_rn(qv.z - __low2float(kh23), qv.w - __high2float(kh23));
        *(__nv_bfloat162*)&kh_hi[row * KHP + c4 * 4]     = kh01;
        *(__nv_bfloat162*)&kh_hi[row * KHP + c4 * 4 + 2] = kh23;
        *(__nv_bfloat162*)&kh_lo[row * KHP + c4 * 4]     = kl01;
        *(__nv_bfloat162*)&kh_lo[row * KHP + c4 * 4 + 2] = kl23;

        float4 vv = *(const float4*)&Vb[(size_t)t * Dd + c4 * 4];
        __nv_bfloat162 vh01 = __floats2bfloat162_rn(vv.x, vv.y);
        __nv_bfloat162 vl01 = __floats2bfloat162_rn(vv.x - __low2float(vh01), vv.y - __high2float(vh01));
        __nv_bfloat162 vh23 = __floats2bfloat162_rn(vv.z, vv.w);
        __nv_bfloat162 vl23 = __floats2bfloat162_rn(vv.z - __low2float(vh23), vv.w - __high2float(vh23));
        *(__nv_bfloat162*)&v_hi[row * VP + c4 * 4]     = vh01;
        *(__nv_bfloat162*)&v_hi[row * VP + c4 * 4 + 2] = vh23;
        *(__nv_bfloat162*)&v_lo[row * VP + c4 * 4]     = vl01;
        *(__nv_bfloat162*)&v_lo[row * VP + c4 * 4 + 2] = vl23;

        float ss = qv.x * qv.x + qv.y * qv.y + qv.z * qv.z + qv.w * qv.w;
        ss += __shfl_xor_sync(0xffffffffu, ss, 1);
        ss += __shfl_xor_sync(0xffffffffu, ss, 2);
        ss += __shfl_xor_sync(0xffffffffu, ss, 4);
        ss += __shfl_xor_sync(0xffffffffu, ss, 8);
        if (c4 == 0) rnorm[row] = 1.f / (sqrtf(ss) + 1e-6f);
    }
    __syncthreads();

    const int w = tid >> 5, lane = tid & 31;
    const int g = lane >> 2, tg = lane & 3;
    const int i0 = w * 16;

    const uint32_t khb_hi = smem_u32(kh_hi), khb_lo = smem_u32(kh_lo);
    const uint32_t vb_hi  = smem_u32(v_hi),  vb_lo  = smem_u32(v_lo);
    const uint32_t aoff = ((i0 + (lane & 15)) * KHP + 8 * (lane >> 4)) * 2;
    const uint32_t boff = (((lane & 7) + ((lane >= 16) ? 8 : 0)) * KHP + ((lane >> 3) & 1) * 8) * 2;
    const uint32_t voff = (((lane & 7) + 8 * ((lane >> 3) & 1)) * VP + 8 * (lane >> 4)) * 2;

    // ---- dots: D_ij = q_i . q_j (raw) ----
    float dc[16][4];
#pragma unroll
    for (int nt = 0; nt < 16; nt++)
#pragma unroll
        for (int k = 0; k < 4; k++) dc[nt][k] = 0.f;

#pragma unroll
    for (int k0 = 0; k0 < 64; k0 += 16) {
        uint32_t ah[4], al[4];
        LDSM4(ah[0], ah[1], ah[2], ah[3], khb_hi + aoff + k0 * 2);
        LDSM4(al[0], al[1], al[2], al[3], khb_lo + aoff + k0 * 2);
#pragma unroll
        for (int jt = 0; jt < 8; jt++) {
            uint32_t bh[4], bl[4];
            const uint32_t jb = (uint32_t)(jt * 16 * KHP + k0) * 2;
            LDSM4(bh[0], bh[1], bh[2], bh[3], khb_hi + boff + jb);
            LDSM4(bl[0], bl[1], bl[2], bl[3], khb_lo + boff + jb);
            MMA_BF16(dc[2 * jt], ah, bh);
            MMA_BF16(dc[2 * jt], ah, bl);
            MMA_BF16(dc[2 * jt], al, bh);
            MMA_BF16(dc[2 * jt + 1], ah, bh + 2);
            MMA_BF16(dc[2 * jt + 1], ah, bl + 2);
            MMA_BF16(dc[2 * jt + 1], al, bh + 2);
        }
    }

    // ---- masks + softmax; S_ij = D_ij * 0.125 * rnorm_j (column scale) ----
    const int ra = i0 + g, rb = i0 + g + 8;
    {
        const int pka = pmeta[ra], pkb = pmeta[rb];

#pragma unroll
        for (int nt = 0; nt < 16; nt++) {
            const int j0 = nt * 8 + 2 * tg;
            const int pj0 = pmeta[j0], pj1 = pmeta[j0 + 1];
            const float s0 = 0.125f * rnorm[j0];
            const float s1 = 0.125f * rnorm[j0 + 1];
            float x;
            x = dc[nt][0] * s0;
            if ((pka >> 16) != (pj0 >> 16)) x = -1e9f;
            if (((pka ^ pj0) & 4095) == 0)  x = -1e-5f;
            dc[nt][0] = x;
            x = dc[nt][1] * s1;
            if ((pka >> 16) != (pj1 >> 16)) x = -1e9f;
            if (((pka ^ pj1) & 4095) == 0)  x = -1e-5f;
            dc[nt][1] = x;
            x = dc[nt][2] * s0;
            if ((pkb >> 16) != (pj0 >> 16)) x = -1e9f;
            if (((pkb ^ pj0) & 4095) == 0)  x = -1e-5f;
            dc[nt][2] = x;
            x = dc[nt][3] * s1;
            if ((pkb >> 16) != (pj1 >> 16)) x = -1e9f;
            if (((pkb ^ pj1) & 4095) == 0)  x = -1e-5f;
            dc[nt][3] = x;
        }

        float ma = -1e30f, mb = -1e30f;
#pragma unroll
        for (int nt = 0; nt < 16; nt++) {
            ma = fmaxf(ma, fmaxf(dc[nt][0], dc[nt][1]));
            mb = fmaxf(mb, fmaxf(dc[nt][2], dc[nt][3]));
        }
        ma = fmaxf(ma, __shfl_xor_sync(0xffffffffu, ma, 1));
        ma = fmaxf(ma, __shfl_xor_sync(0xffffffffu, ma, 2));
        mb = fmaxf(mb, __shfl_xor_sync(0xffffffffu, mb, 1));
        mb = fmaxf(mb, __shfl_xor_sync(0xffffffffu, mb, 2));

        float sa = 0.f, sb2 = 0.f;
#pragma unroll
        for (int nt = 0; nt < 16; nt++) {
            dc[nt][0] = __expf(dc[nt][0] - ma); sa  += dc[nt][0];
            dc[nt][1] = __expf(dc[nt][1] - ma); sa  += dc[nt][1];
            dc[nt][2] = __expf(dc[nt][2] - mb); sb2 += dc[nt][2];
            dc[nt][3] = __expf(dc[nt][3] - mb); sb2 += dc[nt][3];
        }
        sa  += __shfl_xor_sync(0xffffffffu, sa, 1);
        sa  += __shfl_xor_sync(0xffffffffu, sa, 2);
        sb2 += __shfl_xor_sync(0xffffffffu, sb2, 1);
        sb2 += __shfl_xor_sync(0xffffffffu, sb2, 2);

        if (tg == 0) {
            const int nhbase = ((int)n * Hh + h) * NHh;
            const int ta = pka & 4095, rra = (pka >> 12) & 3;
            const int tb = pkb & 4095, rrb = (pkb >> 12) & 3;
            g_logits[((size_t)nhbase + rra) * Tt + ta] = ma + __logf(sa);
            g_logits[((size_t)nhbase + rrb) * Tt + tb] = mb + __logf(sb2);
            invs[ra] = 1.f / sa;
            invs[rb] = 1.f / sb2;
        }
        __syncwarp();
    }

    // ---- PV: O = P @ V, P fed straight from registers ----
    float oc[8][4];
#pragma unroll
    for (int nt = 0; nt < 8; nt++)
#pragma unroll
        for (int k = 0; k < 4; k++) oc[nt][k] = 0.f;

#pragma unroll
    for (int kc = 0; kc < 8; kc++) {
        uint32_t phi[4], plo[4];
        {
            __nv_bfloat162 hp, lp;
            hp = __floats2bfloat162_rn(dc[2 * kc][0], dc[2 * kc][1]);
            lp = __floats2bfloat162_rn(dc[2 * kc][0] - __low2float(hp),
                                       dc[2 * kc][1] - __high2float(hp));
            phi[0] = *(uint32_t*)&hp; plo[0] = *(uint32_t*)&lp;
            hp = __floats2bfloat162_rn(dc[2 * kc][2], dc[2 * kc][3]);
            lp = __floats2bfloat162_rn(dc[2 * kc][2] - __low2float(hp),
                                       dc[2 * kc][3] - __high2float(hp));
            phi[1] = *(uint32_t*)&hp; plo[1] = *(uint32_t*)&lp;
            hp = __floats2bfloat162_rn(dc[2 * kc + 1][0], dc[2 * kc + 1][1]);
            lp = __floats2bfloat162_rn(dc[2 * kc + 1][0] - __low2float(hp),
                                       dc[2 * kc + 1][1] - __high2float(hp));
            phi[2] = *(uint32_t*)&hp; plo[2] = *(uint32_t*)&lp;
            hp = __floats2bfloat162_rn(dc[2 * kc + 1][2], dc[2 * kc + 1][3]);
            lp = __floats2bfloat162_rn(dc[2 * kc + 1][2] - __low2float(hp),
                                       dc[2 * kc + 1][3] - __high2float(hp));
            phi[3] = *(uint32_t*)&hp; plo[3] = *(uint32_t*)&lp;
        }
#pragma unroll
        for (int ft = 0; ft < 4; ft++) {
            uint32_t vh[4], vl[4];
            const uint32_t vbo = (uint32_t)(kc * 16 * VP + ft * 16) * 2;
            LDSM4T(vh[0], vh[1], vh[2], vh[3], vb_hi + voff + vbo);
            LDSM4T(vl[0], vl[1], vl[2], vl[3], vb_lo + voff + vbo);
            MMA_BF16(oc[2 * ft], phi, vh);
            MMA_BF16(oc[2 * ft], phi, vl);
            MMA_BF16(oc[2 * ft], plo, vh);
            MMA_BF16(oc[2 * ft + 1], phi, vh + 2);
            MMA_BF16(oc[2 * ft + 1], phi, vl + 2);
            MMA_BF16(oc[2 * ft + 1], plo, vh + 2);
        }
    }

    {
        const int pka = pmeta[ra], pkb = pmeta[rb];
        const float iva = invs[ra], ivb = invs[rb];
        const size_t obase = ((size_t)n * Hh + h) * NHh;
        const size_t oa = ((obase + ((pka >> 12) & 3)) * Tt + (pka & 4095)) * DHh;
        const size_t ob = ((obase + ((pkb >> 12) & 3)) * Tt + (pkb & 4095)) * DHh;
#pragma unroll
        for (int ft = 0; ft < 4; ft++) {
            const int f0 = ft * 16 + 2 * tg;
            *(float2*)&g_O[oa + f0]     = make_float2(oc[2 * ft][0] * iva, oc[2 * ft][1] * iva);
            *(float2*)&g_O[ob + f0]     = make_float2(oc[2 * ft][2] * ivb, oc[2 * ft][3] * ivb);
            *(float2*)&g_O[oa + f0 + 8] = make_float2(oc[2 * ft + 1][0] * iva, oc[2 * ft + 1][1] * iva);
            *(float2*)&g_O[ob + f0 + 8] = make_float2(oc[2 * ft + 1][2] * ivb, oc[2 * ft + 1][3] * ivb);
        }
    }
}

// ================= round-combine softmax + LayerNorm (shfl reduce) ==========
__global__ void combine_ln_kernel(const float* __restrict__ gamma,
                                  const float* __restrict__ beta,
                                  float* __restrict__ out)
{
    const int bid = blockIdx.x;            // n*T + t
    const int n = bid >> 12, t = bid & 4095;
    const int tid = threadIdx.x;           // 128
    const int w = tid >> 5, lane = tid & 31;
    __shared__ float wsh[Hh][NHh];
    __shared__ float rs[4], rq[4];

    if (tid < Hh) {
        const int h = tid;
        float l[NHh];
        float m = -1e30f;
#pragma unroll
        for (int r = 0; r < NHh; r++) {
            l[r] = g_logits[(((size_t)n * Hh + h) * NHh + r) * Tt + t];
            m = fmaxf(m, l[r]);
        }
        float s = 0.f;
#pragma unroll
        for (int r = 0; r < NHh; r++) s += __expf(l[r] - m);
        const float lse = m + __logf(s);
#pragma unroll
        for (int r = 0; r < NHh; r++) wsh[h][r] = __expf(l[r] - lse);
    }
    __syncthreads();

    float vals[4];
    float lsum = 0.f, lsq = 0.f;
#pragma unroll
    for (int k2 = 0; k2 < 4; k2++) {
        const int d = tid + k2 * 128;
        const int h = d >> 6, f = d & 63;
        float a = 0.f;
#pragma unroll
        for (int r = 0; r < NHh; r++)
            a += wsh[h][r] * g_O[((((size_t)n * Hh + h) * NHh + r) * Tt + t) * DHh + f];
        vals[k2] = a;
        lsum += a;
        lsq  += a * a;
    }

#pragma unroll
    for (int o = 16; o; o >>= 1) {
        lsum += __shfl_xor_sync(0xffffffffu, lsum, o);
        lsq  += __shfl_xor_sync(0xffffffffu, lsq, o);
    }
    if (lane == 0) { rs[w] = lsum; rq[w] = lsq; }
    __syncthreads();
    const float ts = rs[0] + rs[1] + rs[2] + rs[3];
    const float tq = rq[0] + rq[1] + rq[2] + rq[3];
    const float mu = ts * (1.f / Dd);
    const float var = tq * (1.f / Dd) - mu * mu;
    const float rstd = rsqrtf(var + 1e-3f);

#pragma unroll
    for (int k2 = 0; k2 < 4; k2++) {
        const int d = tid + k2 * 128;
        out[(size_t)bid * Dd + d] = gamma[d] * (vals[k2] - mu) * rstd + beta[d];
    }
}

// ================= launch ===================================================
extern "C" void kernel_launch(void* const* d_in, const int* in_sizes, int n_in,
                              void* d_out, int out_size)
{
    const float* x     = (const float*)d_in[0];
    const float* W_Q   = (const float*)d_in[1];
    const float* b_Q   = (const float*)d_in[2];
    const float* W_V   = (const float*)d_in[3];
    const float* b_V   = (const float*)d_in[4];
    const float* gamma = (const float*)d_in[5];
    const float* beta  = (const float*)d_in[6];
    const float* rot   = (const float*)d_in[7];
    float* out = (float*)d_out;

    cudaFuncSetAttribute(attention_kernel,
                         cudaFuncAttributeMaxDynamicSharedMemorySize, SMEM_ATT3);
    cudaFuncSetAttribute(sort_kernel,
                         cudaFuncAttributeMaxDynamicSharedMemorySize, SMEM_SORT);
    cudaFuncSetAttribute(gemm_qv_kernel,
                         cudaFuncAttributeMaxDynamicSharedMemorySize, SMEM_MMA);
    cudaFuncSetAttribute(bucket_kernel,
                         cudaFuncAttributeMaxDynamicSharedMemorySize, SMEM_BKT);
    cudaFuncSetAttribute(fixup_kernel,
                         cudaFuncAttributeMaxDynamicSharedMemorySize, SMEM_FIX);

    reset_kernel<<<1, 1>>>();

    split_x_kernel<<<(Nb * Tt * Dd / 4) / 256, 256>>>(x);   // 8192 blocks
    split_w_kernel<<<dim3(16, 16, 2), dim3(32, 8)>>>(W_Q, W_V);

    dim3 gGrid(2, (Nb * Tt) / 128, 2);          // (2, 128, 2) -> Q and V
    gemm_qv_kernel<<<gGrid, 512, SMEM_MMA>>>(b_Q, b_V);

    dim3 bGrid(Tt / 128, Hh, Nb);               // (32, 8, 4)
    bucket_kernel<<<bGrid, 256, SMEM_BKT>>>(rot);

    fixup_kernel<<<dim3(32, 8), 256, SMEM_FIX>>>(x, W_Q, b_Q, rot);

    sort_kernel<<<Nb * Hh, 256, SMEM_SORT>>>(); // 32 blocks

    dim3 aGrid(CSs, Hh, Nb);                    // (256, 8, 4)
    attention_kernel<<<aGrid, 128, SMEM_ATT3>>>();

    combine_ln_kernel<<<Nb * Tt, 128>>>(gamma, beta, out);
}

// round 15
// speedup vs baseline: 1.2440x; 1.0204x over previous
#include <cuda_runtime.h>
#include <cuda_bf16.h>
#include <math.h>
#include <stdint.h>

// Problem constants
#define Nb   4          // batch
#define Tt   4096       // sequence length
#define Dd   512        // model dim
#define Hh   8          // heads
#define NHh  4          // hash rounds
#define BSs  64         // bucket chunk size
#define DHh  64         // head dim
#define NBb  64         // n_buckets
#define CSs  256        // chunks = NH * NB
#define Ll   16384      // NH * T

typedef unsigned long long u64;

// ---------------- scratch (device globals; no allocation allowed) ----------
__device__ float g_Q[(size_t)Nb * Tt * Dd];                 // 33.5 MB
__device__ float g_V[(size_t)Nb * Tt * Dd];                 // 33.5 MB
__device__ int   g_buckets[(size_t)Nb * Hh * NHh * Tt];     // 2 MB
__device__ int   g_perm[(size_t)Nb * Hh * Ll];              // 2 MB
__device__ float g_O[(size_t)Nb * Hh * NHh * Tt * DHh];     // 134 MB
__device__ float g_logits[(size_t)Nb * Hh * NHh * Tt];      // 2 MB
__device__ __nv_bfloat16 g_wthi[2][Dd * Dd];                // 1 MB (W^T hi: 0=Q,1=V)
__device__ __nv_bfloat16 g_wtlo[2][Dd * Dd];                // 1 MB
__device__ __nv_bfloat16 g_xhi[(size_t)Nb * Tt * Dd];       // 16 MB
__device__ __nv_bfloat16 g_xlo[(size_t)Nb * Tt * Dd];       // 16 MB
#define MAXF 131072
__device__ int g_nflags;
__device__ int g_flags[MAXF];                               // packed (n<<17)|(h<<14)|(r<<12)|t

// ================= helpers ==================================================
__device__ __forceinline__ uint32_t smem_u32(const void* p) {
    uint32_t a;
    asm("{ .reg .u64 t; cvta.to.shared.u64 t, %1; cvt.u32.u64 %0, t; }" : "=r"(a) : "l"(p));
    return a;
}
#define MMA_BF16(d, a, b)                                                     \
    asm volatile("mma.sync.aligned.m16n8k16.row.col.f32.bf16.bf16.f32 "       \
        "{%0,%1,%2,%3}, {%4,%5,%6,%7}, {%8,%9}, {%0,%1,%2,%3};"               \
        : "+f"((d)[0]), "+f"((d)[1]), "+f"((d)[2]), "+f"((d)[3])              \
        : "r"((a)[0]), "r"((a)[1]), "r"((a)[2]), "r"((a)[3]),                 \
          "r"((b)[0]), "r"((b)[1]))
#define LDSM4(r0, r1, r2, r3, addr)                                           \
    asm volatile("ldmatrix.sync.aligned.m8n8.x4.shared.b16 {%0,%1,%2,%3}, [%4];" \
        : "=r"(r0), "=r"(r1), "=r"(r2), "=r"(r3) : "r"(addr))
#define LDSM4T(r0, r1, r2, r3, addr)                                          \
    asm volatile("ldmatrix.sync.aligned.m8n8.x4.trans.shared.b16 {%0,%1,%2,%3}, [%4];" \
        : "=r"(r0), "=r"(r1), "=r"(r2), "=r"(r3) : "r"(addr))
#define FFMA2(d, a, b) \
    asm("fma.rn.f32x2 %0, %1, %2, %0;" : "+l"(d) : "l"(a), "l"(b))
#define PACK2(d, x, y) \
    asm("mov.b64 %0, {%1, %2};" : "=l"(d) : "f"(x), "f"(y))
#define UNPACK2(x, y, d) \
    asm("mov.b64 {%0, %1}, %2;" : "=f"(x), "=f"(y) : "l"(d))

// ================= reset ====================================================
__global__ void reset_kernel() { g_nflags = 0; }

// ================= split x -> bf16 hi/lo ====================================
__global__ void split_x_kernel(const float* __restrict__ x)
{
    const size_t i = (size_t)blockIdx.x * 256 + threadIdx.x;   // per float4
    float4 v = ((const float4*)x)[i];
    __nv_bfloat162 h01 = __floats2bfloat162_rn(v.x, v.y);
    __nv_bfloat162 h23 = __floats2bfloat162_rn(v.z, v.w);
    __nv_bfloat162 l01 = __floats2bfloat162_rn(v.x - __low2float(h01), v.y - __high2float(h01));
    __nv_bfloat162 l23 = __floats2bfloat162_rn(v.z - __low2float(h23), v.w - __high2float(h23));
    ((__nv_bfloat162*)g_xhi)[i * 2]     = h01;
    ((__nv_bfloat162*)g_xhi)[i * 2 + 1] = h23;
    ((__nv_bfloat162*)g_xlo)[i * 2]     = l01;
    ((__nv_bfloat162*)g_xlo)[i * 2 + 1] = l23;
}

// ================= split + transpose W_Q / W_V ==============================
__global__ void split_w_kernel(const float* __restrict__ WQ, const float* __restrict__ WV)
{
    __shared__ float tile[32][33];
    const float* W = blockIdx.z ? WV : WQ;
    const int bx = blockIdx.x * 32;   // n block
    const int by = blockIdx.y * 32;   // k block
    const int tx = threadIdx.x, ty = threadIdx.y;   // 32 x 8
#pragma unroll
    for (int r = 0; r < 32; r += 8)
        tile[ty + r][tx] = W[(size_t)(by + ty + r) * Dd + bx + tx];
    __syncthreads();
#pragma unroll
    for (int r = 0; r < 32; r += 8) {
        float val = tile[tx][ty + r];
        __nv_bfloat16 hi = __float2bfloat16(val);
        __nv_bfloat16 lo = __float2bfloat16(val - __bfloat162float(hi));
        size_t o = (size_t)(bx + ty + r) * Dd + by + tx;
        g_wthi[blockIdx.z][o] = hi;
        g_wtlo[blockIdx.z][o] = lo;
    }
}

// ================= Q/V GEMM: bf16 mma + ldmatrix + double-buffered smem =====
#define PITCH 40
#define A_HI  0
#define A_LO  (128 * PITCH)
#define B_HI  (2 * 128 * PITCH)
#define B_LO  (2 * 128 * PITCH + 256 * PITCH)
#define BUFH  (2 * 128 * PITCH + 2 * 256 * PITCH)      // halves per buffer (30720)
#define BUFB  (BUFH * 2)                               // bytes per buffer (61440)
#define SMEM_MMA (2 * BUFB)
#define ALO_B  (128 * PITCH * 2)
#define BHI_B  (2 * 128 * PITCH * 2)
#define BLO_D  (256 * PITCH * 2)

__global__ __launch_bounds__(512, 1)
void gemm_qv_kernel(const float* __restrict__ bQ, const float* __restrict__ bV)
{
    extern __shared__ uint16_t sm16[];
    const int tid = threadIdx.x;
    const int wid = tid >> 5, lane = tid & 31;
    const int g = lane >> 2, tg = lane & 3;
    const int wm = wid & 3, wn = wid >> 2;
    const int mbase = blockIdx.y * 128;
    const int ncol0 = blockIdx.x * 256;
    const int which = blockIdx.z;                 // 0 = Q, 1 = V
    const __nv_bfloat16* Whi = g_wthi[which];
    const __nv_bfloat16* Wlo = g_wtlo[which];
    const float* bias = which ? bV : bQ;
    float* C = which ? g_V : g_Q;

    const uint32_t smbase = smem_u32(sm16);
    const uint32_t aoff0 = ((wm * 32 + (lane & 15)) * PITCH + 8 * (lane >> 4)) * 2;
    const uint32_t boff0 = (((lane & 7) + ((lane >= 16) ? 8 : 0)) * PITCH
                            + ((lane >> 3) & 1) * 8) * 2;

    // precomputed staging indices (per thread)
    const __nv_bfloat16* asrc[2]; uint32_t adst[2];
#pragma unroll
    for (int i = 0; i < 2; i++) {
        const int e = tid + i * 512;              // [0,1024)
        const int split = e >> 9;
        const int r = (e >> 2) & 127;
        const int k8 = e & 3;
        asrc[i] = (split ? g_xlo : g_xhi) + (size_t)(mbase + r) * Dd + k8 * 8;
        adst[i] = (split ? A_LO : A_HI) + r * PITCH + k8 * 8;
    }
    const __nv_bfloat16* bsrc[4]; uint32_t bdst[4];
#pragma unroll
    for (int i = 0; i < 4; i++) {
        const int e = tid + i * 512;              // [0,2048)
        const int split = e >> 10;
        const int r = (e >> 2) & 255;
        const int k8 = e & 3;
        bsrc[i] = (split ? Wlo : Whi) + (size_t)(ncol0 + r) * Dd + k8 * 8;
        bdst[i] = (split ? B_LO : B_HI) + r * PITCH + k8 * 8;
    }

    float acc[2][8][4];
#pragma unroll
    for (int i = 0; i < 2; i++)
#pragma unroll
        for (int j = 0; j < 8; j++)
#pragma unroll
            for (int k = 0; k < 4; k++) acc[i][j][k] = 0.f;

    uint4 pa[2], pb[4];
    // prologue: load + store slab 0 into buffer 0
#pragma unroll
    for (int i = 0; i < 2; i++) pa[i] = *(const uint4*)(asrc[i]);
#pragma unroll
    for (int i = 0; i < 4; i++) pb[i] = *(const uint4*)(bsrc[i]);
#pragma unroll
    for (int i = 0; i < 2; i++) *(uint4*)(sm16 + adst[i]) = pa[i];
#pragma unroll
    for (int i = 0; i < 4; i++) *(uint4*)(sm16 + bdst[i]) = pb[i];
    __syncthreads();

    for (int slab = 0; slab < 16; slab++) {
        const uint32_t curB = (uint32_t)(slab & 1) * BUFB;
        const uint32_t nxtH = (uint32_t)((slab & 1) ^ 1) * BUFH;

        // prefetch next slab into registers (hidden behind MMA work)
        if (slab < 15) {
            const int kt = (slab + 1) * 32;
#pragma unroll
            for (int i = 0; i < 2; i++) pa[i] = *(const uint4*)(asrc[i] + kt);
#pragma unroll
            for (int i = 0; i < 4; i++) pb[i] = *(const uint4*)(bsrc[i] + kt);
        }

#pragma unroll
        for (int kk = 0; kk < 32; kk += 16) {
            uint32_t ah[2][4], al[2][4];
#pragma unroll
            for (int mt = 0; mt < 2; mt++) {
                const uint32_t aa = smbase + curB + aoff0
                    + (uint32_t)(mt * 16 * PITCH + kk) * 2;
                LDSM4(ah[mt][0], ah[mt][1], ah[mt][2], ah[mt][3], aa);
                LDSM4(al[mt][0], al[mt][1], al[mt][2], al[mt][3], aa + ALO_B);
            }
#pragma unroll
            for (int ng = 0; ng < 2; ng++) {
                uint32_t bh[2][4], bl[2][4];
#pragma unroll
                for (int hh = 0; hh < 2; hh++) {
                    const uint32_t bb = smbase + curB + BHI_B + boff0
                        + (uint32_t)((wn * 64 + ng * 32 + hh * 16) * PITCH + kk) * 2;
                    LDSM4(bh[hh][0], bh[hh][1], bh[hh][2], bh[hh][3], bb);
                    LDSM4(bl[hh][0], bl[hh][1], bl[hh][2], bl[hh][3], bb + BLO_D);
                }
#pragma unroll
                for (int mt = 0; mt < 2; mt++)
#pragma unroll
                    for (int q = 0; q < 4; q++) {
                        float* d = acc[mt][ng * 4 + q];
                        uint32_t* bhp = bh[q >> 1] + (q & 1) * 2;
                        uint32_t* blp = bl[q >> 1] + (q & 1) * 2;
                        MMA_BF16(d, ah[mt], bhp);
                        MMA_BF16(d, ah[mt], blp);
                        MMA_BF16(d, al[mt], bhp);
                    }
            }
        }
        // store next slab into the other buffer (no barrier before: disjoint)
        if (slab < 15) {
#pragma unroll
            for (int i = 0; i < 2; i++) *(uint4*)(sm16 + nxtH + adst[i]) = pa[i];
#pragma unroll
            for (int i = 0; i < 4; i++) *(uint4*)(sm16 + nxtH + bdst[i]) = pb[i];
            __syncthreads();
        }
    }

#pragma unroll
    for (int mt = 0; mt < 2; mt++) {
        const int r0 = mbase + wm * 32 + mt * 16 + g;
#pragma unroll
        for (int nt = 0; nt < 8; nt++) {
            const int col = ncol0 + wn * 64 + nt * 8 + 2 * tg;
            float2 b2 = *(const float2*)&bias[col];
            float2 o0, o1;
            o0.x = acc[mt][nt][0] + b2.x;
            o0.y = acc[mt][nt][1] + b2.y;
            o1.x = acc[mt][nt][2] + b2.x;
            o1.y = acc[mt][nt][3] + b2.y;
            *(float2*)&C[(size_t)r0 * Dd + col] = o0;
            *(float2*)&C[(size_t)(r0 + 8) * Dd + col] = o1;
        }
    }
}

// ================= bucket kernel: GEMM (FFMA2) + argmax + margin flag =======
#define AsP 68
#define BsP 132
#define SMEM_BKT ((128 * AsP + 64 * BsP) * 4)

__global__ __launch_bounds__(256, 2)
void bucket_kernel(const float* __restrict__ rot)
{
    extern __shared__ float smf[];
    float* As = smf;                  // [128 m][68 k]
    float* Bs = smf + 128 * AsP;      // [64 k][132 c]

    const int h = blockIdx.y, n = blockIdx.z;
    const int tid = threadIdx.x;      // 256
    const int tx = tid & 15, ty = tid >> 4;
    const int t0 = blockIdx.x * 128;

    const float* Qb = g_Q + ((size_t)n * Tt + t0) * Dd + h * DHh;
#pragma unroll
    for (int l = 0; l < 8; l++) {
        const int e = tid + l * 256;
        const int r = e >> 4, c4 = e & 15;
        *(float4*)&As[r * AsP + c4 * 4] = *(const float4*)&Qb[(size_t)r * Dd + c4 * 4];
    }
    const float* Rb = rot + (size_t)h * 8192;
#pragma unroll
    for (int l = 0; l < 8; l++) {
        const int e = tid + l * 256;
        const int kr = e >> 5, c4 = e & 31;
        *(float4*)&Bs[kr * BsP + c4 * 4] = *(const float4*)&Rb[kr * 128 + c4 * 4];
    }
    __syncthreads();

    u64 acc2[8][4];
#pragma unroll
    for (int i = 0; i < 8; i++)
#pragma unroll
        for (int j = 0; j < 4; j++) acc2[i][j] = 0ull;

#pragma unroll 4
    for (int k = 0; k < 64; k++) {
        float a[8];
#pragma unroll
        for (int i = 0; i < 8; i++) a[i] = As[(ty * 8 + i) * AsP + k];
        u64 a2[8];
#pragma unroll
        for (int i = 0; i < 8; i++) PACK2(a2[i], a[i], a[i]);
        ulonglong2 bp0 = *(const ulonglong2*)&Bs[k * BsP + tx * 8];
        ulonglong2 bp1 = *(const ulonglong2*)&Bs[k * BsP + tx * 8 + 4];
        u64 b2[4] = {bp0.x, bp0.y, bp1.x, bp1.y};
#pragma unroll
        for (int i = 0; i < 8; i++)
#pragma unroll
            for (int j = 0; j < 4; j++) FFMA2(acc2[i][j], a2[i], b2[j]);
    }

    const int ig = (tx & 3) * 8;
    const int r = tx >> 2;
#pragma unroll
    for (int i = 0; i < 8; i++) {
        float acc[8];
#pragma unroll
        for (int jp = 0; jp < 4; jp++)
            UNPACK2(acc[2 * jp], acc[2 * jp + 1], acc2[i][jp]);

        float t1 = acc[0]; int i1 = ig; float t2 = -3.4e38f;
#pragma unroll
        for (int j = 1; j < 8; j++) {
            float v = acc[j];
            if (v > t1) { t2 = t1; t1 = v; i1 = ig + j; }
            else t2 = fmaxf(t2, v);
        }
#pragma unroll
        for (int j = 0; j < 8; j++) {
            float v = -acc[j];
            if (v > t1) { t2 = t1; t1 = v; i1 = 32 + ig + j; }
            else t2 = fmaxf(t2, v);
        }
#pragma unroll
        for (int o = 1; o <= 2; o <<= 1) {
            float o1 = __shfl_xor_sync(0xffffffffu, t1, o);
            int   oi = __shfl_xor_sync(0xffffffffu, i1, o);
            float o2 = __shfl_xor_sync(0xffffffffu, t2, o);
            if (o1 > t1 || (o1 == t1 && oi < i1)) {
                t2 = fmaxf(t1, o2); t1 = o1; i1 = oi;
            } else {
                t2 = fmaxf(t2, o1);
            }
        }

        if ((tx & 3) == 0) {
            const int t = t0 + ty * 8 + i;
            g_buckets[(((size_t)n * Hh + h) * NHh + r) * Tt + t] = i1 + r * NBb;
            if (t1 - t2 < 1e-4f * t1 + 1e-4f) {
                int p = atomicAdd(&g_nflags, 1);
                if (p < MAXF)
                    g_flags[p] = (n << 17) | (h << 14) | (r << 12) | t;
            }
        }
    }
}

// ================= fix-up: exact recompute of flagged decisions =============
#define FCAP 6144
#define OF_LST 0
#define OF_XB  (FCAP * 4)
#define OF_QB  (FCAP * 4 + 8 * 4 * 512 * 4)
#define SMEM_FIX (FCAP * 4 + 8 * 4 * 512 * 4 + 8 * 4 * 64 * 4)

__global__ __launch_bounds__(256)
void fixup_kernel(const float* __restrict__ x, const float* __restrict__ WQ,
                  const float* __restrict__ bQ, const float* __restrict__ rot)
{
    extern __shared__ char fsm[];
    int*   lst = (int*)(fsm + OF_LST);
    float* xb  = (float*)(fsm + OF_XB);    // [8 warps][4 flags][512]
    float* qb  = (float*)(fsm + OF_QB);    // [8 warps][4 flags][64]
    __shared__ int lcnt;

    const int bin = blockIdx.x;            // n*8 + h
    const int slice = blockIdx.y;          // 0..7
    const int n = bin >> 3, h = bin & 7;
    const int tid = threadIdx.x;
    const int w = tid >> 5, lane = tid & 31;

    if (tid == 0) lcnt = 0;
    __syncthreads();

    int count = g_nflags;
    if (count > MAXF) count = MAXF;
    for (int e = tid; e < count; e += 256) {
        const int pk = g_flags[e];
        if (((pk >> 14) & 31) == bin && (e & 7) == slice) {
            int p = atomicAdd(&lcnt, 1);
            if (p < FCAP) lst[p] = pk;
        }
    }
    __syncthreads();
    int nf = lcnt;
    if (nf > FCAP) nf = FCAP;

    float* xw = xb + w * 4 * 512;
    float* qw = qb + w * 4 * 64;

    for (int s = w * 4; s < nf; s += 32) {
        const int nn = min(4, nf - s);
        for (int ff = 0; ff < nn; ff++) {
            const int t = lst[s + ff] & 4095;
            const float* xr = x + ((size_t)n * Tt + t) * Dd;
            for (int e4 = lane; e4 < 128; e4 += 32)
                *(float4*)&xw[ff * 512 + e4 * 4] = *(const float4*)&xr[e4 * 4];
        }
        __syncwarp();

        float acc[4][2];
#pragma unroll
        for (int ff = 0; ff < 4; ff++) { acc[ff][0] = 0.f; acc[ff][1] = 0.f; }
        const float* Wc = WQ + h * 64;
        for (int k = 0; k < Dd; k++) {
            const float w0 = Wc[(size_t)k * Dd + lane];
            const float w1 = Wc[(size_t)k * Dd + lane + 32];
#pragma unroll
            for (int ff = 0; ff < 4; ff++) {
                acc[ff][0] += xw[ff * 512 + k] * w0;
                acc[ff][1] += xw[ff * 512 + k] * w1;
            }
        }
        const float b0 = bQ[h * 64 + lane], b1 = bQ[h * 64 + lane + 32];
        for (int ff = 0; ff < nn; ff++) {
            qw[ff * 64 + lane]      = acc[ff][0] + b0;
            qw[ff * 64 + lane + 32] = acc[ff][1] + b1;
        }
        __syncwarp();

        for (int ff = 0; ff < nn; ff++) {
            const int pk = lst[s + ff];
            const int t = pk & 4095, r = (pk >> 12) & 3;
            const float* rp = rot + (size_t)h * 8192 + r * 32 + lane;
            float v = 0.f;
#pragma unroll 8
            for (int f = 0; f < 64; f++)
                v += qw[ff * 64 + f] * rp[f * 128];
            float bv; int bi;
            if (-v > v) { bv = -v; bi = 32 + lane; }
            else        { bv = v;  bi = lane; }
#pragma unroll
            for (int o = 16; o; o >>= 1) {
                float ov = __shfl_xor_sync(0xffffffffu, bv, o);
                int   oi = __shfl_xor_sync(0xffffffffu, bi, o);
                if (ov > bv || (ov == bv && oi < bi)) { bv = ov; bi = oi; }
            }
            if (lane == 0)
                g_buckets[(((size_t)n * Hh + h) * NHh + r) * Tt + t] = bi + r * NBb;
        }
        __syncwarp();
    }
}

// ================= segmented stable counting sort per (n,h) =================
#define HROW 258
#define SMEM_SORT (Ll + 256 * HROW * 2 + 256 * 4)
__global__ void sort_kernel()
{
    extern __shared__ char smraw[];
    unsigned char*  sb   = (unsigned char*)smraw;
    unsigned short* hist = (unsigned short*)(smraw + Ll);
    int*            base = (int*)(smraw + Ll + 256 * HROW * 2);
    __shared__ int tot[256];

    const int nh = blockIdx.x;
    const int tid = threadIdx.x;

    for (int e = tid; e < 256 * HROW / 2; e += 256)
        ((unsigned int*)hist)[e] = 0;
    __syncthreads();

    const int* bptr = g_buckets + (size_t)nh * Ll;
    for (int e = tid; e < Ll; e += 256)
        sb[e] = (unsigned char)bptr[e];
    __syncthreads();

    {
        const int s = tid;
#pragma unroll 4
        for (int j = 0; j < 64; j++) {
            int b = sb[s * 64 + j];
            hist[b * HROW + s]++;
        }
    }
    __syncthreads();

    {
        const unsigned short* row = &hist[tid * HROW];
        int sum = 0;
#pragma unroll 8
        for (int s2 = 0; s2 < 256; s2++) sum += row[s2];
        tot[tid] = sum;
    }
    __syncthreads();
    if (tid == 0) {
        int run = 0;
        for (int b = 0; b < 256; b++) { base[b] = run; run += tot[b]; }
    }
    __syncthreads();

    {
        unsigned short* row = &hist[tid * HROW];
        unsigned short run = 0;
        for (int s2 = 0; s2 < 256; s2++) {
            unsigned short v = row[s2];
            row[s2] = run;
            run = (unsigned short)(run + v);
        }
    }
    __syncthreads();

    {
        const int s = tid;
        int* pout = g_perm + (size_t)nh * Ll;
        for (int j = 0; j < 64; j++) {
            int i = s * 64 + j;
            int b = sb[i];
            unsigned short off = hist[b * HROW + s];
            hist[b * HROW + s] = (unsigned short)(off + 1);
            pout[base[b] + off] = (b << 16) | i;
        }
    }
}

// ================= chunked attention (raw-q dots, column norm scale) ========
#define KHP 72
#define VP  72
#define OKH_HI 0
#define OKH_LO 18432
#define OV_HI  36864
#define OV_LO  55296
#define OMETA  73728
#define ORNORM 74240
#define OINVS  74752
#define SMEM_ATT3 75008

__global__ __launch_bounds__(128, 3)
void attention_kernel()
{
    extern __shared__ char smb[];
    __nv_bfloat16* kh_hi = (__nv_bfloat16*)(smb + OKH_HI);   // [128][72] raw q
    __nv_bfloat16* kh_lo = (__nv_bfloat16*)(smb + OKH_LO);
    __nv_bfloat16* v_hi  = (__nv_bfloat16*)(smb + OV_HI);    // [128][72]
    __nv_bfloat16* v_lo  = (__nv_bfloat16*)(smb + OV_LO);
    int*   pmeta = (int*)(smb + OMETA);                      // 128
    float* rnorm = (float*)(smb + ORNORM);                   // 128 (1/(||q||+eps))
    float* invs  = (float*)(smb + OINVS);                    // 64

    const int c = blockIdx.x, h = blockIdx.y, n = blockIdx.z;
    const int tid = threadIdx.x;
    const int pc = (c + CSs - 1) % CSs;

    {
        const int p = (tid < 64) ? (c * BSs + tid) : (pc * BSs + (tid - 64));
        pmeta[tid] = g_perm[((size_t)n * Hh + h) * Ll + p];
    }
    __syncthreads();

    const float* Qb = g_Q + (size_t)n * Tt * Dd + h * DHh;
    const float* Vb = g_V + (size_t)n * Tt * Dd + h * DHh;
    const int sub = tid >> 4, c4 = tid & 15;
#pragma unroll
    for (int i = 0; i < 16; i++) {
        const int row = i * 8 + sub;
        const int t = pmeta[row] & 4095;
        float4 qv = *(const float4*)&Qb[(size_t)t * Dd + c4 * 4];
        __nv_bfloat162 kh01 = __floats2bfloat162_rn(qv.x, qv.y);
        __nv_bfloat162 kl01 = __floats2bfloat162_rn(qv.x - __low2float(kh01), qv.y - __high2float(kh01));
        __nv_bfloat162 kh23 = __floats2bfloat162_rn(qv.z, qv.w);
        __nv_bfloat162 kl23 = __floats2bfloat162_rn(qv.z - __low2float(kh23), qv.w - __high2float(kh23));
        *(__nv_bfloat162*)&kh_hi[row * KHP + c4 * 4]     = kh01;
        *(__nv_bfloat162*)&kh_hi[row * KHP + c4 * 4 + 2] = kh23;
        *(__nv_bfloat162*)&kh_lo[row * KHP + c4 * 4]     = kl01;
        *(__nv_bfloat162*)&kh_lo[row * KHP + c4 * 4 + 2] = kl23;

        float4 vv = *(const float4*)&Vb[(size_t)t * Dd + c4 * 4];
        __nv_bfloat162 vh01 = __floats2bfloat162_rn(vv.x, vv.y);
        __nv_bfloat162 vl01 = __floats2bfloat162_rn(vv.x - __low2float(vh01), vv.y - __high2float(vh01));
        __nv_bfloat162 vh23 = __floats2bfloat162_rn(vv.z, vv.w);
        __nv_bfloat162 vl23 = __floats2bfloat162_rn(vv.z - __low2float(vh23), vv.w - __high2float(vh23));
        *(__nv_bfloat162*)&v_hi[row * VP + c4 * 4]     = vh01;
        *(__nv_bfloat162*)&v_hi[row * VP + c4 * 4 + 2] = vh23;
        *(__nv_bfloat162*)&v_lo[row * VP + c4 * 4]     = vl01;
        *(__nv_bfloat162*)&v_lo[row * VP + c4 * 4 + 2] = vl23;

        float ss = qv.x * qv.x + qv.y * qv.y + qv.z * qv.z + qv.w * qv.w;
        ss += __shfl_xor_sync(0xffffffffu, ss, 1);
        ss += __shfl_xor_sync(0xffffffffu, ss, 2);
        ss += __shfl_xor_sync(0xffffffffu, ss, 4);
        ss += __shfl_xor_sync(0xffffffffu, ss, 8);
        if (c4 == 0) rnorm[row] = 1.f / (sqrtf(ss) + 1e-6f);
    }
    __syncthreads();

    const int w = tid >> 5, lane = tid & 31;
    const int g = lane >> 2, tg = lane & 3;
    const int i0 = w * 16;

    const uint32_t khb_hi = smem_u32(kh_hi), khb_lo = smem_u32(kh_lo);
    const uint32_t vb_hi  = smem_u32(v_hi),  vb_lo  = smem_u32(v_lo);
    const uint32_t aoff = ((i0 + (lane & 15)) * KHP + 8 * (lane >> 4)) * 2;
    const uint32_t boff = (((lane & 7) + ((lane >= 16) ? 8 : 0)) * KHP + ((lane >> 3) & 1) * 8) * 2;
    const uint32_t voff = (((lane & 7) + 8 * ((lane >> 3) & 1)) * VP + 8 * (lane >> 4)) * 2;

    // ---- dots: D_ij = q_i . q_j (raw) ----
    float dc[16][4];
#pragma unroll
    for (int nt = 0; nt < 16; nt++)
#pragma unroll
        for (int k = 0; k < 4; k++) dc[nt][k] = 0.f;

#pragma unroll
    for (int k0 = 0; k0 < 64; k0 += 16) {
        uint32_t ah[4], al[4];
        LDSM4(ah[0], ah[1], ah[2], ah[3], khb_hi + aoff + k0 * 2);
        LDSM4(al[0], al[1], al[2], al[3], khb_lo + aoff + k0 * 2);
#pragma unroll
        for (int jt = 0; jt < 8; jt++) {
            uint32_t bh[4], bl[4];
            const uint32_t jb = (uint32_t)(jt * 16 * KHP + k0) * 2;
            LDSM4(bh[0], bh[1], bh[2], bh[3], khb_hi + boff + jb);
            LDSM4(bl[0], bl[1], bl[2], bl[3], khb_lo + boff + jb);
            MMA_BF16(dc[2 * jt], ah, bh);
            MMA_BF16(dc[2 * jt], ah, bl);
            MMA_BF16(dc[2 * jt], al, bh);
            MMA_BF16(dc[2 * jt + 1], ah, bh + 2);
            MMA_BF16(dc[2 * jt + 1], ah, bl + 2);
            MMA_BF16(dc[2 * jt + 1], al, bh + 2);
        }
    }

    // ---- masks + softmax; S_ij = D_ij * 0.125 * rnorm_j (column scale) ----
    const int ra = i0 + g, rb = i0 + g + 8;
    {
        const int pka = pmeta[ra], pkb = pmeta[rb];

#pragma unroll
        for (int nt = 0; nt < 16; nt++) {
            const int j0 = nt * 8 + 2 * tg;
            const int pj0 = pmeta[j0], pj1 = pmeta[j0 + 1];
            const float s0 = 0.125f * rnorm[j0];
            const float s1 = 0.125f * rnorm[j0 + 1];
            float x;
            x = dc[nt][0] * s0;
            if ((pka >> 16) != (pj0 >> 16)) x = -1e9f;
            if (((pka ^ pj0) & 4095) == 0)  x = -1e-5f;
            dc[nt][0] = x;
            x = dc[nt][1] * s1;
            if ((pka >> 16) != (pj1 >> 16)) x = -1e9f;
            if (((pka ^ pj1) & 4095) == 0)  x = -1e-5f;
            dc[nt][1] = x;
            x = dc[nt][2] * s0;
            if ((pkb >> 16) != (pj0 >> 16)) x = -1e9f;
            if (((pkb ^ pj0) & 4095) == 0)  x = -1e-5f;
            dc[nt][2] = x;
            x = dc[nt][3] * s1;
            if ((pkb >> 16) != (pj1 >> 16)) x = -1e9f;
            if (((pkb ^ pj1) & 4095) == 0)  x = -1e-5f;
            dc[nt][3] = x;
        }

        float ma = -1e30f, mb = -1e30f;
#pragma unroll
        for (int nt = 0; nt < 16; nt++) {
            ma = fmaxf(ma, fmaxf(dc[nt][0], dc[nt][1]));
            mb = fmaxf(mb, fmaxf(dc[nt][2], dc[nt][3]));
        }
        ma = fmaxf(ma, __shfl_xor_sync(0xffffffffu, ma, 1));
        ma = fmaxf(ma, __shfl_xor_sync(0xffffffffu, ma, 2));
        mb = fmaxf(mb, __shfl_xor_sync(0xffffffffu, mb, 1));
        mb = fmaxf(mb, __shfl_xor_sync(0xffffffffu, mb, 2));

        float sa = 0.f, sb2 = 0.f;
#pragma unroll
        for (int nt = 0; nt < 16; nt++) {
            dc[nt][0] = __expf(dc[nt][0] - ma); sa  += dc[nt][0];
            dc[nt][1] = __expf(dc[nt][1] - ma); sa  += dc[nt][1];
            dc[nt][2] = __expf(dc[nt][2] - mb); sb2 += dc[nt][2];
            dc[nt][3] = __expf(dc[nt][3] - mb); sb2 += dc[nt][3];
        }
        sa  += __shfl_xor_sync(0xffffffffu, sa, 1);
        sa  += __shfl_xor_sync(0xffffffffu, sa, 2);
        sb2 += __shfl_xor_sync(0xffffffffu, sb2, 1);
        sb2 += __shfl_xor_sync(0xffffffffu, sb2, 2);

        if (tg == 0) {
            const int nhbase = ((int)n * Hh + h) * NHh;
            const int ta = pka & 4095, rra = (pka >> 12) & 3;
            const int tb = pkb & 4095, rrb = (pkb >> 12) & 3;
            g_logits[((size_t)nhbase + rra) * Tt + ta] = ma + __logf(sa);
            g_logits[((size_t)nhbase + rrb) * Tt + tb] = mb + __logf(sb2);
            invs[ra] = 1.f / sa;
            invs[rb] = 1.f / sb2;
        }
        __syncwarp();
    }

    // ---- PV: O = P @ V, P fed straight from registers ----
    float oc[8][4];
#pragma unroll
    for (int nt = 0; nt < 8; nt++)
#pragma unroll
        for (int k = 0; k < 4; k++) oc[nt][k] = 0.f;

#pragma unroll
    for (int kc = 0; kc < 8; kc++) {
        uint32_t phi[4], plo[4];
        {
            __nv_bfloat162 hp, lp;
            hp = __floats2bfloat162_rn(dc[2 * kc][0], dc[2 * kc][1]);
            lp = __floats2bfloat162_rn(dc[2 * kc][0] - __low2float(hp),
                                       dc[2 * kc][1] - __high2float(hp));
            phi[0] = *(uint32_t*)&hp; plo[0] = *(uint32_t*)&lp;
            hp = __floats2bfloat162_rn(dc[2 * kc][2], dc[2 * kc][3]);
            lp = __floats2bfloat162_rn(dc[2 * kc][2] - __low2float(hp),
                                       dc[2 * kc][3] - __high2float(hp));
            phi[1] = *(uint32_t*)&hp; plo[1] = *(uint32_t*)&lp;
            hp = __floats2bfloat162_rn(dc[2 * kc + 1][0], dc[2 * kc + 1][1]);
            lp = __floats2bfloat162_rn(dc[2 * kc + 1][0] - __low2float(hp),
                                       dc[2 * kc + 1][1] - __high2float(hp));
            phi[2] = *(uint32_t*)&hp; plo[2] = *(uint32_t*)&lp;
            hp = __floats2bfloat162_rn(dc[2 * kc + 1][2], dc[2 * kc + 1][3]);
            lp = __floats2bfloat162_rn(dc[2 * kc + 1][2] - __low2float(hp),
                                       dc[2 * kc + 1][3] - __high2float(hp));
            phi[3] = *(uint32_t*)&hp; plo[3] = *(uint32_t*)&lp;
        }
#pragma unroll
        for (int ft = 0; ft < 4; ft++) {
            uint32_t vh[4], vl[4];
            const uint32_t vbo = (uint32_t)(kc * 16 * VP + ft * 16) * 2;
            LDSM4T(vh[0], vh[1], vh[2], vh[3], vb_hi + voff + vbo);
            LDSM4T(vl[0], vl[1], vl[2], vl[3], vb_lo + voff + vbo);
            MMA_BF16(oc[2 * ft], phi, vh);
            MMA_BF16(oc[2 * ft], phi, vl);
            MMA_BF16(oc[2 * ft], plo, vh);
            MMA_BF16(oc[2 * ft + 1], phi, vh + 2);
            MMA_BF16(oc[2 * ft + 1], phi, vl + 2);
            MMA_BF16(oc[2 * ft + 1], plo, vh + 2);
        }
    }

    {
        const int pka = pmeta[ra], pkb = pmeta[rb];
        const float iva = invs[ra], ivb = invs[rb];
        const size_t obase = ((size_t)n * Hh + h) * NHh;
        const size_t oa = ((obase + ((pka >> 12) & 3)) * Tt + (pka & 4095)) * DHh;
        const size_t ob = ((obase + ((pkb >> 12) & 3)) * Tt + (pkb & 4095)) * DHh;
#pragma unroll
        for (int ft = 0; ft < 4; ft++) {
            const int f0 = ft * 16 + 2 * tg;
            *(float2*)&g_O[oa + f0]     = make_float2(oc[2 * ft][0] * iva, oc[2 * ft][1] * iva);
            *(float2*)&g_O[ob + f0]     = make_float2(oc[2 * ft][2] * ivb, oc[2 * ft][3] * ivb);
            *(float2*)&g_O[oa + f0 + 8] = make_float2(oc[2 * ft + 1][0] * iva, oc[2 * ft + 1][1] * iva);
            *(float2*)&g_O[ob + f0 + 8] = make_float2(oc[2 * ft + 1][2] * ivb, oc[2 * ft + 1][3] * ivb);
        }
    }
}

// ================= round-combine softmax + LayerNorm (shfl reduce) ==========
__global__ void combine_ln_kernel(const float* __restrict__ gamma,
                                  const float* __restrict__ beta,
                                  float* __restrict__ out)
{
    const int bid = blockIdx.x;            // n*T + t
    const int n = bid >> 12, t = bid & 4095;
    const int tid = threadIdx.x;           // 128
    const int w = tid >> 5, lane = tid & 31;
    __shared__ float wsh[Hh][NHh];
    __shared__ float rs[4], rq[4];

    if (tid < Hh) {
        const int h = tid;
        float l[NHh];
        float m = -1e30f;
#pragma unroll
        for (int r = 0; r < NHh; r++) {
            l[r] = g_logits[(((size_t)n * Hh + h) * NHh + r) * Tt + t];
            m = fmaxf(m, l[r]);
        }
        float s = 0.f;
#pragma unroll
        for (int r = 0; r < NHh; r++) s += __expf(l[r] - m);
        const float lse = m + __logf(s);
#pragma unroll
        for (int r = 0; r < NHh; r++) wsh[h][r] = __expf(l[r] - lse);
    }
    __syncthreads();

    float vals[4];
    float lsum = 0.f, lsq = 0.f;
#pragma unroll
    for (int k2 = 0; k2 < 4; k2++) {
        const int d = tid + k2 * 128;
        const int h = d >> 6, f = d & 63;
        float a = 0.f;
#pragma unroll
        for (int r = 0; r < NHh; r++)
            a += wsh[h][r] * g_O[((((size_t)n * Hh + h) * NHh + r) * Tt + t) * DHh + f];
        vals[k2] = a;
        lsum += a;
        lsq  += a * a;
    }

#pragma unroll
    for (int o = 16; o; o >>= 1) {
        lsum += __shfl_xor_sync(0xffffffffu, lsum, o);
        lsq  += __shfl_xor_sync(0xffffffffu, lsq, o);
    }
    if (lane == 0) { rs[w] = lsum; rq[w] = lsq; }
    __syncthreads();
    const float ts = rs[0] + rs[1] + rs[2] + rs[3];
    const float tq = rq[0] + rq[1] + rq[2] + rq[3];
    const float mu = ts * (1.f / Dd);
    const float var = tq * (1.f / Dd) - mu * mu;
    const float rstd = rsqrtf(var + 1e-3f);

#pragma unroll
    for (int k2 = 0; k2 < 4; k2++) {
        const int d = tid + k2 * 128;
        out[(size_t)bid * Dd + d] = gamma[d] * (vals[k2] - mu) * rstd + beta[d];
    }
}

// ================= launch ===================================================
extern "C" void kernel_launch(void* const* d_in, const int* in_sizes, int n_in,
                              void* d_out, int out_size)
{
    const float* x     = (const float*)d_in[0];
    const float* W_Q   = (const float*)d_in[1];
    const float* b_Q   = (const float*)d_in[2];
    const float* W_V   = (const float*)d_in[3];
    const float* b_V   = (const float*)d_in[4];
    const float* gamma = (const float*)d_in[5];
    const float* beta  = (const float*)d_in[6];
    const float* rot   = (const float*)d_in[7];
    float* out = (float*)d_out;

    cudaFuncSetAttribute(attention_kernel,
                         cudaFuncAttributeMaxDynamicSharedMemorySize, SMEM_ATT3);
    cudaFuncSetAttribute(sort_kernel,
                         cudaFuncAttributeMaxDynamicSharedMemorySize, SMEM_SORT);
    cudaFuncSetAttribute(gemm_qv_kernel,
                         cudaFuncAttributeMaxDynamicSharedMemorySize, SMEM_MMA);
    cudaFuncSetAttribute(bucket_kernel,
                         cudaFuncAttributeMaxDynamicSharedMemorySize, SMEM_BKT);
    cudaFuncSetAttribute(fixup_kernel,
                         cudaFuncAttributeMaxDynamicSharedMemorySize, SMEM_FIX);

    reset_kernel<<<1, 1>>>();

    split_x_kernel<<<(Nb * Tt * Dd / 4) / 256, 256>>>(x);   // 8192 blocks
    split_w_kernel<<<dim3(16, 16, 2), dim3(32, 8)>>>(W_Q, W_V);

    dim3 gGrid(2, (Nb * Tt) / 128, 2);          // (2, 128, 2) -> Q and V
    gemm_qv_kernel<<<gGrid, 512, SMEM_MMA>>>(b_Q, b_V);

    dim3 bGrid(Tt / 128, Hh, Nb);               // (32, 8, 4)
    bucket_kernel<<<bGrid, 256, SMEM_BKT>>>(rot);

    fixup_kernel<<<dim3(32, 8), 256, SMEM_FIX>>>(x, W_Q, b_Q, rot);

    sort_kernel<<<Nb * Hh, 256, SMEM_SORT>>>(); // 32 blocks

    dim3 aGrid(CSs, Hh, Nb);                    // (256, 8, 4)
    attention_kernel<<<aGrid, 128, SMEM_ATT3>>>();

    combine_ln_kernel<<<Nb * Tt, 128>>>(gamma, beta, out);
}

// round 16
// speedup vs baseline: 1.2480x; 1.0032x over previous
#include <cuda_runtime.h>
#include <cuda_bf16.h>
#include <math.h>
#include <stdint.h>

// Problem constants
#define Nb   4          // batch
#define Tt   4096       // sequence length
#define Dd   512        // model dim
#define Hh   8          // heads
#define NHh  4          // hash rounds
#define BSs  64         // bucket chunk size
#define DHh  64         // head dim
#define NBb  64         // n_buckets
#define CSs  256        // chunks = NH * NB
#define Ll   16384      // NH * T

typedef unsigned long long u64;

// ---------------- scratch (device globals; no allocation allowed) ----------
__device__ float g_Q[(size_t)Nb * Tt * Dd];                 // 33.5 MB
__device__ float g_V[(size_t)Nb * Tt * Dd];                 // 33.5 MB
__device__ int   g_buckets[(size_t)Nb * Hh * NHh * Tt];     // 2 MB
__device__ int   g_perm[(size_t)Nb * Hh * Ll];              // 2 MB
__device__ float g_O[(size_t)Nb * Hh * NHh * Tt * DHh];     // 134 MB
__device__ float g_logits[(size_t)Nb * Hh * NHh * Tt];      // 2 MB
__device__ __nv_bfloat16 g_wthi[2][Dd * Dd];                // 1 MB (W^T hi: 0=Q,1=V)
__device__ __nv_bfloat16 g_wtlo[2][Dd * Dd];                // 1 MB
__device__ __nv_bfloat16 g_xhi[(size_t)Nb * Tt * Dd];       // 16 MB
__device__ __nv_bfloat16 g_xlo[(size_t)Nb * Tt * Dd];       // 16 MB
#define MAXF 131072
__device__ int g_nflags;
__device__ int g_flags[MAXF];                               // packed (n<<17)|(h<<14)|(r<<12)|t

// ================= helpers ==================================================
__device__ __forceinline__ uint32_t smem_u32(const void* p) {
    uint32_t a;
    asm("{ .reg .u64 t; cvta.to.shared.u64 t, %1; cvt.u32.u64 %0, t; }" : "=r"(a) : "l"(p));
    return a;
}
#define MMA_BF16(d, a, b)                                                     \
    asm volatile("mma.sync.aligned.m16n8k16.row.col.f32.bf16.bf16.f32 "       \
        "{%0,%1,%2,%3}, {%4,%5,%6,%7}, {%8,%9}, {%0,%1,%2,%3};"               \
        : "+f"((d)[0]), "+f"((d)[1]), "+f"((d)[2]), "+f"((d)[3])              \
        : "r"((a)[0]), "r"((a)[1]), "r"((a)[2]), "r"((a)[3]),                 \
          "r"((b)[0]), "r"((b)[1]))
#define LDSM4(r0, r1, r2, r3, addr)                                           \
    asm volatile("ldmatrix.sync.aligned.m8n8.x4.shared.b16 {%0,%1,%2,%3}, [%4];" \
        : "=r"(r0), "=r"(r1), "=r"(r2), "=r"(r3) : "r"(addr))
#define LDSM4T(r0, r1, r2, r3, addr)                                          \
    asm volatile("ldmatrix.sync.aligned.m8n8.x4.trans.shared.b16 {%0,%1,%2,%3}, [%4];" \
        : "=r"(r0), "=r"(r1), "=r"(r2), "=r"(r3) : "r"(addr))
#define FFMA2(d, a, b) \
    asm("fma.rn.f32x2 %0, %1, %2, %0;" : "+l"(d) : "l"(a), "l"(b))
#define PACK2(d, x, y) \
    asm("mov.b64 %0, {%1, %2};" : "=l"(d) : "f"(x), "f"(y))
#define UNPACK2(x, y, d) \
    asm("mov.b64 {%0, %1}, %2;" : "=f"(x), "=f"(y) : "l"(d))

// ================= reset ====================================================
__global__ void reset_kernel() { g_nflags = 0; }

// ================= split x -> bf16 hi/lo ====================================
__global__ void split_x_kernel(const float* __restrict__ x)
{
    const size_t i = (size_t)blockIdx.x * 256 + threadIdx.x;   // per float4
    float4 v = ((const float4*)x)[i];
    __nv_bfloat162 h01 = __floats2bfloat162_rn(v.x, v.y);
    __nv_bfloat162 h23 = __floats2bfloat162_rn(v.z, v.w);
    __nv_bfloat162 l01 = __floats2bfloat162_rn(v.x - __low2float(h01), v.y - __high2float(h01));
    __nv_bfloat162 l23 = __floats2bfloat162_rn(v.z - __low2float(h23), v.w - __high2float(h23));
    ((__nv_bfloat162*)g_xhi)[i * 2]     = h01;
    ((__nv_bfloat162*)g_xhi)[i * 2 + 1] = h23;
    ((__nv_bfloat162*)g_xlo)[i * 2]     = l01;
    ((__nv_bfloat162*)g_xlo)[i * 2 + 1] = l23;
}

// ================= split + transpose W_Q / W_V ==============================
__global__ void split_w_kernel(const float* __restrict__ WQ, const float* __restrict__ WV)
{
    __shared__ float tile[32][33];
    const float* W = blockIdx.z ? WV : WQ;
    const int bx = blockIdx.x * 32;   // n block
    const int by = blockIdx.y * 32;   // k block
    const int tx = threadIdx.x, ty = threadIdx.y;   // 32 x 8
#pragma unroll
    for (int r = 0; r < 32; r += 8)
        tile[ty + r][tx] = W[(size_t)(by + ty + r) * Dd + bx + tx];
    __syncthreads();
#pragma unroll
    for (int r = 0; r < 32; r += 8) {
        float val = tile[tx][ty + r];
        __nv_bfloat16 hi = __float2bfloat16(val);
        __nv_bfloat16 lo = __float2bfloat16(val - __bfloat162float(hi));
        size_t o = (size_t)(bx + ty + r) * Dd + by + tx;
        g_wthi[blockIdx.z][o] = hi;
        g_wtlo[blockIdx.z][o] = lo;
    }
}

// ================= Q/V GEMM: bf16 mma, ldmatrix, dbl-buffer, MMA sweeps =====
#define PITCH 40
#define A_HI  0
#define A_LO  (128 * PITCH)
#define B_HI  (2 * 128 * PITCH)
#define B_LO  (2 * 128 * PITCH + 256 * PITCH)
#define BUFH  (2 * 128 * PITCH + 2 * 256 * PITCH)      // halves per buffer (30720)
#define BUFB  (BUFH * 2)                               // bytes per buffer (61440)
#define SMEM_MMA (2 * BUFB)
#define ALO_B  (128 * PITCH * 2)
#define BHI_B  (2 * 128 * PITCH * 2)
#define BLO_D  (256 * PITCH * 2)

__global__ __launch_bounds__(512, 1)
void gemm_qv_kernel(const float* __restrict__ bQ, const float* __restrict__ bV)
{
    extern __shared__ uint16_t sm16[];
    const int tid = threadIdx.x;
    const int wid = tid >> 5, lane = tid & 31;
    const int g = lane >> 2, tg = lane & 3;
    const int wm = wid & 3, wn = wid >> 2;
    const int mbase = blockIdx.y * 128;
    const int ncol0 = blockIdx.x * 256;
    const int which = blockIdx.z;                 // 0 = Q, 1 = V
    const __nv_bfloat16* Whi = g_wthi[which];
    const __nv_bfloat16* Wlo = g_wtlo[which];
    const float* bias = which ? bV : bQ;
    float* C = which ? g_V : g_Q;

    const uint32_t smbase = smem_u32(sm16);
    const uint32_t aoff0 = ((wm * 32 + (lane & 15)) * PITCH + 8 * (lane >> 4)) * 2;
    const uint32_t boff0 = (((lane & 7) + ((lane >= 16) ? 8 : 0)) * PITCH
                            + ((lane >> 3) & 1) * 8) * 2;

    // precomputed staging indices (per thread)
    const __nv_bfloat16* asrc[2]; uint32_t adst[2];
#pragma unroll
    for (int i = 0; i < 2; i++) {
        const int e = tid + i * 512;              // [0,1024)
        const int split = e >> 9;
        const int r = (e >> 2) & 127;
        const int k8 = e & 3;
        asrc[i] = (split ? g_xlo : g_xhi) + (size_t)(mbase + r) * Dd + k8 * 8;
        adst[i] = (split ? A_LO : A_HI) + r * PITCH + k8 * 8;
    }
    const __nv_bfloat16* bsrc[4]; uint32_t bdst[4];
#pragma unroll
    for (int i = 0; i < 4; i++) {
        const int e = tid + i * 512;              // [0,2048)
        const int split = e >> 10;
        const int r = (e >> 2) & 255;
        const int k8 = e & 3;
        bsrc[i] = (split ? Wlo : Whi) + (size_t)(ncol0 + r) * Dd + k8 * 8;
        bdst[i] = (split ? B_LO : B_HI) + r * PITCH + k8 * 8;
    }

    float acc[2][8][4];
#pragma unroll
    for (int i = 0; i < 2; i++)
#pragma unroll
        for (int j = 0; j < 8; j++)
#pragma unroll
            for (int k = 0; k < 4; k++) acc[i][j][k] = 0.f;

    uint4 pa[2], pb[4];
    // prologue: load + store slab 0 into buffer 0
#pragma unroll
    for (int i = 0; i < 2; i++) pa[i] = *(const uint4*)(asrc[i]);
#pragma unroll
    for (int i = 0; i < 4; i++) pb[i] = *(const uint4*)(bsrc[i]);
#pragma unroll
    for (int i = 0; i < 2; i++) *(uint4*)(sm16 + adst[i]) = pa[i];
#pragma unroll
    for (int i = 0; i < 4; i++) *(uint4*)(sm16 + bdst[i]) = pb[i];
    __syncthreads();

    for (int slab = 0; slab < 16; slab++) {
        const uint32_t curB = (uint32_t)(slab & 1) * BUFB;
        const uint32_t nxtH = (uint32_t)((slab & 1) ^ 1) * BUFH;

        // prefetch next slab into registers (hidden behind MMA work)
        if (slab < 15) {
            const int kt = (slab + 1) * 32;
#pragma unroll
            for (int i = 0; i < 2; i++) pa[i] = *(const uint4*)(asrc[i] + kt);
#pragma unroll
            for (int i = 0; i < 4; i++) pb[i] = *(const uint4*)(bsrc[i] + kt);
        }

#pragma unroll
        for (int kk = 0; kk < 32; kk += 16) {
            uint32_t ah[2][4], al[2][4];
#pragma unroll
            for (int mt = 0; mt < 2; mt++) {
                const uint32_t aa = smbase + curB + aoff0
                    + (uint32_t)(mt * 16 * PITCH + kk) * 2;
                LDSM4(ah[mt][0], ah[mt][1], ah[mt][2], ah[mt][3], aa);
                LDSM4(al[mt][0], al[mt][1], al[mt][2], al[mt][3], aa + ALO_B);
            }
#pragma unroll
            for (int ng = 0; ng < 2; ng++) {
                uint32_t bh[2][4], bl[2][4];
#pragma unroll
                for (int hh = 0; hh < 2; hh++) {
                    const uint32_t bb = smbase + curB + BHI_B + boff0
                        + (uint32_t)((wn * 64 + ng * 32 + hh * 16) * PITCH + kk) * 2;
                    LDSM4(bh[hh][0], bh[hh][1], bh[hh][2], bh[hh][3], bb);
                    LDSM4(bl[hh][0], bl[hh][1], bl[hh][2], bl[hh][3], bb + BLO_D);
                }
                // MMA sweeps: per-acc order preserved (hh, hl, lh), chains 8 apart
#pragma unroll
                for (int mt = 0; mt < 2; mt++)
#pragma unroll
                    for (int q = 0; q < 4; q++)
                        MMA_BF16(acc[mt][ng * 4 + q], ah[mt],
                                 bh[q >> 1] + (q & 1) * 2);
#pragma unroll
                for (int mt = 0; mt < 2; mt++)
#pragma unroll
                    for (int q = 0; q < 4; q++)
                        MMA_BF16(acc[mt][ng * 4 + q], ah[mt],
                                 bl[q >> 1] + (q & 1) * 2);
#pragma unroll
                for (int mt = 0; mt < 2; mt++)
#pragma unroll
                    for (int q = 0; q < 4; q++)
                        MMA_BF16(acc[mt][ng * 4 + q], al[mt],
                                 bh[q >> 1] + (q & 1) * 2);
            }
        }
        // store next slab into the other buffer (no barrier before: disjoint)
        if (slab < 15) {
#pragma unroll
            for (int i = 0; i < 2; i++) *(uint4*)(sm16 + nxtH + adst[i]) = pa[i];
#pragma unroll
            for (int i = 0; i < 4; i++) *(uint4*)(sm16 + nxtH + bdst[i]) = pb[i];
            __syncthreads();
        }
    }

#pragma unroll
    for (int mt = 0; mt < 2; mt++) {
        const int r0 = mbase + wm * 32 + mt * 16 + g;
#pragma unroll
        for (int nt = 0; nt < 8; nt++) {
            const int col = ncol0 + wn * 64 + nt * 8 + 2 * tg;
            float2 b2 = *(const float2*)&bias[col];
            float2 o0, o1;
            o0.x = acc[mt][nt][0] + b2.x;
            o0.y = acc[mt][nt][1] + b2.y;
            o1.x = acc[mt][nt][2] + b2.x;
            o1.y = acc[mt][nt][3] + b2.y;
            *(float2*)&C[(size_t)r0 * Dd + col] = o0;
            *(float2*)&C[(size_t)(r0 + 8) * Dd + col] = o1;
        }
    }
}

// ================= bucket kernel: GEMM (FFMA2) + argmax + margin flag =======
#define AsP 68
#define BsP 132
#define SMEM_BKT ((128 * AsP + 64 * BsP) * 4)

__global__ __launch_bounds__(256, 2)
void bucket_kernel(const float* __restrict__ rot)
{
    extern __shared__ float smf[];
    float* As = smf;                  // [128 m][68 k]
    float* Bs = smf + 128 * AsP;      // [64 k][132 c]

    const int h = blockIdx.y, n = blockIdx.z;
    const int tid = threadIdx.x;      // 256
    const int tx = tid & 15, ty = tid >> 4;
    const int t0 = blockIdx.x * 128;

    const float* Qb = g_Q + ((size_t)n * Tt + t0) * Dd + h * DHh;
#pragma unroll
    for (int l = 0; l < 8; l++) {
        const int e = tid + l * 256;
        const int r = e >> 4, c4 = e & 15;
        *(float4*)&As[r * AsP + c4 * 4] = *(const float4*)&Qb[(size_t)r * Dd + c4 * 4];
    }
    const float* Rb = rot + (size_t)h * 8192;
#pragma unroll
    for (int l = 0; l < 8; l++) {
        const int e = tid + l * 256;
        const int kr = e >> 5, c4 = e & 31;
        *(float4*)&Bs[kr * BsP + c4 * 4] = *(const float4*)&Rb[kr * 128 + c4 * 4];
    }
    __syncthreads();

    u64 acc2[8][4];
#pragma unroll
    for (int i = 0; i < 8; i++)
#pragma unroll
        for (int j = 0; j < 4; j++) acc2[i][j] = 0ull;

#pragma unroll 4
    for (int k = 0; k < 64; k++) {
        float a[8];
#pragma unroll
        for (int i = 0; i < 8; i++) a[i] = As[(ty * 8 + i) * AsP + k];
        u64 a2[8];
#pragma unroll
        for (int i = 0; i < 8; i++) PACK2(a2[i], a[i], a[i]);
        ulonglong2 bp0 = *(const ulonglong2*)&Bs[k * BsP + tx * 8];
        ulonglong2 bp1 = *(const ulonglong2*)&Bs[k * BsP + tx * 8 + 4];
        u64 b2[4] = {bp0.x, bp0.y, bp1.x, bp1.y};
#pragma unroll
        for (int i = 0; i < 8; i++)
#pragma unroll
            for (int j = 0; j < 4; j++) FFMA2(acc2[i][j], a2[i], b2[j]);
    }

    const int ig = (tx & 3) * 8;
    const int r = tx >> 2;
#pragma unroll
    for (int i = 0; i < 8; i++) {
        float acc[8];
#pragma unroll
        for (int jp = 0; jp < 4; jp++)
            UNPACK2(acc[2 * jp], acc[2 * jp + 1], acc2[i][jp]);

        float t1 = acc[0]; int i1 = ig; float t2 = -3.4e38f;
#pragma unroll
        for (int j = 1; j < 8; j++) {
            float v = acc[j];
            if (v > t1) { t2 = t1; t1 = v; i1 = ig + j; }
            else t2 = fmaxf(t2, v);
        }
#pragma unroll
        for (int j = 0; j < 8; j++) {
            float v = -acc[j];
            if (v > t1) { t2 = t1; t1 = v; i1 = 32 + ig + j; }
            else t2 = fmaxf(t2, v);
        }
#pragma unroll
        for (int o = 1; o <= 2; o <<= 1) {
            float o1 = __shfl_xor_sync(0xffffffffu, t1, o);
            int   oi = __shfl_xor_sync(0xffffffffu, i1, o);
            float o2 = __shfl_xor_sync(0xffffffffu, t2, o);
            if (o1 > t1 || (o1 == t1 && oi < i1)) {
                t2 = fmaxf(t1, o2); t1 = o1; i1 = oi;
            } else {
                t2 = fmaxf(t2, o1);
            }
        }

        if ((tx & 3) == 0) {
            const int t = t0 + ty * 8 + i;
            g_buckets[(((size_t)n * Hh + h) * NHh + r) * Tt + t] = i1 + r * NBb;
            if (t1 - t2 < 1e-4f * t1 + 1e-4f) {
                int p = atomicAdd(&g_nflags, 1);
                if (p < MAXF)
                    g_flags[p] = (n << 17) | (h << 14) | (r << 12) | t;
            }
        }
    }
}

// ================= fix-up: exact recompute of flagged decisions =============
#define FCAP 6144
#define OF_LST 0
#define OF_XB  (FCAP * 4)
#define OF_QB  (FCAP * 4 + 8 * 4 * 512 * 4)
#define SMEM_FIX (FCAP * 4 + 8 * 4 * 512 * 4 + 8 * 4 * 64 * 4)

__global__ __launch_bounds__(256)
void fixup_kernel(const float* __restrict__ x, const float* __restrict__ WQ,
                  const float* __restrict__ bQ, const float* __restrict__ rot)
{
    extern __shared__ char fsm[];
    int*   lst = (int*)(fsm + OF_LST);
    float* xb  = (float*)(fsm + OF_XB);    // [8 warps][4 flags][512]
    float* qb  = (float*)(fsm + OF_QB);    // [8 warps][4 flags][64]
    __shared__ int lcnt;

    const int bin = blockIdx.x;            // n*8 + h
    const int slice = blockIdx.y;          // 0..7
    const int n = bin >> 3, h = bin & 7;
    const int tid = threadIdx.x;
    const int w = tid >> 5, lane = tid & 31;

    if (tid == 0) lcnt = 0;
    __syncthreads();

    int count = g_nflags;
    if (count > MAXF) count = MAXF;
    for (int e = tid; e < count; e += 256) {
        const int pk = g_flags[e];
        if (((pk >> 14) & 31) == bin && (e & 7) == slice) {
            int p = atomicAdd(&lcnt, 1);
            if (p < FCAP) lst[p] = pk;
        }
    }
    __syncthreads();
    int nf = lcnt;
    if (nf > FCAP) nf = FCAP;

    float* xw = xb + w * 4 * 512;
    float* qw = qb + w * 4 * 64;

    for (int s = w * 4; s < nf; s += 32) {
        const int nn = min(4, nf - s);
        for (int ff = 0; ff < nn; ff++) {
            const int t = lst[s + ff] & 4095;
            const float* xr = x + ((size_t)n * Tt + t) * Dd;
            for (int e4 = lane; e4 < 128; e4 += 32)
                *(float4*)&xw[ff * 512 + e4 * 4] = *(const float4*)&xr[e4 * 4];
        }
        __syncwarp();

        float acc[4][2];
#pragma unroll
        for (int ff = 0; ff < 4; ff++) { acc[ff][0] = 0.f; acc[ff][1] = 0.f; }
        const float* Wc = WQ + h * 64;
        for (int k = 0; k < Dd; k++) {
            const float w0 = Wc[(size_t)k * Dd + lane];
            const float w1 = Wc[(size_t)k * Dd + lane + 32];
#pragma unroll
            for (int ff = 0; ff < 4; ff++) {
                acc[ff][0] += xw[ff * 512 + k] * w0;
                acc[ff][1] += xw[ff * 512 + k] * w1;
            }
        }
        const float b0 = bQ[h * 64 + lane], b1 = bQ[h * 64 + lane + 32];
        for (int ff = 0; ff < nn; ff++) {
            qw[ff * 64 + lane]      = acc[ff][0] + b0;
            qw[ff * 64 + lane + 32] = acc[ff][1] + b1;
        }
        __syncwarp();

        for (int ff = 0; ff < nn; ff++) {
            const int pk = lst[s + ff];
            const int t = pk & 4095, r = (pk >> 12) & 3;
            const float* rp = rot + (size_t)h * 8192 + r * 32 + lane;
            float v = 0.f;
#pragma unroll 8
            for (int f = 0; f < 64; f++)
                v += qw[ff * 64 + f] * rp[f * 128];
            float bv; int bi;
            if (-v > v) { bv = -v; bi = 32 + lane; }
            else        { bv = v;  bi = lane; }
#pragma unroll
            for (int o = 16; o; o >>= 1) {
                float ov = __shfl_xor_sync(0xffffffffu, bv, o);
                int   oi = __shfl_xor_sync(0xffffffffu, bi, o);
                if (ov > bv || (ov == bv && oi < bi)) { bv = ov; bi = oi; }
            }
            if (lane == 0)
                g_buckets[(((size_t)n * Hh + h) * NHh + r) * Tt + t] = bi + r * NBb;
        }
        __syncwarp();
    }
}

// ================= segmented stable counting sort per (n,h) =================
#define HROW 258
#define SMEM_SORT (Ll + 256 * HROW * 2 + 256 * 4)
__global__ void sort_kernel()
{
    extern __shared__ char smraw[];
    unsigned char*  sb   = (unsigned char*)smraw;
    unsigned short* hist = (unsigned short*)(smraw + Ll);
    int*            base = (int*)(smraw + Ll + 256 * HROW * 2);
    __shared__ int tot[256];

    const int nh = blockIdx.x;
    const int tid = threadIdx.x;

    for (int e = tid; e < 256 * HROW / 2; e += 256)
        ((unsigned int*)hist)[e] = 0;
    __syncthreads();

    const int* bptr = g_buckets + (size_t)nh * Ll;
    for (int e = tid; e < Ll; e += 256)
        sb[e] = (unsigned char)bptr[e];
    __syncthreads();

    {
        const int s = tid;
#pragma unroll 4
        for (int j = 0; j < 64; j++) {
            int b = sb[s * 64 + j];
            hist[b * HROW + s]++;
        }
    }
    __syncthreads();

    {
        const unsigned short* row = &hist[tid * HROW];
        int sum = 0;
#pragma unroll 8
        for (int s2 = 0; s2 < 256; s2++) sum += row[s2];
        tot[tid] = sum;
    }
    __syncthreads();
    if (tid == 0) {
        int run = 0;
        for (int b = 0; b < 256; b++) { base[b] = run; run += tot[b]; }
    }
    __syncthreads();

    {
        unsigned short* row = &hist[tid * HROW];
        unsigned short run = 0;
        for (int s2 = 0; s2 < 256; s2++) {
            unsigned short v = row[s2];
            row[s2] = run;
            run = (unsigned short)(run + v);
        }
    }
    __syncthreads();

    {
        const int s = tid;
        int* pout = g_perm + (size_t)nh * Ll;
        for (int j = 0; j < 64; j++) {
            int i = s * 64 + j;
            int b = sb[i];
            unsigned short off = hist[b * HROW + s];
            hist[b * HROW + s] = (unsigned short)(off + 1);
            pout[base[b] + off] = (b << 16) | i;
        }
    }
}

// ================= chunked attention (raw-q dots, column norm scale) ========
#define KHP 72
#define VP  72
#define OKH_HI 0
#define OKH_LO 18432
#define OV_HI  36864
#define OV_LO  55296
#define OMETA  73728
#define ORNORM 74240
#define OINVS  74752
#define SMEM_ATT3 75008

__global__ __launch_bounds__(128, 3)
void attention_kernel()
{
    extern __shared__ char smb[];
    __nv_bfloat16* kh_hi = (__nv_bfloat16*)(smb + OKH_HI);   // [128][72] raw q
    __nv_bfloat16* kh_lo = (__nv_bfloat16*)(smb + OKH_LO);
    __nv_bfloat16* v_hi  = (__nv_bfloat16*)(smb + OV_HI);    // [128][72]
    __nv_bfloat16* v_lo  = (__nv_bfloat16*)(smb + OV_LO);
    int*   pmeta = (int*)(smb + OMETA);                      // 128
    float* rnorm = (float*)(smb + ORNORM);                   // 128 (1/(||q||+eps))
    float* invs  = (float*)(smb + OINVS);                    // 64

    const int c = blockIdx.x, h = blockIdx.y, n = blockIdx.z;
    const int tid = threadIdx.x;
    const int pc = (c + CSs - 1) % CSs;

    {
        const int p = (tid < 64) ? (c * BSs + tid) : (pc * BSs + (tid - 64));
        pmeta[tid] = g_perm[((size_t)n * Hh + h) * Ll + p];
    }
    __syncthreads();

    const float* Qb = g_Q + (size_t)n * Tt * Dd + h * DHh;
    const float* Vb = g_V + (size_t)n * Tt * Dd + h * DHh;
    const int sub = tid >> 4, c4 = tid & 15;
#pragma unroll
    for (int i = 0; i < 16; i++) {
        const int row = i * 8 + sub;
        const int t = pmeta[row] & 4095;
        float4 qv = *(const float4*)&Qb[(size_t)t * Dd + c4 * 4];
        __nv_bfloat162 kh01 = __floats2bfloat162_rn(qv.x, qv.y);
        __nv_bfloat162 kl01 = __floats2bfloat162_rn(qv.x - __low2float(kh01), qv.y - __high2float(kh01));
        __nv_bfloat162 kh23 = __floats2bfloat162_rn(qv.z, qv.w);
        __nv_bfloat162 kl23 = __floats2bfloat162_rn(qv.z - __low2float(kh23), qv.w - __high2float(kh23));
        *(__nv_bfloat162*)&kh_hi[row * KHP + c4 * 4]     = kh01;
        *(__nv_bfloat162*)&kh_hi[row * KHP + c4 * 4 + 2] = kh23;
        *(__nv_bfloat162*)&kh_lo[row * KHP + c4 * 4]     = kl01;
        *(__nv_bfloat162*)&kh_lo[row * KHP + c4 * 4 + 2] = kl23;

        float4 vv = *(const float4*)&Vb[(size_t)t * Dd + c4 * 4];
        __nv_bfloat162 vh01 = __floats2bfloat162_rn(vv.x, vv.y);
        __nv_bfloat162 vl01 = __floats2bfloat162_rn(vv.x - __low2float(vh01), vv.y - __high2float(vh01));
        __nv_bfloat162 vh23 = __floats2bfloat162_rn(vv.z, vv.w);
        __nv_bfloat162 vl23 = __floats2bfloat162_rn(vv.z - __low2float(vh23), vv.w - __high2float(vh23));
        *(__nv_bfloat162*)&v_hi[row * VP + c4 * 4]     = vh01;
        *(__nv_bfloat162*)&v_hi[row * VP + c4 * 4 + 2] = vh23;
        *(__nv_bfloat162*)&v_lo[row * VP + c4 * 4]     = vl01;
        *(__nv_bfloat162*)&v_lo[row * VP + c4 * 4 + 2] = vl23;

        float ss = qv.x * qv.x + qv.y * qv.y + qv.z * qv.z + qv.w * qv.w;
        ss += __shfl_xor_sync(0xffffffffu, ss, 1);
        ss += __shfl_xor_sync(0xffffffffu, ss, 2);
        ss += __shfl_xor_sync(0xffffffffu, ss, 4);
        ss += __shfl_xor_sync(0xffffffffu, ss, 8);
        if (c4 == 0) rnorm[row] = 1.f / (sqrtf(ss) + 1e-6f);
    }
    __syncthreads();

    const int w = tid >> 5, lane = tid & 31;
    const int g = lane >> 2, tg = lane & 3;
    const int i0 = w * 16;

    const uint32_t khb_hi = smem_u32(kh_hi), khb_lo = smem_u32(kh_lo);
    const uint32_t vb_hi  = smem_u32(v_hi),  vb_lo  = smem_u32(v_lo);
    const uint32_t aoff = ((i0 + (lane & 15)) * KHP + 8 * (lane >> 4)) * 2;
    const uint32_t boff = (((lane & 7) + ((lane >= 16) ? 8 : 0)) * KHP + ((lane >> 3) & 1) * 8) * 2;
    const uint32_t voff = (((lane & 7) + 8 * ((lane >> 3) & 1)) * VP + 8 * (lane >> 4)) * 2;

    // ---- dots: D_ij = q_i . q_j (raw) ----
    float dc[16][4];
#pragma unroll
    for (int nt = 0; nt < 16; nt++)
#pragma unroll
        for (int k = 0; k < 4; k++) dc[nt][k] = 0.f;

#pragma unroll
    for (int k0 = 0; k0 < 64; k0 += 16) {
        uint32_t ah[4], al[4];
        LDSM4(ah[0], ah[1], ah[2], ah[3], khb_hi + aoff + k0 * 2);
        LDSM4(al[0], al[1], al[2], al[3], khb_lo + aoff + k0 * 2);
#pragma unroll
        for (int jt = 0; jt < 8; jt++) {
            uint32_t bh[4], bl[4];
            const uint32_t jb = (uint32_t)(jt * 16 * KHP + k0) * 2;
            LDSM4(bh[0], bh[1], bh[2], bh[3], khb_hi + boff + jb);
            LDSM4(bl[0], bl[1], bl[2], bl[3], khb_lo + boff + jb);
            MMA_BF16(dc[2 * jt], ah, bh);
            MMA_BF16(dc[2 * jt], ah, bl);
            MMA_BF16(dc[2 * jt], al, bh);
            MMA_BF16(dc[2 * jt + 1], ah, bh + 2);
            MMA_BF16(dc[2 * jt + 1], ah, bl + 2);
            MMA_BF16(dc[2 * jt + 1], al, bh + 2);
        }
    }

    // ---- masks + softmax; S_ij = D_ij * 0.125 * rnorm_j (column scale) ----
    const int ra = i0 + g, rb = i0 + g + 8;
    {
        const int pka = pmeta[ra], pkb = pmeta[rb];

#pragma unroll
        for (int nt = 0; nt < 16; nt++) {
            const int j0 = nt * 8 + 2 * tg;
            const int pj0 = pmeta[j0], pj1 = pmeta[j0 + 1];
            const float s0 = 0.125f * rnorm[j0];
            const float s1 = 0.125f * rnorm[j0 + 1];
            float x;
            x = dc[nt][0] * s0;
            if ((pka >> 16) != (pj0 >> 16)) x = -1e9f;
            if (((pka ^ pj0) & 4095) == 0)  x = -1e-5f;
            dc[nt][0] = x;
            x = dc[nt][1] * s1;
            if ((pka >> 16) != (pj1 >> 16)) x = -1e9f;
            if (((pka ^ pj1) & 4095) == 0)  x = -1e-5f;
            dc[nt][1] = x;
            x = dc[nt][2] * s0;
            if ((pkb >> 16) != (pj0 >> 16)) x = -1e9f;
            if (((pkb ^ pj0) & 4095) == 0)  x = -1e-5f;
            dc[nt][2] = x;
            x = dc[nt][3] * s1;
            if ((pkb >> 16) != (pj1 >> 16)) x = -1e9f;
            if (((pkb ^ pj1) & 4095) == 0)  x = -1e-5f;
            dc[nt][3] = x;
        }

        float ma = -1e30f, mb = -1e30f;
#pragma unroll
        for (int nt = 0; nt < 16; nt++) {
            ma = fmaxf(ma, fmaxf(dc[nt][0], dc[nt][1]));
            mb = fmaxf(mb, fmaxf(dc[nt][2], dc[nt][3]));
        }
        ma = fmaxf(ma, __shfl_xor_sync(0xffffffffu, ma, 1));
        ma = fmaxf(ma, __shfl_xor_sync(0xffffffffu, ma, 2));
        mb = fmaxf(mb, __shfl_xor_sync(0xffffffffu, mb, 1));
        mb = fmaxf(mb, __shfl_xor_sync(0xffffffffu, mb, 2));

        float sa = 0.f, sb2 = 0.f;
#pragma unroll
        for (int nt = 0; nt < 16; nt++) {
            dc[nt][0] = __expf(dc[nt][0] - ma); sa  += dc[nt][0];
            dc[nt][1] = __expf(dc[nt][1] - ma); sa  += dc[nt][1];
            dc[nt][2] = __expf(dc[nt][2] - mb); sb2 += dc[nt][2];
            dc[nt][3] = __expf(dc[nt][3] - mb); sb2 += dc[nt][3];
        }
        sa  += __shfl_xor_sync(0xffffffffu, sa, 1);
        sa  += __shfl_xor_sync(0xffffffffu, sa, 2);
        sb2 += __shfl_xor_sync(0xffffffffu, sb2, 1);
        sb2 += __shfl_xor_sync(0xffffffffu, sb2, 2);

        if (tg == 0) {
            const int nhbase = ((int)n * Hh + h) * NHh;
            const int ta = pka & 4095, rra = (pka >> 12) & 3;
            const int tb = pkb & 4095, rrb = (pkb >> 12) & 3;
            g_logits[((size_t)nhbase + rra) * Tt + ta] = ma + __logf(sa);
            g_logits[((size_t)nhbase + rrb) * Tt + tb] = mb + __logf(sb2);
            invs[ra] = 1.f / sa;
            invs[rb] = 1.f / sb2;
        }
        __syncwarp();
    }

    // ---- PV: O = P @ V, P fed straight from registers ----
    float oc[8][4];
#pragma unroll
    for (int nt = 0; nt < 8; nt++)
#pragma unroll
        for (int k = 0; k < 4; k++) oc[nt][k] = 0.f;

#pragma unroll
    for (int kc = 0; kc < 8; kc++) {
        uint32_t phi[4], plo[4];
        {
            __nv_bfloat162 hp, lp;
            hp = __floats2bfloat162_rn(dc[2 * kc][0], dc[2 * kc][1]);
            lp = __floats2bfloat162_rn(dc[2 * kc][0] - __low2float(hp),
                                       dc[2 * kc][1] - __high2float(hp));
            phi[0] = *(uint32_t*)&hp; plo[0] = *(uint32_t*)&lp;
            hp = __floats2bfloat162_rn(dc[2 * kc][2], dc[2 * kc][3]);
            lp = __floats2bfloat162_rn(dc[2 * kc][2] - __low2float(hp),
                                       dc[2 * kc][3] - __high2float(hp));
            phi[1] = *(uint32_t*)&hp; plo[1] = *(uint32_t*)&lp;
            hp = __floats2bfloat162_rn(dc[2 * kc + 1][0], dc[2 * kc + 1][1]);
            lp = __floats2bfloat162_rn(dc[2 * kc + 1][0] - __low2float(hp),
                                       dc[2 * kc + 1][1] - __high2float(hp));
            phi[2] = *(uint32_t*)&hp; plo[2] = *(uint32_t*)&lp;
            hp = __floats2bfloat162_rn(dc[2 * kc + 1][2], dc[2 * kc + 1][3]);
            lp = __floats2bfloat162_rn(dc[2 * kc + 1][2] - __low2float(hp),
                                       dc[2 * kc + 1][3] - __high2float(hp));
            phi[3] = *(uint32_t*)&hp; plo[3] = *(uint32_t*)&lp;
        }
#pragma unroll
        for (int ft = 0; ft < 4; ft++) {
            uint32_t vh[4], vl[4];
            const uint32_t vbo = (uint32_t)(kc * 16 * VP + ft * 16) * 2;
            LDSM4T(vh[0], vh[1], vh[2], vh[3], vb_hi + voff + vbo);
            LDSM4T(vl[0], vl[1], vl[2], vl[3], vb_lo + voff + vbo);
            MMA_BF16(oc[2 * ft], phi, vh);
            MMA_BF16(oc[2 * ft], phi, vl);
            MMA_BF16(oc[2 * ft], plo, vh);
            MMA_BF16(oc[2 * ft + 1], phi, vh + 2);
            MMA_BF16(oc[2 * ft + 1], phi, vl + 2);
            MMA_BF16(oc[2 * ft + 1], plo, vh + 2);
        }
    }

    {
        const int pka = pmeta[ra], pkb = pmeta[rb];
        const float iva = invs[ra], ivb = invs[rb];
        const size_t obase = ((size_t)n * Hh + h) * NHh;
        const size_t oa = ((obase + ((pka >> 12) & 3)) * Tt + (pka & 4095)) * DHh;
        const size_t ob = ((obase + ((pkb >> 12) & 3)) * Tt + (pkb & 4095)) * DHh;
#pragma unroll
        for (int ft = 0; ft < 4; ft++) {
            const int f0 = ft * 16 + 2 * tg;
            *(float2*)&g_O[oa + f0]     = make_float2(oc[2 * ft][0] * iva, oc[2 * ft][1] * iva);
            *(float2*)&g_O[ob + f0]     = make_float2(oc[2 * ft][2] * ivb, oc[2 * ft][3] * ivb);
            *(float2*)&g_O[oa + f0 + 8] = make_float2(oc[2 * ft + 1][0] * iva, oc[2 * ft + 1][1] * iva);
            *(float2*)&g_O[ob + f0 + 8] = make_float2(oc[2 * ft + 1][2] * ivb, oc[2 * ft + 1][3] * ivb);
        }
    }
}

// ================= round-combine softmax + LayerNorm (shfl reduce) ==========
__global__ void combine_ln_kernel(const float* __restrict__ gamma,
                                  const float* __restrict__ beta,
                                  float* __restrict__ out)
{
    const int bid = blockIdx.x;            // n*T + t
    const int n = bid >> 12, t = bid & 4095;
    const int tid = threadIdx.x;           // 128
    const int w = tid >> 5, lane = tid & 31;
    __shared__ float wsh[Hh][NHh];
    __shared__ float rs[4], rq[4];

    if (tid < Hh) {
        const int h = tid;
        float l[NHh];
        float m = -1e30f;
#pragma unroll
        for (int r = 0; r < NHh; r++) {
            l[r] = g_logits[(((size_t)n * Hh + h) * NHh + r) * Tt + t];
            m = fmaxf(m, l[r]);
        }
        float s = 0.f;
#pragma unroll
        for (int r = 0; r < NHh; r++) s += __expf(l[r] - m);
        const float lse = m + __logf(s);
#pragma unroll
        for (int r = 0; r < NHh; r++) wsh[h][r] = __expf(l[r] - lse);
    }
    __syncthreads();

    float vals[4];
    float lsum = 0.f, lsq = 0.f;
#pragma unroll
    for (int k2 = 0; k2 < 4; k2++) {
        const int d = tid + k2 * 128;
        const int h = d >> 6, f = d & 63;
        float a = 0.f;
#pragma unroll
        for (int r = 0; r < NHh; r++)
            a += wsh[h][r] * g_O[((((size_t)n * Hh + h) * NHh + r) * Tt + t) * DHh + f];
        vals[k2] = a;
        lsum += a;
        lsq  += a * a;
    }

#pragma unroll
    for (int o = 16; o; o >>= 1) {
        lsum += __shfl_xor_sync(0xffffffffu, lsum, o);
        lsq  += __shfl_xor_sync(0xffffffffu, lsq, o);
    }
    if (lane == 0) { rs[w] = lsum; rq[w] = lsq; }
    __syncthreads();
    const float ts = rs[0] + rs[1] + rs[2] + rs[3];
    const float tq = rq[0] + rq[1] + rq[2] + rq[3];
    const float mu = ts * (1.f / Dd);
    const float var = tq * (1.f / Dd) - mu * mu;
    const float rstd = rsqrtf(var + 1e-3f);

#pragma unroll
    for (int k2 = 0; k2 < 4; k2++) {
        const int d = tid + k2 * 128;
        out[(size_t)bid * Dd + d] = gamma[d] * (vals[k2] - mu) * rstd + beta[d];
    }
}

// ================= launch ===================================================
extern "C" void kernel_launch(void* const* d_in, const int* in_sizes, int n_in,
                              void* d_out, int out_size)
{
    const float* x     = (const float*)d_in[0];
    const float* W_Q   = (const float*)d_in[1];
    const float* b_Q   = (const float*)d_in[2];
    const float* W_V   = (const float*)d_in[3];
    const float* b_V   = (const float*)d_in[4];
    const float* gamma = (const float*)d_in[5];
    const float* beta  = (const float*)d_in[6];
    const float* rot   = (const float*)d_in[7];
    float* out = (float*)d_out;

    cudaFuncSetAttribute(attention_kernel,
                         cudaFuncAttributeMaxDynamicSharedMemorySize, SMEM_ATT3);
    cudaFuncSetAttribute(sort_kernel,
                         cudaFuncAttributeMaxDynamicSharedMemorySize, SMEM_SORT);
    cudaFuncSetAttribute(gemm_qv_kernel,
                         cudaFuncAttributeMaxDynamicSharedMemorySize, SMEM_MMA);
    cudaFuncSetAttribute(bucket_kernel,
                         cudaFuncAttributeMaxDynamicSharedMemorySize, SMEM_BKT);
    cudaFuncSetAttribute(fixup_kernel,
                         cudaFuncAttributeMaxDynamicSharedMemorySize, SMEM_FIX);

    reset_kernel<<<1, 1>>>();

    split_x_kernel<<<(Nb * Tt * Dd / 4) / 256, 256>>>(x);   // 8192 blocks
    split_w_kernel<<<dim3(16, 16, 2), dim3(32, 8)>>>(W_Q, W_V);

    dim3 gGrid(2, (Nb * Tt) / 128, 2);          // (2, 128, 2) -> Q and V
    gemm_qv_kernel<<<gGrid, 512, SMEM_MMA>>>(b_Q, b_V);

    dim3 bGrid(Tt / 128, Hh, Nb);               // (32, 8, 4)
    bucket_kernel<<<bGrid, 256, SMEM_BKT>>>(rot);

    fixup_kernel<<<dim3(32, 8), 256, SMEM_FIX>>>(x, W_Q, b_Q, rot);

    sort_kernel<<<Nb * Hh, 256, SMEM_SORT>>>(); // 32 blocks

    dim3 aGrid(CSs, Hh, Nb);                    // (256, 8, 4)
    attention_kernel<<<aGrid, 128, SMEM_ATT3>>>();

    combine_ln_kernel<<<Nb * Tt, 128>>>(gamma, beta, out);
}